// round 1
// baseline (speedup 1.0000x reference)
#include <cuda_runtime.h>
#include <cfloat>
#include <climits>
#include <math.h>
#include <stdint.h>

// ---------------- problem constants ----------------
#define NTOK   4096   // N = H*W
#define CDIM   512    // C
#define DIDIM  512    // HEADS*DH
#define NHEADS 8
#define DH     64
#define NCOARSE 257   // 1 mem slot + 256 coarse blocks
#define CBLK   16     // CB
#define SBLK   2      // SB
#define NFB    2048   // N / SB
#define SWIN   8

static constexpr size_t SZ_NC = (size_t)NTOK * CDIM; // 2,097,152 floats

// scratch layout (floats) in one big device buffer
static constexpr size_t O_XT   = 0;                       // x^T        (N, C)
static constexpr size_t O_XST  = O_XT   + SZ_NC;          // xs^T       (N, C)
static constexpr size_t O_XS   = O_XST  + SZ_NC;          // xs         (C, N)
static constexpr size_t O_H    = O_XS   + SZ_NC;          // h          (N, C)
static constexpr size_t O_Q    = O_H    + SZ_NC;          // q          (N, DI)
static constexpr size_t O_K    = O_Q    + SZ_NC;          // k          (N, DI)
static constexpr size_t O_V    = O_K    + SZ_NC;          // v          (N, DI)
static constexpr size_t O_RQ   = O_V    + SZ_NC;          // rope(q)
static constexpr size_t O_RK   = O_RQ   + SZ_NC;          // rope(k)
static constexpr size_t O_KIN  = O_RK   + SZ_NC;          // kin        (2048, 1024)
static constexpr size_t O_VIN  = O_KIN  + SZ_NC;          // vin
static constexpr size_t O_HID  = O_VIN  + SZ_NC;          // MLP hidden (2048, 1024)
static constexpr size_t O_CKF  = O_HID  + SZ_NC;          // ck flat    (2048, 64)
static constexpr size_t O_CVF  = O_CKF  + (size_t)2048*64;
static constexpr size_t O_CK   = O_CVF  + (size_t)2048*64;            // (8,257,64)
static constexpr size_t O_CV   = O_CK   + (size_t)NHEADS*NCOARSE*DH;
static constexpr size_t O_CSIM = O_CV   + (size_t)NHEADS*NCOARSE*DH;  // (8,4096,257)
static constexpr size_t O_COMP = O_CSIM + (size_t)NHEADS*NTOK*NCOARSE;// (8,4096,64)
static constexpr size_t O_GATE = O_COMP + (size_t)NHEADS*NTOK*DH;     // (4096,24)
static constexpr size_t O_ATTN = O_GATE + (size_t)NTOK*24;            // (N, DI)
static constexpr size_t O_OUTC = O_ATTN + SZ_NC;                      // (N, C)
static constexpr size_t TOTAL  = O_OUTC + SZ_NC;

__device__ float g_buf[TOTAL];

// ---------------- generic NT GEMM: C[m,n] = dot(A[m,:], B[n,:]) ----------------
// A: (M,K) row-major, B: (Ncols,K) row-major, K % 16 == 0.
// bias_mode: 0 none, 1 per-column bias[n], 2 per-row bias[m]
// act: 0 none, 1 relu, 2 sigmoid.  resid (optional): added as resid[m*Ncols+n].
__global__ __launch_bounds__(256) void gemm_nt_kernel(
    const float* __restrict__ A, const float* __restrict__ B, float* __restrict__ C,
    int M, int Ncols, int K, const float* __restrict__ bias, int bias_mode,
    const float* __restrict__ resid, int act)
{
    __shared__ float As[16][64];
    __shared__ float Bs[16][64];
    const int tid = threadIdx.x;
    const int tx  = tid & 15;
    const int ty  = tid >> 4;
    const int bm0 = blockIdx.y * 64;
    const int bn0 = blockIdx.x * 64;
    const int lr  = tid >> 2;         // 0..63
    const int lk  = (tid & 3) << 2;   // 0,4,8,12

    float acc[4][4];
#pragma unroll
    for (int i = 0; i < 4; i++)
#pragma unroll
        for (int j = 0; j < 4; j++) acc[i][j] = 0.f;

    for (int k0 = 0; k0 < K; k0 += 16) {
        {
            int am = bm0 + lr;
            float4 av = make_float4(0.f, 0.f, 0.f, 0.f);
            if (am < M) av = *reinterpret_cast<const float4*>(A + (size_t)am * K + k0 + lk);
            As[lk + 0][lr] = av.x; As[lk + 1][lr] = av.y;
            As[lk + 2][lr] = av.z; As[lk + 3][lr] = av.w;
        }
        {
            int bn = bn0 + lr;
            float4 bv = make_float4(0.f, 0.f, 0.f, 0.f);
            if (bn < Ncols) bv = *reinterpret_cast<const float4*>(B + (size_t)bn * K + k0 + lk);
            Bs[lk + 0][lr] = bv.x; Bs[lk + 1][lr] = bv.y;
            Bs[lk + 2][lr] = bv.z; Bs[lk + 3][lr] = bv.w;
        }
        __syncthreads();
#pragma unroll
        for (int kk = 0; kk < 16; kk++) {
            float4 a = *reinterpret_cast<const float4*>(&As[kk][ty << 2]);
            float4 b = *reinterpret_cast<const float4*>(&Bs[kk][tx << 2]);
            acc[0][0] += a.x * b.x; acc[0][1] += a.x * b.y; acc[0][2] += a.x * b.z; acc[0][3] += a.x * b.w;
            acc[1][0] += a.y * b.x; acc[1][1] += a.y * b.y; acc[1][2] += a.y * b.z; acc[1][3] += a.y * b.w;
            acc[2][0] += a.z * b.x; acc[2][1] += a.z * b.y; acc[2][2] += a.z * b.z; acc[2][3] += a.z * b.w;
            acc[3][0] += a.w * b.x; acc[3][1] += a.w * b.y; acc[3][2] += a.w * b.z; acc[3][3] += a.w * b.w;
        }
        __syncthreads();
    }
#pragma unroll
    for (int i = 0; i < 4; i++) {
        int m = bm0 + (ty << 2) + i;
        if (m >= M) continue;
#pragma unroll
        for (int j = 0; j < 4; j++) {
            int nn = bn0 + (tx << 2) + j;
            if (nn >= Ncols) continue;
            float vv = acc[i][j];
            if (bias_mode == 1) vv += bias[nn];
            else if (bias_mode == 2) vv += bias[m];
            if (act == 1) vv = fmaxf(vv, 0.f);
            else if (act == 2) vv = 1.f / (1.f + expf(-vv));
            if (resid) vv += resid[(size_t)m * Ncols + nn];
            C[(size_t)m * Ncols + nn] = vv;
        }
    }
}

// ---------------- transpose (R,Ccols) -> (Ccols,R) ----------------
__global__ void transpose_kernel(const float* __restrict__ in, float* __restrict__ out,
                                 int R, int Ccols)
{
    __shared__ float tile[32][33];
    int r0 = blockIdx.y * 32, c0 = blockIdx.x * 32;
#pragma unroll
    for (int i = 0; i < 32; i += 8) {
        int r = r0 + threadIdx.y + i, c = c0 + threadIdx.x;
        if (r < R && c < Ccols) tile[threadIdx.y + i][threadIdx.x] = in[(size_t)r * Ccols + c];
    }
    __syncthreads();
#pragma unroll
    for (int i = 0; i < 32; i += 8) {
        int rr = c0 + threadIdx.y + i, cc = r0 + threadIdx.x;
        if (rr < Ccols && cc < R) out[(size_t)rr * R + cc] = tile[threadIdx.x][threadIdx.y + i];
    }
}

// ---------------- RMSNorm over rows of (N, C) ----------------
__global__ void rmsnorm_kernel(const float* __restrict__ xs_t, const float* __restrict__ g,
                               float* __restrict__ h)
{
    int n = blockIdx.x, tid = threadIdx.x;
    const float* row = xs_t + (size_t)n * CDIM;
    float s = 0.f;
    for (int c = tid; c < CDIM; c += 256) { float v = row[c]; s += v * v; }
    __shared__ float red[256];
    red[tid] = s; __syncthreads();
    for (int o = 128; o; o >>= 1) { if (tid < o) red[tid] += red[tid + o]; __syncthreads(); }
    float inv = rsqrtf(red[0] / (float)CDIM + 1e-6f);
    for (int c = tid; c < CDIM; c += 256)
        h[(size_t)n * CDIM + c] = row[c] * inv * g[c];
}

// ---------------- RoPE on q and k ----------------
__global__ void rope_kernel(const float* __restrict__ q, const float* __restrict__ k,
                            float* __restrict__ rq, float* __restrict__ rk)
{
    int p = blockIdx.x * blockDim.x + threadIdx.x;
    if (p >= NTOK * (DIDIM / 2)) return;
    int n = p / (DIDIM / 2);
    int r = p % (DIDIM / 2);
    int i = r & 31;                    // pair index within head (0..31)
    int base = n * DIDIM + (r >> 5) * DH + 2 * i;
    double inv = pow(10000.0, -(double)(2 * i) / 64.0);
    double ang = (double)n * inv;
    float c = (float)cos(ang), s = (float)sin(ang);
    float q0 = q[base], q1 = q[base + 1];
    rq[base]     = q0 * c - q1 * s;
    rq[base + 1] = q1 * c + q0 * s;
    float k0 = k[base], k1 = k[base + 1];
    rk[base]     = k0 * c - k1 * s;
    rk[base + 1] = k1 * c + k0 * s;
}

// ---------------- build compression MLP inputs ----------------
__global__ void build_kin_kernel(const float* __restrict__ k, const float* __restrict__ v,
                                 const float* __restrict__ k_pos, const float* __restrict__ v_pos,
                                 float* __restrict__ kin, float* __restrict__ vin)
{
    int idx = blockIdx.x * 256 + threadIdx.x;
    if (idx >= 2048 * 1024) return;
    int row = idx >> 10;          // h*256 + cb
    int col = idx & 1023;         // i*64 + d
    int hh = row >> 8, cb = row & 255;
    int i = col >> 6, d = col & 63;
    int n = cb * CBLK + i;
    size_t ko = (size_t)n * DIDIM + hh * DH + d;
    size_t po = (size_t)(hh * CBLK + i) * DH + d;
    kin[idx] = k[ko] + k_pos[po];
    vin[idx] = v[ko] + v_pos[po];
}

// ---------------- concat mem slot + compressed k/v ----------------
__global__ void build_ckcv_kernel(const float* __restrict__ ckf, const float* __restrict__ cvf,
                                  const float* __restrict__ mem_k, const float* __restrict__ mem_v,
                                  float* __restrict__ ck, float* __restrict__ cv)
{
    int idx = blockIdx.x * 256 + threadIdx.x;
    if (idx >= NHEADS * NCOARSE * DH) return;
    int hh = idx / (NCOARSE * DH);
    int rem = idx - hh * (NCOARSE * DH);
    int j = rem / DH, d = rem % DH;
    if (j == 0) {
        ck[idx] = mem_k[hh * DH + d];
        cv[idx] = mem_v[hh * DH + d];
    } else {
        size_t src = (size_t)((hh << 8) + j - 1) * DH + d;
        ck[idx] = ckf[src];
        cv[idx] = cvf[src];
    }
}

// ---------------- compressed attention: csim (stored) + softmax + AV ----------------
// grid (NTOK/8, NHEADS), 256 threads. 8 query rows per block.
__global__ __launch_bounds__(256) void csim_comp_kernel(
    const float* __restrict__ q, const float* __restrict__ ck, const float* __restrict__ cv,
    float* __restrict__ csim, float* __restrict__ comp)
{
    __shared__ float sq[8][64];
    __shared__ float sims[8][258];
    const int hh = blockIdx.y;
    const int n0 = blockIdx.x * 8;
    const int tid = threadIdx.x;
    const float SCALE = 0.125f;

    for (int t = tid; t < 8 * 64; t += 256) {
        int r = t >> 6, d = t & 63;
        sq[r][d] = q[(size_t)(n0 + r) * DIDIM + hh * DH + d];
    }
    __syncthreads();

    for (int j = tid; j < NCOARSE; j += 256) {
        const float* ckr = ck + ((size_t)(hh * NCOARSE + j) << 6);
        float acc[8] = {0.f, 0.f, 0.f, 0.f, 0.f, 0.f, 0.f, 0.f};
#pragma unroll 4
        for (int d = 0; d < 64; d++) {
            float kv = ckr[d];
#pragma unroll
            for (int r = 0; r < 8; r++) acc[r] += kv * sq[r][d];
        }
#pragma unroll
        for (int r = 0; r < 8; r++) {
            int n = n0 + r;
            float s = (j <= (n >> 4)) ? acc[r] * SCALE : -FLT_MAX;
            csim[((size_t)hh * NTOK + n) * NCOARSE + j] = s;
            sims[r][j] = s;
        }
    }
    __syncthreads();

    const int r = tid >> 5, lane = tid & 31;
    const int n = n0 + r;
    const int jmax = n >> 4;   // valid coarse entries: 0..jmax
    float m = -FLT_MAX;
    for (int j = lane; j <= jmax; j += 32) m = fmaxf(m, sims[r][j]);
    for (int o = 16; o; o >>= 1) m = fmaxf(m, __shfl_xor_sync(0xffffffffu, m, o));
    float z = 0.f;
    for (int j = lane; j <= jmax; j += 32) {
        float e = expf(sims[r][j] - m);
        sims[r][j] = e;
        z += e;
    }
    for (int o = 16; o; o >>= 1) z += __shfl_xor_sync(0xffffffffu, z, o);
    __syncwarp();
    float invz = 1.f / z;
    for (int d = lane; d < 64; d += 32) {
        float acc = 0.f;
        for (int j = 0; j <= jmax; j++)
            acc += sims[r][j] * cv[((size_t)(hh * NCOARSE + j) << 6) + d];
        comp[((size_t)hh * NTOK + n) * DH + d] = acc * invz;
    }
}

// ---------------- top-2 helpers (stable: value desc, index asc on ties) ----------------
__device__ __forceinline__ void top2_insert(float v, int f,
                                            float& t1v, int& t1f, float& t2v, int& t2f)
{
    if (f == t1f || f == t2f) return;
    if (v > t1v || (v == t1v && f < t1f)) { t2v = t1v; t2f = t1f; t1v = v; t1f = f; }
    else if (v > t2v || (v == t2v && f < t2f)) { t2v = v; t2f = f; }
}

// ---------------- top-k select + fine attn + sliding attn + gated combine ----------------
// grid (NTOK/8, NHEADS), 256 threads; one warp per (head, token).
__global__ __launch_bounds__(256) void fine_slide_kernel(
    const float* __restrict__ rq, const float* __restrict__ rk, const float* __restrict__ v,
    const float* __restrict__ csim, const float* __restrict__ comp,
    const float* __restrict__ gates, float* __restrict__ attn)
{
    const int hh = blockIdx.y;
    const int warp = threadIdx.x >> 5, lane = threadIdx.x & 31;
    const int n = blockIdx.x * 8 + warp;
    const float SCALE = 0.125f;
    const unsigned FULL = 0xffffffffu;

    const size_t qb = (size_t)n * DIDIM + hh * DH;
    const float q0 = rq[qb + lane];
    const float q1 = rq[qb + lane + 32];

    // ---- stable top-2 over fine blocks (value = coarse sim, validity fb < n/SB) ----
    const int nfb = n >> 1;
    float t1v = -INFINITY, t2v = -INFINITY;
    int   t1f = INT_MAX,   t2f = INT_MAX;
    float vloc[8]; int cloc[8];
    const size_t cbase = ((size_t)hh * NTOK + n) * NCOARSE + 1;
#pragma unroll
    for (int i = 0; i < 8; i++) {
        int jp = i * 32 + lane;               // coarse block 0..255
        int cnt = nfb - jp * 8;
        cnt = cnt > 8 ? 8 : cnt;
        if (cnt > 0) {
            float val = csim[cbase + jp];
            vloc[i] = val; cloc[i] = cnt;
            top2_insert(val, jp * 8, t1v, t1f, t2v, t2f);
            if (cnt > 1) top2_insert(val, jp * 8 + 1, t1v, t1f, t2v, t2f);
        } else cloc[i] = 0;
    }
    for (int o = 16; o; o >>= 1) {
        float ov1 = __shfl_xor_sync(FULL, t1v, o); int of1 = __shfl_xor_sync(FULL, t1f, o);
        float ov2 = __shfl_xor_sync(FULL, t2v, o); int of2 = __shfl_xor_sync(FULL, t2f, o);
        top2_insert(ov1, of1, t1v, t1f, t2v, t2f);
        top2_insert(ov2, of2, t1v, t1f, t2v, t2f);
    }
    // softmax normalizer over [-1000] + valid fine logits
    const float mx = fmaxf(t1v, -1000.f);
    float part = 0.f;
#pragma unroll
    for (int i = 0; i < 8; i++)
        if (cloc[i]) part += (float)cloc[i] * expf(vloc[i] - mx);
    for (int o = 16; o; o >>= 1) part += __shfl_xor_sync(FULL, part, o);
    const float Z = expf(-1000.f - mx) + part;

    int fb1, fb2; float sv1, sv2;
    if (t1f == INT_MAX) { fb1 = 0; fb2 = 1; sv1 = 0.f; sv2 = 0.f; }
    else {
        fb1 = t1f; sv1 = expf(t1v - mx) / Z;
        if (t2f == INT_MAX) { fb2 = (t1f == 0) ? 1 : 0; sv2 = 0.f; }
        else { fb2 = t2f; sv2 = expf(t2v - mx) / Z; }
    }

    // ---- fine attention: blocks {sel1, sel2, diag}, 2 keys each ----
    int rows6[6]; float sims6[6];
    const int blks[3] = { fb1, fb2, n >> 1 };
    const float svs[2] = { sv1, sv2 };
#pragma unroll
    for (int e = 0; e < 6; e++) {
        int b = blks[e >> 1], s = e & 1;
        int row = b * 2 + s;
        rows6[e] = row;
        bool vld = (e < 4) ? (svs[e >> 1] > 1e-10f) : (s <= (n & 1));
        size_t kb = (size_t)row * DIDIM + hh * DH;
        float p = q0 * rk[kb + lane] + q1 * rk[kb + lane + 32];
        for (int o = 16; o; o >>= 1) p += __shfl_xor_sync(FULL, p, o);
        sims6[e] = vld ? p * SCALE : -FLT_MAX;
    }
    float fm = -FLT_MAX;
#pragma unroll
    for (int e = 0; e < 6; e++) fm = fmaxf(fm, sims6[e]);
    float fz = 0.f, fo0 = 0.f, fo1 = 0.f;
#pragma unroll
    for (int e = 0; e < 6; e++) {
        float pe = expf(sims6[e] - fm);
        fz += pe;
        size_t vb = (size_t)rows6[e] * DIDIM + hh * DH;
        fo0 += pe * v[vb + lane];
        fo1 += pe * v[vb + lane + 32];
    }
    fo0 /= fz; fo1 /= fz;

    // ---- sliding window attention: keys n-8..n ----
    float simsw[SWIN + 1];
#pragma unroll
    for (int w = 0; w <= SWIN; w++) {
        int row = n - SWIN + w;
        bool vld = (row >= 0);
        size_t kb = (size_t)(vld ? row : 0) * DIDIM + hh * DH;
        float k0 = vld ? rk[kb + lane] : 0.f;
        float k1 = vld ? rk[kb + lane + 32] : 0.f;
        float p = q0 * k0 + q1 * k1;
        for (int o = 16; o; o >>= 1) p += __shfl_xor_sync(FULL, p, o);
        simsw[w] = vld ? p * SCALE : -FLT_MAX;
    }
    float sm = -FLT_MAX;
#pragma unroll
    for (int w = 0; w <= SWIN; w++) sm = fmaxf(sm, simsw[w]);
    float sz = 0.f, so0 = 0.f, so1 = 0.f;
#pragma unroll
    for (int w = 0; w <= SWIN; w++) {
        float pe = expf(simsw[w] - sm);
        sz += pe;
        int row = n - SWIN + w;
        if (row >= 0) {
            size_t vb = (size_t)row * DIDIM + hh * DH;
            so0 += pe * v[vb + lane];
            so1 += pe * v[vb + lane + 32];
        }
    }
    so0 /= sz; so1 /= sz;

    // ---- gated combine ----
    const float g0 = gates[n * 24 + hh * 3 + 0];
    const float g1 = gates[n * 24 + hh * 3 + 1];
    const float g2 = gates[n * 24 + hh * 3 + 2];
    const size_t cb2 = ((size_t)hh * NTOK + n) * DH;
    const float c0 = comp[cb2 + lane], c1 = comp[cb2 + lane + 32];
    attn[qb + lane]      = g0 * c0 + g1 * fo0 + g2 * so0;
    attn[qb + lane + 32] = g0 * c1 + g1 * fo1 + g2 * so1;
}

// ---------------- host-side orchestration ----------------
static inline void launch_gemm(const float* A, const float* B, float* C,
                               int M, int Ncols, int K,
                               const float* bias, int bias_mode,
                               const float* resid, int act)
{
    dim3 grid((Ncols + 63) / 64, (M + 63) / 64);
    gemm_nt_kernel<<<grid, 256>>>(A, B, C, M, Ncols, K, bias, bias_mode, resid, act);
}

extern "C" void kernel_launch(void* const* d_in, const int* in_sizes, int n_in,
                              void* d_out, int out_size)
{
    (void)in_sizes; (void)n_in; (void)out_size;
    float* base = nullptr;
    cudaGetSymbolAddress((void**)&base, g_buf);

    const float* x       = (const float*)d_in[0];
    const float* w_in    = (const float*)d_in[1];
    const float* b_in    = (const float*)d_in[2];
    const float* g_norm  = (const float*)d_in[3];
    const float* wq      = (const float*)d_in[4];
    const float* wk      = (const float*)d_in[5];
    const float* wv      = (const float*)d_in[6];
    const float* k_pos   = (const float*)d_in[7];
    const float* v_pos   = (const float*)d_in[8];
    const float* mem_k   = (const float*)d_in[9];
    const float* mem_v   = (const float*)d_in[10];
    const float* kc_w1   = (const float*)d_in[11];
    const float* kc_b1   = (const float*)d_in[12];
    const float* kc_w2   = (const float*)d_in[13];
    const float* kc_b2   = (const float*)d_in[14];
    const float* vc_w1   = (const float*)d_in[15];
    const float* vc_b1   = (const float*)d_in[16];
    const float* vc_w2   = (const float*)d_in[17];
    const float* vc_b2   = (const float*)d_in[18];
    const float* w_strat = (const float*)d_in[19];
    const float* b_strat = (const float*)d_in[20];
    const float* w_comb  = (const float*)d_in[21];
    const float* w_out   = (const float*)d_in[22];
    const float* b_out   = (const float*)d_in[23];
    float* out = (float*)d_out;

    // 1. x (C,N) -> xt (N,C)
    {
        dim3 th(32, 8), gr(NTOK / 32, CDIM / 32);
        transpose_kernel<<<gr, th>>>(x, base + O_XT, CDIM, NTOK);
    }
    // 2. xs_t = xt @ w_in^T + b_in
    launch_gemm(base + O_XT, w_in, base + O_XST, NTOK, CDIM, CDIM, b_in, 1, nullptr, 0);
    // 3. xs_t (N,C) -> xs (C,N)   (residual for the final GEMM)
    {
        dim3 th(32, 8), gr(CDIM / 32, NTOK / 32);
        transpose_kernel<<<gr, th>>>(base + O_XST, base + O_XS, NTOK, CDIM);
    }
    // 4. RMSNorm
    rmsnorm_kernel<<<NTOK, 256>>>(base + O_XST, g_norm, base + O_H);
    // 5. q, k, v projections
    launch_gemm(base + O_H, wq, base + O_Q, NTOK, DIDIM, CDIM, nullptr, 0, nullptr, 0);
    launch_gemm(base + O_H, wk, base + O_K, NTOK, DIDIM, CDIM, nullptr, 0, nullptr, 0);
    launch_gemm(base + O_H, wv, base + O_V, NTOK, DIDIM, CDIM, nullptr, 0, nullptr, 0);
    // 6. RoPE
    rope_kernel<<<(NTOK * (DIDIM / 2) + 255) / 256, 256>>>(base + O_Q, base + O_K,
                                                           base + O_RQ, base + O_RK);
    // 7. kin/vin
    build_kin_kernel<<<(2048 * 1024) / 256, 256>>>(base + O_K, base + O_V, k_pos, v_pos,
                                                   base + O_KIN, base + O_VIN);
    // 8-11. compression MLPs (heads folded: 2048 rows)
    launch_gemm(base + O_KIN, kc_w1, base + O_HID, 2048, 1024, 1024, kc_b1, 1, nullptr, 1);
    launch_gemm(base + O_HID, kc_w2, base + O_CKF, 2048, 64, 1024, kc_b2, 1, nullptr, 0);
    launch_gemm(base + O_VIN, vc_w1, base + O_HID, 2048, 1024, 1024, vc_b1, 1, nullptr, 1);
    launch_gemm(base + O_HID, vc_w2, base + O_CVF, 2048, 64, 1024, vc_b2, 1, nullptr, 0);
    // 12. concat mem slots
    build_ckcv_kernel<<<(NHEADS * NCOARSE * DH + 255) / 256, 256>>>(
        base + O_CKF, base + O_CVF, mem_k, mem_v, base + O_CK, base + O_CV);
    // 13. compressed attention (+ csim stored for importance)
    {
        dim3 gr(NTOK / 8, NHEADS);
        csim_comp_kernel<<<gr, 256>>>(base + O_Q, base + O_CK, base + O_CV,
                                      base + O_CSIM, base + O_COMP);
    }
    // 14. gates
    launch_gemm(base + O_H, w_strat, base + O_GATE, NTOK, 24, CDIM, b_strat, 1, nullptr, 2);
    // 15. top-k select + fine + slide + combine
    {
        dim3 gr(NTOK / 8, NHEADS);
        fine_slide_kernel<<<gr, 256>>>(base + O_RQ, base + O_RK, base + O_V,
                                       base + O_CSIM, base + O_COMP, base + O_GATE,
                                       base + O_ATTN);
    }
    // 16. combine projection
    launch_gemm(base + O_ATTN, w_comb, base + O_OUTC, NTOK, CDIM, DIDIM, nullptr, 0, nullptr, 0);
    // 17. output conv + bias + xs residual -> d_out
    launch_gemm(w_out, base + O_OUTC, out, CDIM, NTOK, CDIM, b_out, 2, base + O_XS, 0);
}

// round 2
// speedup vs baseline: 1.1025x; 1.1025x over previous
#include <cuda_runtime.h>
#include <cfloat>
#include <climits>
#include <math.h>
#include <stdint.h>

// ---------------- problem constants ----------------
#define NTOK   4096   // N = H*W
#define CDIM   512    // C
#define DIDIM  512    // HEADS*DH
#define NHEADS 8
#define DH     64
#define NCOARSE 257   // 1 mem slot + 256 coarse blocks
#define CBLK   16     // CB
#define SBLK   2      // SB
#define SWIN   8

static constexpr size_t SZ_NC = (size_t)NTOK * CDIM; // 2,097,152 floats

// scratch layout (floats) in one big device buffer
static constexpr size_t O_XT   = 0;                       // x^T        (N, C)
static constexpr size_t O_XST  = O_XT   + SZ_NC;          // xs^T       (N, C)
static constexpr size_t O_XS   = O_XST  + SZ_NC;          // xs         (C, N)
static constexpr size_t O_H    = O_XS   + SZ_NC;          // h          (N, C)
static constexpr size_t O_Q    = O_H    + SZ_NC;          // q          (N, DI)
static constexpr size_t O_K    = O_Q    + SZ_NC;          // k          (N, DI)
static constexpr size_t O_V    = O_K    + SZ_NC;          // v          (N, DI)
static constexpr size_t O_RQ   = O_V    + SZ_NC;          // rope(q)
static constexpr size_t O_RK   = O_RQ   + SZ_NC;          // rope(k)
static constexpr size_t O_KIN  = O_RK   + SZ_NC;          // kin        (2048, 1024)
static constexpr size_t O_VIN  = O_KIN  + SZ_NC;          // vin
static constexpr size_t O_HID  = O_VIN  + SZ_NC;          // MLP hidden (2048, 1024)
static constexpr size_t O_CKF  = O_HID  + SZ_NC;          // ck flat    (2048, 64)
static constexpr size_t O_CVF  = O_CKF  + (size_t)2048*64;
static constexpr size_t O_CK   = O_CVF  + (size_t)2048*64;            // (8,257,64)
static constexpr size_t O_CV   = O_CK   + (size_t)NHEADS*NCOARSE*DH;
static constexpr size_t O_CSIM = O_CV   + (size_t)NHEADS*NCOARSE*DH;  // (8,4096,257)
static constexpr size_t O_COMP = O_CSIM + (size_t)NHEADS*NTOK*NCOARSE;// (8,4096,64)
static constexpr size_t O_GATE = O_COMP + (size_t)NHEADS*NTOK*DH;     // (4096,24)
static constexpr size_t O_ATTN = O_GATE + (size_t)NTOK*24;            // (N, DI)
static constexpr size_t O_OUTC = O_ATTN + SZ_NC;                      // (N, C)
static constexpr size_t TOTAL  = O_OUTC + SZ_NC;

__device__ float g_buf[TOTAL];

// ============================================================================
// TF32 tensor-core NT GEMM with 3xTF32 split (fp32-level accuracy)
// C[m,n] = dot(A[m,:], B[n,:]); A (M,K) row-major, B (N,K) row-major.
// Requirements: M % 128 == 0, N % BN == 0, K % 32 == 0.
// bias_mode: 0 none, 1 per-col, 2 per-row.  act: 0 none, 1 relu.
// ============================================================================

__device__ __forceinline__ float to_tf32(float f) {
    uint32_t u;
    asm("cvt.rna.tf32.f32 %0, %1;" : "=r"(u) : "f"(f));
    return __uint_as_float(u);
}

// float4 a = (a0, a2, a1, a3) in PTX fragment naming
__device__ __forceinline__ void mma_tf32(float4& d, const float4 a, const float2 b) {
    asm volatile(
        "mma.sync.aligned.m16n8k8.row.col.f32.tf32.tf32.f32 "
        "{%0,%1,%2,%3}, {%4,%5,%6,%7}, {%8,%9}, {%0,%1,%2,%3};\n"
        : "+f"(d.x), "+f"(d.y), "+f"(d.z), "+f"(d.w)
        : "r"(__float_as_uint(a.x)), "r"(__float_as_uint(a.z)),
          "r"(__float_as_uint(a.y)), "r"(__float_as_uint(a.w)),
          "r"(__float_as_uint(b.x)), "r"(__float_as_uint(b.y)));
}

template<int BN>
__global__ __launch_bounds__(256, 1) void gemm_tf32_kernel(
    const float* __restrict__ A, const float* __restrict__ B, float* __restrict__ C,
    int M, int N, int K, const float* __restrict__ bias, int bias_mode,
    const float* __restrict__ resid, int act)
{
    constexpr int NT   = BN / 8;        // total n-tiles per block
    constexpr int NTW  = NT / 2;        // n-tiles per warp
    constexpr int BREG = (BN * 32) / (256 * 4); // float4 per thread for B tile
    constexpr int ASZ  = 128 * 32;      // floats per A stage
    constexpr int BSZ  = BN * 32;       // floats per B stage

    extern __shared__ float smf[];
    float* Ah = smf;
    float* Al = Ah + 2 * ASZ;
    float* Bh = Al + 2 * ASZ;
    float* Bl = Bh + 2 * BSZ;

    const int tid  = threadIdx.x;
    const int bm0  = blockIdx.y * 128;
    const int bn0  = blockIdx.x * BN;
    const int warp = tid >> 5, lane = tid & 31;
    const int wm = warp >> 1, wn = warp & 1;
    const int g  = lane >> 2, cc = lane & 3;

    float4 acc[2][NTW];
#pragma unroll
    for (int i = 0; i < 2; i++)
#pragma unroll
        for (int j = 0; j < NTW; j++) acc[i][j] = make_float4(0.f, 0.f, 0.f, 0.f);

    const int arow = tid >> 1;
    const int akb  = (tid & 1) * 16;
    const float* aptr = A + (size_t)(bm0 + arow) * K + akb;

    float4 areg[4], breg[BREG];

    auto ldg_tiles = [&](int k0) {
#pragma unroll
        for (int i = 0; i < 4; i++)
            areg[i] = *reinterpret_cast<const float4*>(aptr + k0 + i * 4);
#pragma unroll
        for (int t = 0; t < BREG; t++) {
            int e4 = tid + t * 256;
            int n  = e4 >> 3;
            int k4 = (e4 & 7) * 4;
            breg[t] = *reinterpret_cast<const float4*>(B + (size_t)(bn0 + n) * K + k0 + k4);
        }
    };

    auto sts_tiles = [&](int st) {
        const int r = arow & 15, mt = arow >> 4, gg = r & 7, hs = r >> 3;
#pragma unroll
        for (int i = 0; i < 4; i++) {
            const float* fv = reinterpret_cast<const float*>(&areg[i]);
#pragma unroll
            for (int j = 0; j < 4; j++) {
                int k = akb + i * 4 + j;
                float f  = fv[j];
                float hf = to_tf32(f);
                float lf = to_tf32(f - hf);
                int ks = k >> 3, c3 = k & 3, khi = (k >> 2) & 1;
                int idx = ((ks * 8 + mt) * 32 + gg * 4 + c3) * 4 + hs * 2 + khi;
                Ah[st * ASZ + idx] = hf;
                Al[st * ASZ + idx] = lf;
            }
        }
#pragma unroll
        for (int t = 0; t < BREG; t++) {
            int e4 = tid + t * 256;
            int n  = e4 >> 3;
            int nt = n >> 3, gg2 = n & 7;
            const float* fv = reinterpret_cast<const float*>(&breg[t]);
#pragma unroll
            for (int j = 0; j < 4; j++) {
                int k = (e4 & 7) * 4 + j;
                float f  = fv[j];
                float hf = to_tf32(f);
                float lf = to_tf32(f - hf);
                int ks = k >> 3, c3 = k & 3, khi = (k >> 2) & 1;
                int idx = ((ks * NT + nt) * 32 + gg2 * 4 + c3) * 2 + khi;
                Bh[st * BSZ + idx] = hf;
                Bl[st * BSZ + idx] = lf;
            }
        }
    };

    auto compute = [&](int st) {
#pragma unroll
        for (int ks = 0; ks < 4; ks++) {
            float4 afh[2], afl[2];
#pragma unroll
            for (int mi = 0; mi < 2; mi++) {
                int mt = wm * 2 + mi;
                int o  = st * ASZ + ((ks * 8 + mt) * 32 + lane) * 4;
                afh[mi] = *reinterpret_cast<const float4*>(&Ah[o]);
                afl[mi] = *reinterpret_cast<const float4*>(&Al[o]);
            }
            float2 bfh[NTW], bfl[NTW];
#pragma unroll
            for (int ni = 0; ni < NTW; ni++) {
                int nt = wn * NTW + ni;
                int o  = st * BSZ + ((ks * NT + nt) * 32 + lane) * 2;
                bfh[ni] = *reinterpret_cast<const float2*>(&Bh[o]);
                bfl[ni] = *reinterpret_cast<const float2*>(&Bl[o]);
            }
#pragma unroll
            for (int mi = 0; mi < 2; mi++)
#pragma unroll
                for (int ni = 0; ni < NTW; ni++) {
                    mma_tf32(acc[mi][ni], afh[mi], bfh[ni]);
                    mma_tf32(acc[mi][ni], afh[mi], bfl[ni]);
                    mma_tf32(acc[mi][ni], afl[mi], bfh[ni]);
                }
        }
    };

    ldg_tiles(0);
    sts_tiles(0);
    __syncthreads();

    const int slabs = K / 32;
    for (int s = 0; s < slabs; s++) {
        int st = s & 1;
        if (s + 1 < slabs) ldg_tiles((s + 1) * 32);
        compute(st);
        if (s + 1 < slabs) sts_tiles(st ^ 1);
        __syncthreads();
    }

    // epilogue
#pragma unroll
    for (int mi = 0; mi < 2; mi++) {
#pragma unroll
        for (int ni = 0; ni < NTW; ni++) {
            int mrow = bm0 + wm * 32 + mi * 16 + g;
            int ncol = bn0 + wn * (BN / 2) + ni * 8 + cc * 2;
            float2 r0 = make_float2(acc[mi][ni].x, acc[mi][ni].y);
            float2 r1 = make_float2(acc[mi][ni].z, acc[mi][ni].w);
            if (bias_mode == 1) {
                float b0 = bias[ncol], b1 = bias[ncol + 1];
                r0.x += b0; r0.y += b1; r1.x += b0; r1.y += b1;
            } else if (bias_mode == 2) {
                float bt = bias[mrow], bb = bias[mrow + 8];
                r0.x += bt; r0.y += bt; r1.x += bb; r1.y += bb;
            }
            if (act == 1) {
                r0.x = fmaxf(r0.x, 0.f); r0.y = fmaxf(r0.y, 0.f);
                r1.x = fmaxf(r1.x, 0.f); r1.y = fmaxf(r1.y, 0.f);
            }
            if (resid) {
                float2 q0 = *reinterpret_cast<const float2*>(resid + (size_t)mrow * N + ncol);
                float2 q1 = *reinterpret_cast<const float2*>(resid + (size_t)(mrow + 8) * N + ncol);
                r0.x += q0.x; r0.y += q0.y; r1.x += q1.x; r1.y += q1.y;
            }
            *reinterpret_cast<float2*>(C + (size_t)mrow * N + ncol) = r0;
            *reinterpret_cast<float2*>(C + (size_t)(mrow + 8) * N + ncol) = r1;
        }
    }
}

// ---------------- fallback SIMT NT GEMM (small N, e.g. gates) ----------------
__global__ __launch_bounds__(256) void gemm_nt_kernel(
    const float* __restrict__ A, const float* __restrict__ B, float* __restrict__ C,
    int M, int Ncols, int K, const float* __restrict__ bias, int bias_mode,
    const float* __restrict__ resid, int act)
{
    __shared__ float As[16][64];
    __shared__ float Bs[16][64];
    const int tid = threadIdx.x;
    const int tx  = tid & 15;
    const int ty  = tid >> 4;
    const int bm0 = blockIdx.y * 64;
    const int bn0 = blockIdx.x * 64;
    const int lr  = tid >> 2;
    const int lk  = (tid & 3) << 2;

    float acc[4][4];
#pragma unroll
    for (int i = 0; i < 4; i++)
#pragma unroll
        for (int j = 0; j < 4; j++) acc[i][j] = 0.f;

    for (int k0 = 0; k0 < K; k0 += 16) {
        {
            int am = bm0 + lr;
            float4 av = make_float4(0.f, 0.f, 0.f, 0.f);
            if (am < M) av = *reinterpret_cast<const float4*>(A + (size_t)am * K + k0 + lk);
            As[lk + 0][lr] = av.x; As[lk + 1][lr] = av.y;
            As[lk + 2][lr] = av.z; As[lk + 3][lr] = av.w;
        }
        {
            int bn = bn0 + lr;
            float4 bv = make_float4(0.f, 0.f, 0.f, 0.f);
            if (bn < Ncols) bv = *reinterpret_cast<const float4*>(B + (size_t)bn * K + k0 + lk);
            Bs[lk + 0][lr] = bv.x; Bs[lk + 1][lr] = bv.y;
            Bs[lk + 2][lr] = bv.z; Bs[lk + 3][lr] = bv.w;
        }
        __syncthreads();
#pragma unroll
        for (int kk = 0; kk < 16; kk++) {
            float4 a = *reinterpret_cast<const float4*>(&As[kk][ty << 2]);
            float4 b = *reinterpret_cast<const float4*>(&Bs[kk][tx << 2]);
            acc[0][0] += a.x * b.x; acc[0][1] += a.x * b.y; acc[0][2] += a.x * b.z; acc[0][3] += a.x * b.w;
            acc[1][0] += a.y * b.x; acc[1][1] += a.y * b.y; acc[1][2] += a.y * b.z; acc[1][3] += a.y * b.w;
            acc[2][0] += a.z * b.x; acc[2][1] += a.z * b.y; acc[2][2] += a.z * b.z; acc[2][3] += a.z * b.w;
            acc[3][0] += a.w * b.x; acc[3][1] += a.w * b.y; acc[3][2] += a.w * b.z; acc[3][3] += a.w * b.w;
        }
        __syncthreads();
    }
#pragma unroll
    for (int i = 0; i < 4; i++) {
        int m = bm0 + (ty << 2) + i;
        if (m >= M) continue;
#pragma unroll
        for (int j = 0; j < 4; j++) {
            int nn = bn0 + (tx << 2) + j;
            if (nn >= Ncols) continue;
            float vv = acc[i][j];
            if (bias_mode == 1) vv += bias[nn];
            else if (bias_mode == 2) vv += bias[m];
            if (act == 1) vv = fmaxf(vv, 0.f);
            else if (act == 2) vv = 1.f / (1.f + expf(-vv));
            if (resid) vv += resid[(size_t)m * Ncols + nn];
            C[(size_t)m * Ncols + nn] = vv;
        }
    }
}

// ---------------- transpose (R,Ccols) -> (Ccols,R) ----------------
__global__ void transpose_kernel(const float* __restrict__ in, float* __restrict__ out,
                                 int R, int Ccols)
{
    __shared__ float tile[32][33];
    int r0 = blockIdx.y * 32, c0 = blockIdx.x * 32;
#pragma unroll
    for (int i = 0; i < 32; i += 8) {
        int r = r0 + threadIdx.y + i, c = c0 + threadIdx.x;
        if (r < R && c < Ccols) tile[threadIdx.y + i][threadIdx.x] = in[(size_t)r * Ccols + c];
    }
    __syncthreads();
#pragma unroll
    for (int i = 0; i < 32; i += 8) {
        int rr = c0 + threadIdx.y + i, cc = r0 + threadIdx.x;
        if (rr < Ccols && cc < R) out[(size_t)rr * R + cc] = tile[threadIdx.x][threadIdx.y + i];
    }
}

// ---------------- RMSNorm over rows of (N, C) ----------------
__global__ void rmsnorm_kernel(const float* __restrict__ xs_t, const float* __restrict__ g,
                               float* __restrict__ h)
{
    int n = blockIdx.x, tid = threadIdx.x;
    const float* row = xs_t + (size_t)n * CDIM;
    float s = 0.f;
    for (int c = tid; c < CDIM; c += 256) { float v = row[c]; s += v * v; }
    __shared__ float red[256];
    red[tid] = s; __syncthreads();
    for (int o = 128; o; o >>= 1) { if (tid < o) red[tid] += red[tid + o]; __syncthreads(); }
    float inv = rsqrtf(red[0] / (float)CDIM + 1e-6f);
    for (int c = tid; c < CDIM; c += 256)
        h[(size_t)n * CDIM + c] = row[c] * inv * g[c];
}

// ---------------- RoPE on q and k ----------------
__global__ void rope_kernel(const float* __restrict__ q, const float* __restrict__ k,
                            float* __restrict__ rq, float* __restrict__ rk)
{
    int p = blockIdx.x * blockDim.x + threadIdx.x;
    if (p >= NTOK * (DIDIM / 2)) return;
    int n = p / (DIDIM / 2);
    int r = p % (DIDIM / 2);
    int i = r & 31;
    int base = n * DIDIM + (r >> 5) * DH + 2 * i;
    double inv = pow(10000.0, -(double)(2 * i) / 64.0);
    double ang = (double)n * inv;
    float c = (float)cos(ang), s = (float)sin(ang);
    float q0 = q[base], q1 = q[base + 1];
    rq[base]     = q0 * c - q1 * s;
    rq[base + 1] = q1 * c + q0 * s;
    float k0 = k[base], k1 = k[base + 1];
    rk[base]     = k0 * c - k1 * s;
    rk[base + 1] = k1 * c + k0 * s;
}

// ---------------- build compression MLP inputs ----------------
__global__ void build_kin_kernel(const float* __restrict__ k, const float* __restrict__ v,
                                 const float* __restrict__ k_pos, const float* __restrict__ v_pos,
                                 float* __restrict__ kin, float* __restrict__ vin)
{
    int idx = blockIdx.x * 256 + threadIdx.x;
    if (idx >= 2048 * 1024) return;
    int row = idx >> 10;
    int col = idx & 1023;
    int hh = row >> 8, cb = row & 255;
    int i = col >> 6, d = col & 63;
    int n = cb * CBLK + i;
    size_t ko = (size_t)n * DIDIM + hh * DH + d;
    size_t po = (size_t)(hh * CBLK + i) * DH + d;
    kin[idx] = k[ko] + k_pos[po];
    vin[idx] = v[ko] + v_pos[po];
}

// ---------------- concat mem slot + compressed k/v ----------------
__global__ void build_ckcv_kernel(const float* __restrict__ ckf, const float* __restrict__ cvf,
                                  const float* __restrict__ mem_k, const float* __restrict__ mem_v,
                                  float* __restrict__ ck, float* __restrict__ cv)
{
    int idx = blockIdx.x * 256 + threadIdx.x;
    if (idx >= NHEADS * NCOARSE * DH) return;
    int hh = idx / (NCOARSE * DH);
    int rem = idx - hh * (NCOARSE * DH);
    int j = rem / DH, d = rem % DH;
    if (j == 0) {
        ck[idx] = mem_k[hh * DH + d];
        cv[idx] = mem_v[hh * DH + d];
    } else {
        size_t src = (size_t)((hh << 8) + j - 1) * DH + d;
        ck[idx] = ckf[src];
        cv[idx] = cvf[src];
    }
}

// ---------------- compressed attention: csim (stored) + softmax + AV ----------------
__global__ __launch_bounds__(256) void csim_comp_kernel(
    const float* __restrict__ q, const float* __restrict__ ck, const float* __restrict__ cv,
    float* __restrict__ csim, float* __restrict__ comp)
{
    __shared__ float sq[8][64];
    __shared__ float sims[8][258];
    const int hh = blockIdx.y;
    const int n0 = blockIdx.x * 8;
    const int tid = threadIdx.x;
    const float SCALE = 0.125f;

    for (int t = tid; t < 8 * 64; t += 256) {
        int r = t >> 6, d = t & 63;
        sq[r][d] = q[(size_t)(n0 + r) * DIDIM + hh * DH + d];
    }
    __syncthreads();

    for (int j = tid; j < NCOARSE; j += 256) {
        const float* ckr = ck + ((size_t)(hh * NCOARSE + j) << 6);
        float acc[8] = {0.f, 0.f, 0.f, 0.f, 0.f, 0.f, 0.f, 0.f};
#pragma unroll 4
        for (int d = 0; d < 64; d++) {
            float kv = ckr[d];
#pragma unroll
            for (int r = 0; r < 8; r++) acc[r] += kv * sq[r][d];
        }
#pragma unroll
        for (int r = 0; r < 8; r++) {
            int n = n0 + r;
            float s = (j <= (n >> 4)) ? acc[r] * SCALE : -FLT_MAX;
            csim[((size_t)hh * NTOK + n) * NCOARSE + j] = s;
            sims[r][j] = s;
        }
    }
    __syncthreads();

    const int r = tid >> 5, lane = tid & 31;
    const int n = n0 + r;
    const int jmax = n >> 4;
    float m = -FLT_MAX;
    for (int j = lane; j <= jmax; j += 32) m = fmaxf(m, sims[r][j]);
    for (int o = 16; o; o >>= 1) m = fmaxf(m, __shfl_xor_sync(0xffffffffu, m, o));
    float z = 0.f;
    for (int j = lane; j <= jmax; j += 32) {
        float e = expf(sims[r][j] - m);
        sims[r][j] = e;
        z += e;
    }
    for (int o = 16; o; o >>= 1) z += __shfl_xor_sync(0xffffffffu, z, o);
    __syncwarp();
    float invz = 1.f / z;
    for (int d = lane; d < 64; d += 32) {
        float acc = 0.f;
        for (int j = 0; j <= jmax; j++)
            acc += sims[r][j] * cv[((size_t)(hh * NCOARSE + j) << 6) + d];
        comp[((size_t)hh * NTOK + n) * DH + d] = acc * invz;
    }
}

// ---------------- top-2 helpers ----------------
__device__ __forceinline__ void top2_insert(float v, int f,
                                            float& t1v, int& t1f, float& t2v, int& t2f)
{
    if (f == t1f || f == t2f) return;
    if (v > t1v || (v == t1v && f < t1f)) { t2v = t1v; t2f = t1f; t1v = v; t1f = f; }
    else if (v > t2v || (v == t2v && f < t2f)) { t2v = v; t2f = f; }
}

// ---------------- top-k select + fine attn + sliding attn + gated combine ----------------
__global__ __launch_bounds__(256) void fine_slide_kernel(
    const float* __restrict__ rq, const float* __restrict__ rk, const float* __restrict__ v,
    const float* __restrict__ csim, const float* __restrict__ comp,
    const float* __restrict__ gates, float* __restrict__ attn)
{
    const int hh = blockIdx.y;
    const int warp = threadIdx.x >> 5, lane = threadIdx.x & 31;
    const int n = blockIdx.x * 8 + warp;
    const float SCALE = 0.125f;
    const unsigned FULL = 0xffffffffu;

    const size_t qb = (size_t)n * DIDIM + hh * DH;
    const float q0 = rq[qb + lane];
    const float q1 = rq[qb + lane + 32];

    const int nfb = n >> 1;
    float t1v = -INFINITY, t2v = -INFINITY;
    int   t1f = INT_MAX,   t2f = INT_MAX;
    float vloc[8]; int cloc[8];
    const size_t cbase = ((size_t)hh * NTOK + n) * NCOARSE + 1;
#pragma unroll
    for (int i = 0; i < 8; i++) {
        int jp = i * 32 + lane;
        int cnt = nfb - jp * 8;
        cnt = cnt > 8 ? 8 : cnt;
        if (cnt > 0) {
            float val = csim[cbase + jp];
            vloc[i] = val; cloc[i] = cnt;
            top2_insert(val, jp * 8, t1v, t1f, t2v, t2f);
            if (cnt > 1) top2_insert(val, jp * 8 + 1, t1v, t1f, t2v, t2f);
        } else cloc[i] = 0;
    }
    for (int o = 16; o; o >>= 1) {
        float ov1 = __shfl_xor_sync(FULL, t1v, o); int of1 = __shfl_xor_sync(FULL, t1f, o);
        float ov2 = __shfl_xor_sync(FULL, t2v, o); int of2 = __shfl_xor_sync(FULL, t2f, o);
        top2_insert(ov1, of1, t1v, t1f, t2v, t2f);
        top2_insert(ov2, of2, t1v, t1f, t2v, t2f);
    }
    const float mx = fmaxf(t1v, -1000.f);
    float part = 0.f;
#pragma unroll
    for (int i = 0; i < 8; i++)
        if (cloc[i]) part += (float)cloc[i] * expf(vloc[i] - mx);
    for (int o = 16; o; o >>= 1) part += __shfl_xor_sync(FULL, part, o);
    const float Z = expf(-1000.f - mx) + part;

    int fb1, fb2; float sv1, sv2;
    if (t1f == INT_MAX) { fb1 = 0; fb2 = 1; sv1 = 0.f; sv2 = 0.f; }
    else {
        fb1 = t1f; sv1 = expf(t1v - mx) / Z;
        if (t2f == INT_MAX) { fb2 = (t1f == 0) ? 1 : 0; sv2 = 0.f; }
        else { fb2 = t2f; sv2 = expf(t2v - mx) / Z; }
    }

    int rows6[6]; float sims6[6];
    const int blks[3] = { fb1, fb2, n >> 1 };
    const float svs[2] = { sv1, sv2 };
#pragma unroll
    for (int e = 0; e < 6; e++) {
        int b = blks[e >> 1], s = e & 1;
        int row = b * 2 + s;
        rows6[e] = row;
        bool vld = (e < 4) ? (svs[e >> 1] > 1e-10f) : (s <= (n & 1));
        size_t kb = (size_t)row * DIDIM + hh * DH;
        float p = q0 * rk[kb + lane] + q1 * rk[kb + lane + 32];
        for (int o = 16; o; o >>= 1) p += __shfl_xor_sync(FULL, p, o);
        sims6[e] = vld ? p * SCALE : -FLT_MAX;
    }
    float fm = -FLT_MAX;
#pragma unroll
    for (int e = 0; e < 6; e++) fm = fmaxf(fm, sims6[e]);
    float fz = 0.f, fo0 = 0.f, fo1 = 0.f;
#pragma unroll
    for (int e = 0; e < 6; e++) {
        float pe = expf(sims6[e] - fm);
        fz += pe;
        size_t vb = (size_t)rows6[e] * DIDIM + hh * DH;
        fo0 += pe * v[vb + lane];
        fo1 += pe * v[vb + lane + 32];
    }
    fo0 /= fz; fo1 /= fz;

    float simsw[SWIN + 1];
#pragma unroll
    for (int w = 0; w <= SWIN; w++) {
        int row = n - SWIN + w;
        bool vld = (row >= 0);
        size_t kb = (size_t)(vld ? row : 0) * DIDIM + hh * DH;
        float k0 = vld ? rk[kb + lane] : 0.f;
        float k1 = vld ? rk[kb + lane + 32] : 0.f;
        float p = q0 * k0 + q1 * k1;
        for (int o = 16; o; o >>= 1) p += __shfl_xor_sync(FULL, p, o);
        simsw[w] = vld ? p * SCALE : -FLT_MAX;
    }
    float sm = -FLT_MAX;
#pragma unroll
    for (int w = 0; w <= SWIN; w++) sm = fmaxf(sm, simsw[w]);
    float sz = 0.f, so0 = 0.f, so1 = 0.f;
#pragma unroll
    for (int w = 0; w <= SWIN; w++) {
        float pe = expf(simsw[w] - sm);
        sz += pe;
        int row = n - SWIN + w;
        if (row >= 0) {
            size_t vb = (size_t)row * DIDIM + hh * DH;
            so0 += pe * v[vb + lane];
            so1 += pe * v[vb + lane + 32];
        }
    }
    so0 /= sz; so1 /= sz;

    const float g0 = gates[n * 24 + hh * 3 + 0];
    const float g1 = gates[n * 24 + hh * 3 + 1];
    const float g2 = gates[n * 24 + hh * 3 + 2];
    const size_t cb2 = ((size_t)hh * NTOK + n) * DH;
    const float c0 = comp[cb2 + lane], c1 = comp[cb2 + lane + 32];
    attn[qb + lane]      = g0 * c0 + g1 * fo0 + g2 * so0;
    attn[qb + lane + 32] = g0 * c1 + g1 * fo1 + g2 * so1;
}

// ---------------- host-side orchestration ----------------
static inline void launch_gemm_simt(const float* A, const float* B, float* C,
                                    int M, int Ncols, int K,
                                    const float* bias, int bias_mode,
                                    const float* resid, int act)
{
    dim3 grid((Ncols + 63) / 64, (M + 63) / 64);
    gemm_nt_kernel<<<grid, 256>>>(A, B, C, M, Ncols, K, bias, bias_mode, resid, act);
}

static inline void launch_gemm_tc(const float* A, const float* B, float* C,
                                  int M, int N, int K,
                                  const float* bias, int bias_mode,
                                  const float* resid, int act)
{
    if (N % 128 == 0) {
        size_t smem = (size_t)(2 * 4096 * 2 + 2 * 128 * 32 * 2) * sizeof(float); // 128KB
        cudaFuncSetAttribute(gemm_tf32_kernel<128>,
                             cudaFuncAttributeMaxDynamicSharedMemorySize, (int)smem);
        dim3 grid(N / 128, M / 128);
        gemm_tf32_kernel<128><<<grid, 256, smem>>>(A, B, C, M, N, K, bias, bias_mode, resid, act);
    } else {
        size_t smem = (size_t)(2 * 4096 * 2 + 2 * 64 * 32 * 2) * sizeof(float);  // 96KB
        cudaFuncSetAttribute(gemm_tf32_kernel<64>,
                             cudaFuncAttributeMaxDynamicSharedMemorySize, (int)smem);
        dim3 grid(N / 64, M / 128);
        gemm_tf32_kernel<64><<<grid, 256, smem>>>(A, B, C, M, N, K, bias, bias_mode, resid, act);
    }
}

extern "C" void kernel_launch(void* const* d_in, const int* in_sizes, int n_in,
                              void* d_out, int out_size)
{
    (void)in_sizes; (void)n_in; (void)out_size;
    float* base = nullptr;
    cudaGetSymbolAddress((void**)&base, g_buf);

    const float* x       = (const float*)d_in[0];
    const float* w_in    = (const float*)d_in[1];
    const float* b_in    = (const float*)d_in[2];
    const float* g_norm  = (const float*)d_in[3];
    const float* wq      = (const float*)d_in[4];
    const float* wk      = (const float*)d_in[5];
    const float* wv      = (const float*)d_in[6];
    const float* k_pos   = (const float*)d_in[7];
    const float* v_pos   = (const float*)d_in[8];
    const float* mem_k   = (const float*)d_in[9];
    const float* mem_v   = (const float*)d_in[10];
    const float* kc_w1   = (const float*)d_in[11];
    const float* kc_b1   = (const float*)d_in[12];
    const float* kc_w2   = (const float*)d_in[13];
    const float* kc_b2   = (const float*)d_in[14];
    const float* vc_w1   = (const float*)d_in[15];
    const float* vc_b1   = (const float*)d_in[16];
    const float* vc_w2   = (const float*)d_in[17];
    const float* vc_b2   = (const float*)d_in[18];
    const float* w_strat = (const float*)d_in[19];
    const float* b_strat = (const float*)d_in[20];
    const float* w_comb  = (const float*)d_in[21];
    const float* w_out   = (const float*)d_in[22];
    const float* b_out   = (const float*)d_in[23];
    float* out = (float*)d_out;

    // 1. x (C,N) -> xt (N,C)
    {
        dim3 th(32, 8), gr(NTOK / 32, CDIM / 32);
        transpose_kernel<<<gr, th>>>(x, base + O_XT, CDIM, NTOK);
    }
    // 2. xs_t = xt @ w_in^T + b_in
    launch_gemm_tc(base + O_XT, w_in, base + O_XST, NTOK, CDIM, CDIM, b_in, 1, nullptr, 0);
    // 3. xs_t (N,C) -> xs (C,N)
    {
        dim3 th(32, 8), gr(CDIM / 32, NTOK / 32);
        transpose_kernel<<<gr, th>>>(base + O_XST, base + O_XS, NTOK, CDIM);
    }
    // 4. RMSNorm
    rmsnorm_kernel<<<NTOK, 256>>>(base + O_XST, g_norm, base + O_H);
    // 5. q, k, v projections
    launch_gemm_tc(base + O_H, wq, base + O_Q, NTOK, DIDIM, CDIM, nullptr, 0, nullptr, 0);
    launch_gemm_tc(base + O_H, wk, base + O_K, NTOK, DIDIM, CDIM, nullptr, 0, nullptr, 0);
    launch_gemm_tc(base + O_H, wv, base + O_V, NTOK, DIDIM, CDIM, nullptr, 0, nullptr, 0);
    // 6. RoPE
    rope_kernel<<<(NTOK * (DIDIM / 2) + 255) / 256, 256>>>(base + O_Q, base + O_K,
                                                           base + O_RQ, base + O_RK);
    // 7. kin/vin
    build_kin_kernel<<<(2048 * 1024) / 256, 256>>>(base + O_K, base + O_V, k_pos, v_pos,
                                                   base + O_KIN, base + O_VIN);
    // 8-11. compression MLPs
    launch_gemm_tc(base + O_KIN, kc_w1, base + O_HID, 2048, 1024, 1024, kc_b1, 1, nullptr, 1);
    launch_gemm_tc(base + O_HID, kc_w2, base + O_CKF, 2048, 64, 1024, kc_b2, 1, nullptr, 0);
    launch_gemm_tc(base + O_VIN, vc_w1, base + O_HID, 2048, 1024, 1024, vc_b1, 1, nullptr, 1);
    launch_gemm_tc(base + O_HID, vc_w2, base + O_CVF, 2048, 64, 1024, vc_b2, 1, nullptr, 0);
    // 12. concat mem slots
    build_ckcv_kernel<<<(NHEADS * NCOARSE * DH + 255) / 256, 256>>>(
        base + O_CKF, base + O_CVF, mem_k, mem_v, base + O_CK, base + O_CV);
    // 13. compressed attention
    {
        dim3 gr(NTOK / 8, NHEADS);
        csim_comp_kernel<<<gr, 256>>>(base + O_Q, base + O_CK, base + O_CV,
                                      base + O_CSIM, base + O_COMP);
    }
    // 14. gates (small N -> SIMT)
    launch_gemm_simt(base + O_H, w_strat, base + O_GATE, NTOK, 24, CDIM, b_strat, 1, nullptr, 2);
    // 15. top-k select + fine + slide + combine
    {
        dim3 gr(NTOK / 8, NHEADS);
        fine_slide_kernel<<<gr, 256>>>(base + O_RQ, base + O_RK, base + O_V,
                                       base + O_CSIM, base + O_COMP, base + O_GATE,
                                       base + O_ATTN);
    }
    // 16. combine projection
    launch_gemm_tc(base + O_ATTN, w_comb, base + O_OUTC, NTOK, CDIM, DIDIM, nullptr, 0, nullptr, 0);
    // 17. output conv + bias + xs residual -> d_out
    launch_gemm_tc(w_out, base + O_OUTC, out, CDIM, NTOK, CDIM, b_out, 2, base + O_XS, 0);
}

// round 5
// speedup vs baseline: 1.3413x; 1.2166x over previous
#include <cuda_runtime.h>
#include <cuda_bf16.h>
#include <cfloat>
#include <climits>
#include <math.h>
#include <stdint.h>

// ---------------- problem constants ----------------
#define NTOK   4096
#define CDIM   512
#define DIDIM  512
#define NHEADS 8
#define DH     64
#define NCOARSE 257
#define CBLK   16
#define SWIN   8

static constexpr size_t SZ_NC = (size_t)NTOK * CDIM;

static constexpr size_t O_XT   = 0;
static constexpr size_t O_XST  = O_XT   + SZ_NC;
static constexpr size_t O_XS   = O_XST  + SZ_NC;
static constexpr size_t O_H    = O_XS   + SZ_NC;
static constexpr size_t O_Q    = O_H    + SZ_NC;
static constexpr size_t O_K    = O_Q    + SZ_NC;
static constexpr size_t O_V    = O_K    + SZ_NC;
static constexpr size_t O_RQ   = O_V    + SZ_NC;
static constexpr size_t O_RK   = O_RQ   + SZ_NC;
static constexpr size_t O_KIN  = O_RK   + SZ_NC;
static constexpr size_t O_VIN  = O_KIN  + SZ_NC;
static constexpr size_t O_HID  = O_VIN  + SZ_NC;
static constexpr size_t O_CKF  = O_HID  + SZ_NC;
static constexpr size_t O_CVF  = O_CKF  + (size_t)2048*64;
static constexpr size_t O_CK   = O_CVF  + (size_t)2048*64;
static constexpr size_t O_CV   = O_CK   + (size_t)NHEADS*NCOARSE*DH;
static constexpr size_t O_CSIM = O_CV   + (size_t)NHEADS*NCOARSE*DH;
static constexpr size_t O_COMP = O_CSIM + (size_t)NHEADS*NTOK*NCOARSE;
static constexpr size_t O_GATE = O_COMP + (size_t)NHEADS*NTOK*DH;
static constexpr size_t O_ATTN = O_GATE + (size_t)NTOK*24;
static constexpr size_t O_OUTC = O_ATTN + SZ_NC;
static constexpr size_t TOTAL  = O_OUTC + SZ_NC;

__device__ float g_buf[TOTAL];

// ============================================================================
// 3-limb bf16-split NT GEMM on mma.sync.m16n8k16 (fp32-class accuracy)
// C[m,n] = dot(A[m,:], B[n,:]); A (M,K) rm, B (N,K) rm; fp32 in/out.
// x = h + m + l (bf16 limbs); accumulate hh + hm + mh + hl + lh + mm.
// M%128==0, N%BN==0, K%32==0.
// ============================================================================

__device__ __forceinline__ uint32_t smem_u32(const void* p) {
    uint32_t a;
    asm("{ .reg .u64 t; cvta.to.shared.u64 t, %1; cvt.u32.u64 %0, t; }" : "=r"(a) : "l"(p));
    return a;
}

__device__ __forceinline__ void split3(float x, float y,
                                       uint32_t& hp, uint32_t& mp, uint32_t& lp)
{
    __nv_bfloat16 hx = __float2bfloat16(x), hy = __float2bfloat16(y);
    float rx = x - __bfloat162float(hx), ry = y - __bfloat162float(hy);
    __nv_bfloat16 mx = __float2bfloat16(rx), my = __float2bfloat16(ry);
    float sx = rx - __bfloat162float(mx), sy = ry - __bfloat162float(my);
    __nv_bfloat16 lx = __float2bfloat16(sx), ly = __float2bfloat16(sy);
    __nv_bfloat162 hv; hv.x = hx; hv.y = hy;
    __nv_bfloat162 mv; mv.x = mx; mv.y = my;
    __nv_bfloat162 lv; lv.x = lx; lv.y = ly;
    hp = *reinterpret_cast<uint32_t*>(&hv);
    mp = *reinterpret_cast<uint32_t*>(&mv);
    lp = *reinterpret_cast<uint32_t*>(&lv);
}

#define LDSM_X4(r0, r1, r2, r3, addr) \
    asm volatile("ldmatrix.sync.aligned.m8n8.x4.shared.b16 {%0,%1,%2,%3}, [%4];" \
                 : "=r"(r0), "=r"(r1), "=r"(r2), "=r"(r3) : "r"(addr))

__device__ __forceinline__ void mma_bf16(float4& d, const uint32_t* a, const uint32_t* b) {
    asm volatile(
        "mma.sync.aligned.m16n8k16.row.col.f32.bf16.bf16.f32 "
        "{%0,%1,%2,%3}, {%4,%5,%6,%7}, {%8,%9}, {%0,%1,%2,%3};"
        : "+f"(d.x), "+f"(d.y), "+f"(d.z), "+f"(d.w)
        : "r"(a[0]), "r"(a[1]), "r"(a[2]), "r"(a[3]), "r"(b[0]), "r"(b[1]));
}

template<int BN>
__global__ __launch_bounds__(256, 1) void gemm_bf16s_kernel(
    const float* __restrict__ A, const float* __restrict__ B, float* __restrict__ C,
    int M, int N, int K, const float* __restrict__ bias, int bias_mode,
    const float* __restrict__ resid, int act)
{
    constexpr int LDSB = 80;                 // row stride bytes (32 bf16 + 8 pad)
    constexpr int ASZ  = 128 * LDSB;         // 10240 B per limb
    constexpr int BSZ  = BN * LDSB;
    constexpr int STAGE = 3 * ASZ + 3 * BSZ;
    constexpr int NTW  = BN / 16;            // n8-tiles per warp (8 or 4)

    extern __shared__ char dsm[];
    const uint32_t sb = smem_u32(dsm);
    const int tid = threadIdx.x, warp = tid >> 5, lane = tid & 31;
    const int wm = warp >> 1, wn = warp & 1;
    const int bm0 = blockIdx.y * 128, bn0 = blockIdx.x * BN;

    float4 acc[2][NTW];
#pragma unroll
    for (int i = 0; i < 2; i++)
#pragma unroll
        for (int j = 0; j < NTW; j++) acc[i][j] = make_float4(0.f, 0.f, 0.f, 0.f);

    const int arow = tid >> 1, akh = (tid & 1) * 16;
    const float* aptr = A + (size_t)(bm0 + arow) * K + akh;
    const float* bptr = B + (size_t)(bn0 + arow) * K + akh;   // valid when arow < BN

    float4 areg[4], breg[4];

    auto ldg_tiles = [&](int k0) {
#pragma unroll
        for (int i = 0; i < 4; i++) areg[i] = *reinterpret_cast<const float4*>(aptr + k0 + i * 4);
        if (BN == 128 || arow < BN) {
#pragma unroll
            for (int i = 0; i < 4; i++) breg[i] = *reinterpret_cast<const float4*>(bptr + k0 + i * 4);
        }
    };

    auto sts_split = [&](char* hb, char* mb, char* lb, float4* rg) {
        uint32_t h[8], m[8], l[8];
#pragma unroll
        for (int i = 0; i < 4; i++) {
            const float* f = reinterpret_cast<const float*>(&rg[i]);
#pragma unroll
            for (int j = 0; j < 2; j++)
                split3(f[2 * j], f[2 * j + 1], h[2 * i + j], m[2 * i + j], l[2 * i + j]);
        }
        int off = arow * LDSB + akh * 2;
        *reinterpret_cast<uint4*>(hb + off)      = make_uint4(h[0], h[1], h[2], h[3]);
        *reinterpret_cast<uint4*>(hb + off + 16) = make_uint4(h[4], h[5], h[6], h[7]);
        *reinterpret_cast<uint4*>(mb + off)      = make_uint4(m[0], m[1], m[2], m[3]);
        *reinterpret_cast<uint4*>(mb + off + 16) = make_uint4(m[4], m[5], m[6], m[7]);
        *reinterpret_cast<uint4*>(lb + off)      = make_uint4(l[0], l[1], l[2], l[3]);
        *reinterpret_cast<uint4*>(lb + off + 16) = make_uint4(l[4], l[5], l[6], l[7]);
    };

    auto sts_tiles = [&](int st) {
        char* base = dsm + st * STAGE;
        sts_split(base, base + ASZ, base + 2 * ASZ, areg);
        if (BN == 128 || arow < BN)
            sts_split(base + 3 * ASZ, base + 3 * ASZ + BSZ, base + 3 * ASZ + 2 * BSZ, breg);
    };

    // ldmatrix address components (constant across slabs)
    const int a_r  = wm * 32 + (lane & 7) + ((lane >> 3) & 1) * 8;   // + mi*16
    const int a_kc = (lane >> 4) * 8;                                // + kk*16
    const int b_sel = lane >> 3;
    const int b_r   = wn * (BN / 2) + (b_sel >> 1) * 8 + (lane & 7); // + np*16
    const int b_kc  = (b_sel & 1) * 8;                               // + kk*16

    auto compute = [&](int st) {
        const uint32_t s0 = sb + st * STAGE;
#pragma unroll
        for (int kk = 0; kk < 2; kk++) {
            uint32_t afh[2][4], afm[2][4], afl[2][4];
#pragma unroll
            for (int mi = 0; mi < 2; mi++) {
                int off = (a_r + mi * 16) * LDSB + (a_kc + kk * 16) * 2;
                LDSM_X4(afh[mi][0], afh[mi][1], afh[mi][2], afh[mi][3], s0 + off);
                LDSM_X4(afm[mi][0], afm[mi][1], afm[mi][2], afm[mi][3], s0 + ASZ + off);
                LDSM_X4(afl[mi][0], afl[mi][1], afl[mi][2], afl[mi][3], s0 + 2 * ASZ + off);
            }
#pragma unroll
            for (int np = 0; np < NTW / 2; np++) {
                int off = (b_r + np * 16) * LDSB + (b_kc + kk * 16) * 2;
                uint32_t bh[2][2], bm[2][2], bl[2][2];
                LDSM_X4(bh[0][0], bh[0][1], bh[1][0], bh[1][1], s0 + 3 * ASZ + off);
                LDSM_X4(bm[0][0], bm[0][1], bm[1][0], bm[1][1], s0 + 3 * ASZ + BSZ + off);
                LDSM_X4(bl[0][0], bl[0][1], bl[1][0], bl[1][1], s0 + 3 * ASZ + 2 * BSZ + off);
#pragma unroll
                for (int mi = 0; mi < 2; mi++)
#pragma unroll
                    for (int q = 0; q < 2; q++) {
                        int ni = 2 * np + q;
                        mma_bf16(acc[mi][ni], afh[mi], bh[q]);
                        mma_bf16(acc[mi][ni], afh[mi], bm[q]);
                        mma_bf16(acc[mi][ni], afm[mi], bh[q]);
                        mma_bf16(acc[mi][ni], afh[mi], bl[q]);
                        mma_bf16(acc[mi][ni], afl[mi], bh[q]);
                        mma_bf16(acc[mi][ni], afm[mi], bm[q]);
                    }
            }
        }
    };

    ldg_tiles(0);
    sts_tiles(0);
    __syncthreads();

    const int slabs = K / 32;
    for (int s = 0; s < slabs; s++) {
        int st = s & 1;
        if (s + 1 < slabs) ldg_tiles((s + 1) * 32);
        compute(st);
        if (s + 1 < slabs) sts_tiles(st ^ 1);
        __syncthreads();
    }

    // epilogue
    const int g = lane >> 2, cc = lane & 3;
#pragma unroll
    for (int mi = 0; mi < 2; mi++) {
#pragma unroll
        for (int ni = 0; ni < NTW; ni++) {
            int mrow = bm0 + wm * 32 + mi * 16 + g;
            int ncol = bn0 + wn * (BN / 2) + ni * 8 + cc * 2;
            float2 r0 = make_float2(acc[mi][ni].x, acc[mi][ni].y);
            float2 r1 = make_float2(acc[mi][ni].z, acc[mi][ni].w);
            if (bias_mode == 1) {
                float b0 = bias[ncol], b1 = bias[ncol + 1];
                r0.x += b0; r0.y += b1; r1.x += b0; r1.y += b1;
            } else if (bias_mode == 2) {
                float bt = bias[mrow], bb = bias[mrow + 8];
                r0.x += bt; r0.y += bt; r1.x += bb; r1.y += bb;
            }
            if (act == 1) {
                r0.x = fmaxf(r0.x, 0.f); r0.y = fmaxf(r0.y, 0.f);
                r1.x = fmaxf(r1.x, 0.f); r1.y = fmaxf(r1.y, 0.f);
            }
            if (resid) {
                float2 q0 = *reinterpret_cast<const float2*>(resid + (size_t)mrow * N + ncol);
                float2 q1 = *reinterpret_cast<const float2*>(resid + (size_t)(mrow + 8) * N + ncol);
                r0.x += q0.x; r0.y += q0.y; r1.x += q1.x; r1.y += q1.y;
            }
            *reinterpret_cast<float2*>(C + (size_t)mrow * N + ncol) = r0;
            *reinterpret_cast<float2*>(C + (size_t)(mrow + 8) * N + ncol) = r1;
        }
    }
}

// ---------------- SIMT NT GEMM (gates only) ----------------
__global__ __launch_bounds__(256) void gemm_nt_kernel(
    const float* __restrict__ A, const float* __restrict__ B, float* __restrict__ C,
    int M, int Ncols, int K, const float* __restrict__ bias, int bias_mode,
    const float* __restrict__ resid, int act)
{
    __shared__ float As[16][64];
    __shared__ float Bs[16][64];
    const int tid = threadIdx.x;
    const int tx  = tid & 15;
    const int ty  = tid >> 4;
    const int bm0 = blockIdx.y * 64;
    const int bn0 = blockIdx.x * 64;
    const int lr  = tid >> 2;
    const int lk  = (tid & 3) << 2;

    float acc[4][4];
#pragma unroll
    for (int i = 0; i < 4; i++)
#pragma unroll
        for (int j = 0; j < 4; j++) acc[i][j] = 0.f;

    for (int k0 = 0; k0 < K; k0 += 16) {
        {
            int am = bm0 + lr;
            float4 av = make_float4(0.f, 0.f, 0.f, 0.f);
            if (am < M) av = *reinterpret_cast<const float4*>(A + (size_t)am * K + k0 + lk);
            As[lk + 0][lr] = av.x; As[lk + 1][lr] = av.y;
            As[lk + 2][lr] = av.z; As[lk + 3][lr] = av.w;
        }
        {
            int bn = bn0 + lr;
            float4 bv = make_float4(0.f, 0.f, 0.f, 0.f);
            if (bn < Ncols) bv = *reinterpret_cast<const float4*>(B + (size_t)bn * K + k0 + lk);
            Bs[lk + 0][lr] = bv.x; Bs[lk + 1][lr] = bv.y;
            Bs[lk + 2][lr] = bv.z; Bs[lk + 3][lr] = bv.w;
        }
        __syncthreads();
#pragma unroll
        for (int kk = 0; kk < 16; kk++) {
            float4 a = *reinterpret_cast<const float4*>(&As[kk][ty << 2]);
            float4 b = *reinterpret_cast<const float4*>(&Bs[kk][tx << 2]);
            acc[0][0] += a.x * b.x; acc[0][1] += a.x * b.y; acc[0][2] += a.x * b.z; acc[0][3] += a.x * b.w;
            acc[1][0] += a.y * b.x; acc[1][1] += a.y * b.y; acc[1][2] += a.y * b.z; acc[1][3] += a.y * b.w;
            acc[2][0] += a.z * b.x; acc[2][1] += a.z * b.y; acc[2][2] += a.z * b.z; acc[2][3] += a.z * b.w;
            acc[3][0] += a.w * b.x; acc[3][1] += a.w * b.y; acc[3][2] += a.w * b.z; acc[3][3] += a.w * b.w;
        }
        __syncthreads();
    }
#pragma unroll
    for (int i = 0; i < 4; i++) {
        int m = bm0 + (ty << 2) + i;
        if (m >= M) continue;
#pragma unroll
        for (int j = 0; j < 4; j++) {
            int nn = bn0 + (tx << 2) + j;
            if (nn >= Ncols) continue;
            float vv = acc[i][j];
            if (bias_mode == 1) vv += bias[nn];
            else if (bias_mode == 2) vv += bias[m];
            if (act == 1) vv = fmaxf(vv, 0.f);
            else if (act == 2) vv = 1.f / (1.f + expf(-vv));
            if (resid) vv += resid[(size_t)m * Ncols + nn];
            C[(size_t)m * Ncols + nn] = vv;
        }
    }
}

// ---------------- transpose ----------------
__global__ void transpose_kernel(const float* __restrict__ in, float* __restrict__ out,
                                 int R, int Ccols)
{
    __shared__ float tile[32][33];
    int r0 = blockIdx.y * 32, c0 = blockIdx.x * 32;
#pragma unroll
    for (int i = 0; i < 32; i += 8) {
        int r = r0 + threadIdx.y + i, c = c0 + threadIdx.x;
        if (r < R && c < Ccols) tile[threadIdx.y + i][threadIdx.x] = in[(size_t)r * Ccols + c];
    }
    __syncthreads();
#pragma unroll
    for (int i = 0; i < 32; i += 8) {
        int rr = c0 + threadIdx.y + i, cc = r0 + threadIdx.x;
        if (rr < Ccols && cc < R) out[(size_t)rr * R + cc] = tile[threadIdx.x][threadIdx.y + i];
    }
}

// ---------------- RMSNorm ----------------
__global__ void rmsnorm_kernel(const float* __restrict__ xs_t, const float* __restrict__ g,
                               float* __restrict__ h)
{
    int n = blockIdx.x, tid = threadIdx.x;
    const float* row = xs_t + (size_t)n * CDIM;
    float s = 0.f;
    for (int c = tid; c < CDIM; c += 256) { float v = row[c]; s += v * v; }
    __shared__ float red[256];
    red[tid] = s; __syncthreads();
    for (int o = 128; o; o >>= 1) { if (tid < o) red[tid] += red[tid + o]; __syncthreads(); }
    float inv = rsqrtf(red[0] / (float)CDIM + 1e-6f);
    for (int c = tid; c < CDIM; c += 256)
        h[(size_t)n * CDIM + c] = row[c] * inv * g[c];
}

// ---------------- RoPE ----------------
__global__ void rope_kernel(const float* __restrict__ q, const float* __restrict__ k,
                            float* __restrict__ rq, float* __restrict__ rk)
{
    int p = blockIdx.x * blockDim.x + threadIdx.x;
    if (p >= NTOK * (DIDIM / 2)) return;
    int n = p / (DIDIM / 2);
    int r = p % (DIDIM / 2);
    int i = r & 31;
    int base = n * DIDIM + (r >> 5) * DH + 2 * i;
    double inv = pow(10000.0, -(double)(2 * i) / 64.0);
    double ang = (double)n * inv;
    float c = (float)cos(ang), s = (float)sin(ang);
    float q0 = q[base], q1 = q[base + 1];
    rq[base]     = q0 * c - q1 * s;
    rq[base + 1] = q1 * c + q0 * s;
    float k0 = k[base], k1 = k[base + 1];
    rk[base]     = k0 * c - k1 * s;
    rk[base + 1] = k1 * c + k0 * s;
}

// ---------------- build compression MLP inputs ----------------
__global__ void build_kin_kernel(const float* __restrict__ k, const float* __restrict__ v,
                                 const float* __restrict__ k_pos, const float* __restrict__ v_pos,
                                 float* __restrict__ kin, float* __restrict__ vin)
{
    int idx = blockIdx.x * 256 + threadIdx.x;
    if (idx >= 2048 * 1024) return;
    int row = idx >> 10;
    int col = idx & 1023;
    int hh = row >> 8, cb = row & 255;
    int i = col >> 6, d = col & 63;
    int n = cb * CBLK + i;
    size_t ko = (size_t)n * DIDIM + hh * DH + d;
    size_t po = (size_t)(hh * CBLK + i) * DH + d;
    kin[idx] = k[ko] + k_pos[po];
    vin[idx] = v[ko] + v_pos[po];
}

// ---------------- concat mem slot + compressed k/v ----------------
__global__ void build_ckcv_kernel(const float* __restrict__ ckf, const float* __restrict__ cvf,
                                  const float* __restrict__ mem_k, const float* __restrict__ mem_v,
                                  float* __restrict__ ck, float* __restrict__ cv)
{
    int idx = blockIdx.x * 256 + threadIdx.x;
    if (idx >= NHEADS * NCOARSE * DH) return;
    int hh = idx / (NCOARSE * DH);
    int rem = idx - hh * (NCOARSE * DH);
    int j = rem / DH, d = rem % DH;
    if (j == 0) {
        ck[idx] = mem_k[hh * DH + d];
        cv[idx] = mem_v[hh * DH + d];
    } else {
        size_t src = (size_t)((hh << 8) + j - 1) * DH + d;
        ck[idx] = ckf[src];
        cv[idx] = cvf[src];
    }
}

// ---------------- compressed attention ----------------
__global__ __launch_bounds__(256) void csim_comp_kernel(
    const float* __restrict__ q, const float* __restrict__ ck, const float* __restrict__ cv,
    float* __restrict__ csim, float* __restrict__ comp)
{
    __shared__ float sq[8][64];
    __shared__ float sims[8][258];
    const int hh = blockIdx.y;
    const int n0 = blockIdx.x * 8;
    const int tid = threadIdx.x;
    const float SCALE = 0.125f;

    for (int t = tid; t < 8 * 64; t += 256) {
        int r = t >> 6, d = t & 63;
        sq[r][d] = q[(size_t)(n0 + r) * DIDIM + hh * DH + d];
    }
    __syncthreads();

    for (int j = tid; j < NCOARSE; j += 256) {
        const float* ckr = ck + ((size_t)(hh * NCOARSE + j) << 6);
        float acc[8] = {0.f, 0.f, 0.f, 0.f, 0.f, 0.f, 0.f, 0.f};
#pragma unroll 4
        for (int d = 0; d < 64; d++) {
            float kv = ckr[d];
#pragma unroll
            for (int r = 0; r < 8; r++) acc[r] += kv * sq[r][d];
        }
#pragma unroll
        for (int r = 0; r < 8; r++) {
            int n = n0 + r;
            float s = (j <= (n >> 4)) ? acc[r] * SCALE : -FLT_MAX;
            csim[((size_t)hh * NTOK + n) * NCOARSE + j] = s;
            sims[r][j] = s;
        }
    }
    __syncthreads();

    const int r = tid >> 5, lane = tid & 31;
    const int n = n0 + r;
    const int jmax = n >> 4;
    float m = -FLT_MAX;
    for (int j = lane; j <= jmax; j += 32) m = fmaxf(m, sims[r][j]);
    for (int o = 16; o; o >>= 1) m = fmaxf(m, __shfl_xor_sync(0xffffffffu, m, o));
    float z = 0.f;
    for (int j = lane; j <= jmax; j += 32) {
        float e = expf(sims[r][j] - m);
        sims[r][j] = e;
        z += e;
    }
    for (int o = 16; o; o >>= 1) z += __shfl_xor_sync(0xffffffffu, z, o);
    __syncwarp();
    float invz = 1.f / z;
    for (int d = lane; d < 64; d += 32) {
        float acc = 0.f;
        for (int j = 0; j <= jmax; j++)
            acc += sims[r][j] * cv[((size_t)(hh * NCOARSE + j) << 6) + d];
        comp[((size_t)hh * NTOK + n) * DH + d] = acc * invz;
    }
}

// ---------------- top-2 helper ----------------
__device__ __forceinline__ void top2_insert(float v, int f,
                                            float& t1v, int& t1f, float& t2v, int& t2f)
{
    if (f == t1f || f == t2f) return;
    if (v > t1v || (v == t1v && f < t1f)) { t2v = t1v; t2f = t1f; t1v = v; t1f = f; }
    else if (v > t2v || (v == t2v && f < t2f)) { t2v = v; t2f = f; }
}

// ---------------- top-k + fine + slide + combine ----------------
__global__ __launch_bounds__(256) void fine_slide_kernel(
    const float* __restrict__ rq, const float* __restrict__ rk, const float* __restrict__ v,
    const float* __restrict__ csim, const float* __restrict__ comp,
    const float* __restrict__ gates, float* __restrict__ attn)
{
    const int hh = blockIdx.y;
    const int warp = threadIdx.x >> 5, lane = threadIdx.x & 31;
    const int n = blockIdx.x * 8 + warp;
    const float SCALE = 0.125f;
    const unsigned FULL = 0xffffffffu;

    const size_t qb = (size_t)n * DIDIM + hh * DH;
    const float q0 = rq[qb + lane];
    const float q1 = rq[qb + lane + 32];

    const int nfb = n >> 1;
    float t1v = -INFINITY, t2v = -INFINITY;
    int   t1f = INT_MAX,   t2f = INT_MAX;
    float vloc[8]; int cloc[8];
    const size_t cbase = ((size_t)hh * NTOK + n) * NCOARSE + 1;
#pragma unroll
    for (int i = 0; i < 8; i++) {
        int jp = i * 32 + lane;
        int cnt = nfb - jp * 8;
        cnt = cnt > 8 ? 8 : cnt;
        if (cnt > 0) {
            float val = csim[cbase + jp];
            vloc[i] = val; cloc[i] = cnt;
            top2_insert(val, jp * 8, t1v, t1f, t2v, t2f);
            if (cnt > 1) top2_insert(val, jp * 8 + 1, t1v, t1f, t2v, t2f);
        } else cloc[i] = 0;
    }
    for (int o = 16; o; o >>= 1) {
        float ov1 = __shfl_xor_sync(FULL, t1v, o); int of1 = __shfl_xor_sync(FULL, t1f, o);
        float ov2 = __shfl_xor_sync(FULL, t2v, o); int of2 = __shfl_xor_sync(FULL, t2f, o);
        top2_insert(ov1, of1, t1v, t1f, t2v, t2f);
        top2_insert(ov2, of2, t1v, t1f, t2v, t2f);
    }
    const float mx = fmaxf(t1v, -1000.f);
    float part = 0.f;
#pragma unroll
    for (int i = 0; i < 8; i++)
        if (cloc[i]) part += (float)cloc[i] * expf(vloc[i] - mx);
    for (int o = 16; o; o >>= 1) part += __shfl_xor_sync(FULL, part, o);
    const float Z = expf(-1000.f - mx) + part;

    int fb1, fb2; float sv1, sv2;
    if (t1f == INT_MAX) { fb1 = 0; fb2 = 1; sv1 = 0.f; sv2 = 0.f; }
    else {
        fb1 = t1f; sv1 = expf(t1v - mx) / Z;
        if (t2f == INT_MAX) { fb2 = (t1f == 0) ? 1 : 0; sv2 = 0.f; }
        else { fb2 = t2f; sv2 = expf(t2v - mx) / Z; }
    }

    int rows6[6]; float sims6[6];
    const int blks[3] = { fb1, fb2, n >> 1 };
    const float svs[2] = { sv1, sv2 };
#pragma unroll
    for (int e = 0; e < 6; e++) {
        int b = blks[e >> 1], s = e & 1;
        int row = b * 2 + s;
        rows6[e] = row;
        bool vld = (e < 4) ? (svs[e >> 1] > 1e-10f) : (s <= (n & 1));
        size_t kb = (size_t)row * DIDIM + hh * DH;
        float p = q0 * rk[kb + lane] + q1 * rk[kb + lane + 32];
        for (int o = 16; o; o >>= 1) p += __shfl_xor_sync(FULL, p, o);
        sims6[e] = vld ? p * SCALE : -FLT_MAX;
    }
    float fm = -FLT_MAX;
#pragma unroll
    for (int e = 0; e < 6; e++) fm = fmaxf(fm, sims6[e]);
    float fz = 0.f, fo0 = 0.f, fo1 = 0.f;
#pragma unroll
    for (int e = 0; e < 6; e++) {
        float pe = expf(sims6[e] - fm);
        fz += pe;
        size_t vb = (size_t)rows6[e] * DIDIM + hh * DH;
        fo0 += pe * v[vb + lane];
        fo1 += pe * v[vb + lane + 32];
    }
    fo0 /= fz; fo1 /= fz;

    float simsw[SWIN + 1];
#pragma unroll
    for (int w = 0; w <= SWIN; w++) {
        int row = n - SWIN + w;
        bool vld = (row >= 0);
        size_t kb = (size_t)(vld ? row : 0) * DIDIM + hh * DH;
        float k0 = vld ? rk[kb + lane] : 0.f;
        float k1 = vld ? rk[kb + lane + 32] : 0.f;
        float p = q0 * k0 + q1 * k1;
        for (int o = 16; o; o >>= 1) p += __shfl_xor_sync(FULL, p, o);
        simsw[w] = vld ? p * SCALE : -FLT_MAX;
    }
    float sm = -FLT_MAX;
#pragma unroll
    for (int w = 0; w <= SWIN; w++) sm = fmaxf(sm, simsw[w]);
    float sz = 0.f, so0 = 0.f, so1 = 0.f;
#pragma unroll
    for (int w = 0; w <= SWIN; w++) {
        float pe = expf(simsw[w] - sm);
        sz += pe;
        int row = n - SWIN + w;
        if (row >= 0) {
            size_t vb = (size_t)row * DIDIM + hh * DH;
            so0 += pe * v[vb + lane];
            so1 += pe * v[vb + lane + 32];
        }
    }
    so0 /= sz; so1 /= sz;

    const float g0 = gates[n * 24 + hh * 3 + 0];
    const float g1 = gates[n * 24 + hh * 3 + 1];
    const float g2 = gates[n * 24 + hh * 3 + 2];
    const size_t cb2 = ((size_t)hh * NTOK + n) * DH;
    const float c0 = comp[cb2 + lane], c1 = comp[cb2 + lane + 32];
    attn[qb + lane]      = g0 * c0 + g1 * fo0 + g2 * so0;
    attn[qb + lane + 32] = g0 * c1 + g1 * fo1 + g2 * so1;
}

// ---------------- host-side orchestration ----------------
static inline void launch_gemm_simt(const float* A, const float* B, float* C,
                                    int M, int Ncols, int K,
                                    const float* bias, int bias_mode,
                                    const float* resid, int act)
{
    dim3 grid((Ncols + 63) / 64, (M + 63) / 64);
    gemm_nt_kernel<<<grid, 256>>>(A, B, C, M, Ncols, K, bias, bias_mode, resid, act);
}

static inline void launch_gemm_tc(const float* A, const float* B, float* C,
                                  int M, int N, int K,
                                  const float* bias, int bias_mode,
                                  const float* resid, int act)
{
    if (N % 128 == 0) {
        constexpr int STAGE = 3 * 128 * 80 + 3 * 128 * 80;    // 61440
        size_t smem = 2 * STAGE;                              // 122880
        cudaFuncSetAttribute(gemm_bf16s_kernel<128>,
                             cudaFuncAttributeMaxDynamicSharedMemorySize, (int)smem);
        dim3 grid(N / 128, M / 128);
        gemm_bf16s_kernel<128><<<grid, 256, smem>>>(A, B, C, M, N, K, bias, bias_mode, resid, act);
    } else {
        constexpr int STAGE = 3 * 128 * 80 + 3 * 64 * 80;     // 46080
        size_t smem = 2 * STAGE;                              // 92160
        cudaFuncSetAttribute(gemm_bf16s_kernel<64>,
                             cudaFuncAttributeMaxDynamicSharedMemorySize, (int)smem);
        dim3 grid(N / 64, M / 128);
        gemm_bf16s_kernel<64><<<grid, 256, smem>>>(A, B, C, M, N, K, bias, bias_mode, resid, act);
    }
}

extern "C" void kernel_launch(void* const* d_in, const int* in_sizes, int n_in,
                              void* d_out, int out_size)
{
    (void)in_sizes; (void)n_in; (void)out_size;
    float* base = nullptr;
    cudaGetSymbolAddress((void**)&base, g_buf);

    const float* x       = (const float*)d_in[0];
    const float* w_in    = (const float*)d_in[1];
    const float* b_in    = (const float*)d_in[2];
    const float* g_norm  = (const float*)d_in[3];
    const float* wq      = (const float*)d_in[4];
    const float* wk      = (const float*)d_in[5];
    const float* wv      = (const float*)d_in[6];
    const float* k_pos   = (const float*)d_in[7];
    const float* v_pos   = (const float*)d_in[8];
    const float* mem_k   = (const float*)d_in[9];
    const float* mem_v   = (const float*)d_in[10];
    const float* kc_w1   = (const float*)d_in[11];
    const float* kc_b1   = (const float*)d_in[12];
    const float* kc_w2   = (const float*)d_in[13];
    const float* kc_b2   = (const float*)d_in[14];
    const float* vc_w1   = (const float*)d_in[15];
    const float* vc_b1   = (const float*)d_in[16];
    const float* vc_w2   = (const float*)d_in[17];
    const float* vc_b2   = (const float*)d_in[18];
    const float* w_strat = (const float*)d_in[19];
    const float* b_strat = (const float*)d_in[20];
    const float* w_comb  = (const float*)d_in[21];
    const float* w_out   = (const float*)d_in[22];
    const float* b_out   = (const float*)d_in[23];
    float* out = (float*)d_out;

    // 1. x (C,N) -> xt (N,C)
    {
        dim3 th(32, 8), gr(NTOK / 32, CDIM / 32);
        transpose_kernel<<<gr, th>>>(x, base + O_XT, CDIM, NTOK);
    }
    // 2. xs_t = xt @ w_in^T + b_in
    launch_gemm_tc(base + O_XT, w_in, base + O_XST, NTOK, CDIM, CDIM, b_in, 1, nullptr, 0);
    // 3. xs_t (N,C) -> xs (C,N)
    {
        dim3 th(32, 8), gr(CDIM / 32, NTOK / 32);
        transpose_kernel<<<gr, th>>>(base + O_XST, base + O_XS, NTOK, CDIM);
    }
    // 4. RMSNorm
    rmsnorm_kernel<<<NTOK, 256>>>(base + O_XST, g_norm, base + O_H);
    // 5. q, k, v projections
    launch_gemm_tc(base + O_H, wq, base + O_Q, NTOK, DIDIM, CDIM, nullptr, 0, nullptr, 0);
    launch_gemm_tc(base + O_H, wk, base + O_K, NTOK, DIDIM, CDIM, nullptr, 0, nullptr, 0);
    launch_gemm_tc(base + O_H, wv, base + O_V, NTOK, DIDIM, CDIM, nullptr, 0, nullptr, 0);
    // 6. RoPE
    rope_kernel<<<(NTOK * (DIDIM / 2) + 255) / 256, 256>>>(base + O_Q, base + O_K,
                                                           base + O_RQ, base + O_RK);
    // 7. kin/vin
    build_kin_kernel<<<(2048 * 1024) / 256, 256>>>(base + O_K, base + O_V, k_pos, v_pos,
                                                   base + O_KIN, base + O_VIN);
    // 8-11. compression MLPs
    launch_gemm_tc(base + O_KIN, kc_w1, base + O_HID, 2048, 1024, 1024, kc_b1, 1, nullptr, 1);
    launch_gemm_tc(base + O_HID, kc_w2, base + O_CKF, 2048, 64, 1024, kc_b2, 1, nullptr, 0);
    launch_gemm_tc(base + O_VIN, vc_w1, base + O_HID, 2048, 1024, 1024, vc_b1, 1, nullptr, 1);
    launch_gemm_tc(base + O_HID, vc_w2, base + O_CVF, 2048, 64, 1024, vc_b2, 1, nullptr, 0);
    // 12. concat mem slots
    build_ckcv_kernel<<<(NHEADS * NCOARSE * DH + 255) / 256, 256>>>(
        base + O_CKF, base + O_CVF, mem_k, mem_v, base + O_CK, base + O_CV);
    // 13. compressed attention
    {
        dim3 gr(NTOK / 8, NHEADS);
        csim_comp_kernel<<<gr, 256>>>(base + O_Q, base + O_CK, base + O_CV,
                                      base + O_CSIM, base + O_COMP);
    }
    // 14. gates
    launch_gemm_simt(base + O_H, w_strat, base + O_GATE, NTOK, 24, CDIM, b_strat, 1, nullptr, 2);
    // 15. top-k + fine + slide + combine
    {
        dim3 gr(NTOK / 8, NHEADS);
        fine_slide_kernel<<<gr, 256>>>(base + O_RQ, base + O_RK, base + O_V,
                                       base + O_CSIM, base + O_COMP, base + O_GATE,
                                       base + O_ATTN);
    }
    // 16. combine projection
    launch_gemm_tc(base + O_ATTN, w_comb, base + O_OUTC, NTOK, CDIM, DIDIM, nullptr, 0, nullptr, 0);
    // 17. output conv + bias + xs residual -> d_out
    launch_gemm_tc(w_out, base + O_OUTC, out, CDIM, NTOK, CDIM, b_out, 2, base + O_XS, 0);
}

// round 6
// speedup vs baseline: 1.7049x; 1.2711x over previous
#include <cuda_runtime.h>
#include <cuda_bf16.h>
#include <cfloat>
#include <climits>
#include <math.h>
#include <stdint.h>

// ---------------- problem constants ----------------
#define NTOK   4096
#define CDIM   512
#define DIDIM  512
#define NHEADS 8
#define DH     64
#define NCOARSE 257
#define CBLK   16
#define SWIN   8

static constexpr size_t SZ_NC = (size_t)NTOK * CDIM;

static constexpr size_t O_XT   = 0;
static constexpr size_t O_XST  = O_XT   + SZ_NC;
static constexpr size_t O_XS   = O_XST  + SZ_NC;
static constexpr size_t O_H    = O_XS   + SZ_NC;
static constexpr size_t O_Q    = O_H    + SZ_NC;
static constexpr size_t O_K    = O_Q    + SZ_NC;
static constexpr size_t O_V    = O_K    + SZ_NC;
static constexpr size_t O_RQ   = O_V    + SZ_NC;
static constexpr size_t O_RK   = O_RQ   + SZ_NC;
static constexpr size_t O_KIN  = O_RK   + SZ_NC;
static constexpr size_t O_VIN  = O_KIN  + SZ_NC;
static constexpr size_t O_HID  = O_VIN  + SZ_NC;
static constexpr size_t O_CKF  = O_HID  + SZ_NC;
static constexpr size_t O_CVF  = O_CKF  + (size_t)2048*64;
static constexpr size_t O_CK   = O_CVF  + (size_t)2048*64;
static constexpr size_t O_CV   = O_CK   + (size_t)NHEADS*NCOARSE*DH;
static constexpr size_t O_CSIM = O_CV   + (size_t)NHEADS*NCOARSE*DH;
static constexpr size_t O_COMP = O_CSIM + (size_t)NHEADS*NTOK*NCOARSE;
static constexpr size_t O_GATE = O_COMP + (size_t)NHEADS*NTOK*DH;
static constexpr size_t O_ATTN = O_GATE + (size_t)NTOK*24;
static constexpr size_t O_OUTC = O_ATTN + SZ_NC;
static constexpr size_t TOTAL  = O_OUTC + SZ_NC;

__device__ float g_buf[TOTAL];

// ============================================================================
// 3-limb bf16-split NT GEMM on mma.sync.m16n8k16.
// PASSES=6: hh+hm+mh+hl+lh+mm (fp32-class).  PASSES=4: hh+hm+mh+mm.
// C[m,n] = dot(A[m,:], B[n,:]); A (M,K) rm, B (N,K) rm; fp32 in/out.
// M%128==0, N%BN==0, K%32==0.
// ============================================================================

__device__ __forceinline__ uint32_t smem_u32(const void* p) {
    uint32_t a;
    asm("{ .reg .u64 t; cvta.to.shared.u64 t, %1; cvt.u32.u64 %0, t; }" : "=r"(a) : "l"(p));
    return a;
}

__device__ __forceinline__ void split3(float x, float y,
                                       uint32_t& hp, uint32_t& mp, uint32_t& lp)
{
    __nv_bfloat16 hx = __float2bfloat16(x), hy = __float2bfloat16(y);
    float rx = x - __bfloat162float(hx), ry = y - __bfloat162float(hy);
    __nv_bfloat16 mx = __float2bfloat16(rx), my = __float2bfloat16(ry);
    float sx = rx - __bfloat162float(mx), sy = ry - __bfloat162float(my);
    __nv_bfloat16 lx = __float2bfloat16(sx), ly = __float2bfloat16(sy);
    __nv_bfloat162 hv; hv.x = hx; hv.y = hy;
    __nv_bfloat162 mv; mv.x = mx; mv.y = my;
    __nv_bfloat162 lv; lv.x = lx; lv.y = ly;
    hp = *reinterpret_cast<uint32_t*>(&hv);
    mp = *reinterpret_cast<uint32_t*>(&mv);
    lp = *reinterpret_cast<uint32_t*>(&lv);
}

#define LDSM_X4(r0, r1, r2, r3, addr) \
    asm volatile("ldmatrix.sync.aligned.m8n8.x4.shared.b16 {%0,%1,%2,%3}, [%4];" \
                 : "=r"(r0), "=r"(r1), "=r"(r2), "=r"(r3) : "r"(addr))

__device__ __forceinline__ void mma_bf16(float4& d, const uint32_t* a, const uint32_t* b) {
    asm volatile(
        "mma.sync.aligned.m16n8k16.row.col.f32.bf16.bf16.f32 "
        "{%0,%1,%2,%3}, {%4,%5,%6,%7}, {%8,%9}, {%0,%1,%2,%3};"
        : "+f"(d.x), "+f"(d.y), "+f"(d.z), "+f"(d.w)
        : "r"(a[0]), "r"(a[1]), "r"(a[2]), "r"(a[3]), "r"(b[0]), "r"(b[1]));
}

template<int BN, int PASSES>
__global__ __launch_bounds__(256, 1) void gemm_bf16s_kernel(
    const float* __restrict__ A, const float* __restrict__ B, float* __restrict__ C,
    int M, int N, int K, const float* __restrict__ bias, int bias_mode,
    const float* __restrict__ resid, int act)
{
    constexpr int LDSB = 80;                 // row stride bytes (32 bf16 + 8 pad)
    constexpr int ASZ  = 128 * LDSB;         // 10240 B per limb
    constexpr int BSZ  = BN * LDSB;
    constexpr int STAGE = 3 * ASZ + 3 * BSZ;
    constexpr int NTW  = BN / 16;            // n8-tiles per warp (8 or 4)

    extern __shared__ char dsm[];
    const uint32_t sb = smem_u32(dsm);
    const int tid = threadIdx.x, warp = tid >> 5, lane = tid & 31;
    const int wm = warp >> 1, wn = warp & 1;
    const int bm0 = blockIdx.y * 128, bn0 = blockIdx.x * BN;

    float4 acc[2][NTW];
#pragma unroll
    for (int i = 0; i < 2; i++)
#pragma unroll
        for (int j = 0; j < NTW; j++) acc[i][j] = make_float4(0.f, 0.f, 0.f, 0.f);

    const int arow = tid >> 1, akh = (tid & 1) * 16;
    const float* aptr = A + (size_t)(bm0 + arow) * K + akh;
    const float* bptr = B + (size_t)(bn0 + arow) * K + akh;   // valid when arow < BN

    float4 areg[4], breg[4];

    auto ldg_tiles = [&](int k0) {
#pragma unroll
        for (int i = 0; i < 4; i++) areg[i] = *reinterpret_cast<const float4*>(aptr + k0 + i * 4);
        if (BN == 128 || arow < BN) {
#pragma unroll
            for (int i = 0; i < 4; i++) breg[i] = *reinterpret_cast<const float4*>(bptr + k0 + i * 4);
        }
    };

    auto sts_split = [&](char* hb, char* mb, char* lb, float4* rg) {
        uint32_t h[8], m[8], l[8];
#pragma unroll
        for (int i = 0; i < 4; i++) {
            const float* f = reinterpret_cast<const float*>(&rg[i]);
#pragma unroll
            for (int j = 0; j < 2; j++)
                split3(f[2 * j], f[2 * j + 1], h[2 * i + j], m[2 * i + j], l[2 * i + j]);
        }
        int off = arow * LDSB + akh * 2;
        *reinterpret_cast<uint4*>(hb + off)      = make_uint4(h[0], h[1], h[2], h[3]);
        *reinterpret_cast<uint4*>(hb + off + 16) = make_uint4(h[4], h[5], h[6], h[7]);
        *reinterpret_cast<uint4*>(mb + off)      = make_uint4(m[0], m[1], m[2], m[3]);
        *reinterpret_cast<uint4*>(mb + off + 16) = make_uint4(m[4], m[5], m[6], m[7]);
        if (PASSES == 6) {
            *reinterpret_cast<uint4*>(lb + off)      = make_uint4(l[0], l[1], l[2], l[3]);
            *reinterpret_cast<uint4*>(lb + off + 16) = make_uint4(l[4], l[5], l[6], l[7]);
        }
    };

    auto sts_tiles = [&](int st) {
        char* base = dsm + st * STAGE;
        sts_split(base, base + ASZ, base + 2 * ASZ, areg);
        if (BN == 128 || arow < BN)
            sts_split(base + 3 * ASZ, base + 3 * ASZ + BSZ, base + 3 * ASZ + 2 * BSZ, breg);
    };

    // ldmatrix address components (constant across slabs)
    const int a_r  = wm * 32 + (lane & 7) + ((lane >> 3) & 1) * 8;   // + mi*16
    const int a_kc = (lane >> 4) * 8;                                // + kk*16
    const int b_sel = lane >> 3;
    const int b_r   = wn * (BN / 2) + (b_sel >> 1) * 8 + (lane & 7); // + np*16
    const int b_kc  = (b_sel & 1) * 8;                               // + kk*16

    auto compute = [&](int st) {
        const uint32_t s0 = sb + st * STAGE;
#pragma unroll
        for (int kk = 0; kk < 2; kk++) {
            uint32_t afh[2][4], afm[2][4], afl[2][4];
#pragma unroll
            for (int mi = 0; mi < 2; mi++) {
                int off = (a_r + mi * 16) * LDSB + (a_kc + kk * 16) * 2;
                LDSM_X4(afh[mi][0], afh[mi][1], afh[mi][2], afh[mi][3], s0 + off);
                LDSM_X4(afm[mi][0], afm[mi][1], afm[mi][2], afm[mi][3], s0 + ASZ + off);
                if (PASSES == 6)
                    LDSM_X4(afl[mi][0], afl[mi][1], afl[mi][2], afl[mi][3], s0 + 2 * ASZ + off);
            }
#pragma unroll
            for (int np = 0; np < NTW / 2; np++) {
                int off = (b_r + np * 16) * LDSB + (b_kc + kk * 16) * 2;
                uint32_t bh[2][2], bm[2][2], bl[2][2];
                LDSM_X4(bh[0][0], bh[0][1], bh[1][0], bh[1][1], s0 + 3 * ASZ + off);
                LDSM_X4(bm[0][0], bm[0][1], bm[1][0], bm[1][1], s0 + 3 * ASZ + BSZ + off);
                if (PASSES == 6)
                    LDSM_X4(bl[0][0], bl[0][1], bl[1][0], bl[1][1], s0 + 3 * ASZ + 2 * BSZ + off);
#pragma unroll
                for (int mi = 0; mi < 2; mi++)
#pragma unroll
                    for (int q = 0; q < 2; q++) {
                        int ni = 2 * np + q;
                        mma_bf16(acc[mi][ni], afh[mi], bh[q]);
                        mma_bf16(acc[mi][ni], afh[mi], bm[q]);
                        mma_bf16(acc[mi][ni], afm[mi], bh[q]);
                        if (PASSES == 6) {
                            mma_bf16(acc[mi][ni], afh[mi], bl[q]);
                            mma_bf16(acc[mi][ni], afl[mi], bh[q]);
                        }
                        mma_bf16(acc[mi][ni], afm[mi], bm[q]);
                    }
            }
        }
    };

    ldg_tiles(0);
    sts_tiles(0);
    __syncthreads();

    const int slabs = K / 32;
    for (int s = 0; s < slabs; s++) {
        int st = s & 1;
        if (s + 1 < slabs) ldg_tiles((s + 1) * 32);
        compute(st);
        if (s + 1 < slabs) sts_tiles(st ^ 1);
        __syncthreads();
    }

    // epilogue
    const int g = lane >> 2, cc = lane & 3;
#pragma unroll
    for (int mi = 0; mi < 2; mi++) {
#pragma unroll
        for (int ni = 0; ni < NTW; ni++) {
            int mrow = bm0 + wm * 32 + mi * 16 + g;
            int ncol = bn0 + wn * (BN / 2) + ni * 8 + cc * 2;
            float2 r0 = make_float2(acc[mi][ni].x, acc[mi][ni].y);
            float2 r1 = make_float2(acc[mi][ni].z, acc[mi][ni].w);
            if (bias_mode == 1) {
                float b0 = bias[ncol], b1 = bias[ncol + 1];
                r0.x += b0; r0.y += b1; r1.x += b0; r1.y += b1;
            } else if (bias_mode == 2) {
                float bt = bias[mrow], bb = bias[mrow + 8];
                r0.x += bt; r0.y += bt; r1.x += bb; r1.y += bb;
            }
            if (act == 1) {
                r0.x = fmaxf(r0.x, 0.f); r0.y = fmaxf(r0.y, 0.f);
                r1.x = fmaxf(r1.x, 0.f); r1.y = fmaxf(r1.y, 0.f);
            }
            if (resid) {
                float2 q0 = *reinterpret_cast<const float2*>(resid + (size_t)mrow * N + ncol);
                float2 q1 = *reinterpret_cast<const float2*>(resid + (size_t)(mrow + 8) * N + ncol);
                r0.x += q0.x; r0.y += q0.y; r1.x += q1.x; r1.y += q1.y;
            }
            *reinterpret_cast<float2*>(C + (size_t)mrow * N + ncol) = r0;
            *reinterpret_cast<float2*>(C + (size_t)(mrow + 8) * N + ncol) = r1;
        }
    }
}

// ---------------- SIMT NT GEMM (gates only) ----------------
__global__ __launch_bounds__(256) void gemm_nt_kernel(
    const float* __restrict__ A, const float* __restrict__ B, float* __restrict__ C,
    int M, int Ncols, int K, const float* __restrict__ bias, int bias_mode,
    const float* __restrict__ resid, int act)
{
    __shared__ float As[16][64];
    __shared__ float Bs[16][64];
    const int tid = threadIdx.x;
    const int tx  = tid & 15;
    const int ty  = tid >> 4;
    const int bm0 = blockIdx.y * 64;
    const int bn0 = blockIdx.x * 64;
    const int lr  = tid >> 2;
    const int lk  = (tid & 3) << 2;

    float acc[4][4];
#pragma unroll
    for (int i = 0; i < 4; i++)
#pragma unroll
        for (int j = 0; j < 4; j++) acc[i][j] = 0.f;

    for (int k0 = 0; k0 < K; k0 += 16) {
        {
            int am = bm0 + lr;
            float4 av = make_float4(0.f, 0.f, 0.f, 0.f);
            if (am < M) av = *reinterpret_cast<const float4*>(A + (size_t)am * K + k0 + lk);
            As[lk + 0][lr] = av.x; As[lk + 1][lr] = av.y;
            As[lk + 2][lr] = av.z; As[lk + 3][lr] = av.w;
        }
        {
            int bn = bn0 + lr;
            float4 bv = make_float4(0.f, 0.f, 0.f, 0.f);
            if (bn < Ncols) bv = *reinterpret_cast<const float4*>(B + (size_t)bn * K + k0 + lk);
            Bs[lk + 0][lr] = bv.x; Bs[lk + 1][lr] = bv.y;
            Bs[lk + 2][lr] = bv.z; Bs[lk + 3][lr] = bv.w;
        }
        __syncthreads();
#pragma unroll
        for (int kk = 0; kk < 16; kk++) {
            float4 a = *reinterpret_cast<const float4*>(&As[kk][ty << 2]);
            float4 b = *reinterpret_cast<const float4*>(&Bs[kk][tx << 2]);
            acc[0][0] += a.x * b.x; acc[0][1] += a.x * b.y; acc[0][2] += a.x * b.z; acc[0][3] += a.x * b.w;
            acc[1][0] += a.y * b.x; acc[1][1] += a.y * b.y; acc[1][2] += a.y * b.z; acc[1][3] += a.y * b.w;
            acc[2][0] += a.z * b.x; acc[2][1] += a.z * b.y; acc[2][2] += a.z * b.z; acc[2][3] += a.z * b.w;
            acc[3][0] += a.w * b.x; acc[3][1] += a.w * b.y; acc[3][2] += a.w * b.z; acc[3][3] += a.w * b.w;
        }
        __syncthreads();
    }
#pragma unroll
    for (int i = 0; i < 4; i++) {
        int m = bm0 + (ty << 2) + i;
        if (m >= M) continue;
#pragma unroll
        for (int j = 0; j < 4; j++) {
            int nn = bn0 + (tx << 2) + j;
            if (nn >= Ncols) continue;
            float vv = acc[i][j];
            if (bias_mode == 1) vv += bias[nn];
            else if (bias_mode == 2) vv += bias[m];
            if (act == 1) vv = fmaxf(vv, 0.f);
            else if (act == 2) vv = 1.f / (1.f + expf(-vv));
            if (resid) vv += resid[(size_t)m * Ncols + nn];
            C[(size_t)m * Ncols + nn] = vv;
        }
    }
}

// ---------------- transpose ----------------
__global__ void transpose_kernel(const float* __restrict__ in, float* __restrict__ out,
                                 int R, int Ccols)
{
    __shared__ float tile[32][33];
    int r0 = blockIdx.y * 32, c0 = blockIdx.x * 32;
#pragma unroll
    for (int i = 0; i < 32; i += 8) {
        int r = r0 + threadIdx.y + i, c = c0 + threadIdx.x;
        if (r < R && c < Ccols) tile[threadIdx.y + i][threadIdx.x] = in[(size_t)r * Ccols + c];
    }
    __syncthreads();
#pragma unroll
    for (int i = 0; i < 32; i += 8) {
        int rr = c0 + threadIdx.y + i, cc = r0 + threadIdx.x;
        if (rr < Ccols && cc < R) out[(size_t)rr * R + cc] = tile[threadIdx.x][threadIdx.y + i];
    }
}

// ---------------- RMSNorm ----------------
__global__ void rmsnorm_kernel(const float* __restrict__ xs_t, const float* __restrict__ g,
                               float* __restrict__ h)
{
    int n = blockIdx.x, tid = threadIdx.x;
    const float* row = xs_t + (size_t)n * CDIM;
    float s = 0.f;
    for (int c = tid; c < CDIM; c += 256) { float v = row[c]; s += v * v; }
    __shared__ float red[256];
    red[tid] = s; __syncthreads();
    for (int o = 128; o; o >>= 1) { if (tid < o) red[tid] += red[tid + o]; __syncthreads(); }
    float inv = rsqrtf(red[0] / (float)CDIM + 1e-6f);
    for (int c = tid; c < CDIM; c += 256)
        h[(size_t)n * CDIM + c] = row[c] * inv * g[c];
}

// ---------------- RoPE (fp32 transcendentals, reference-faithful) ----------------
__global__ void rope_kernel(const float* __restrict__ q, const float* __restrict__ k,
                            float* __restrict__ rq, float* __restrict__ rk)
{
    int p = blockIdx.x * blockDim.x + threadIdx.x;
    if (p >= NTOK * (DIDIM / 2)) return;
    int n = p / (DIDIM / 2);
    int r = p % (DIDIM / 2);
    int i = r & 31;
    int base = n * DIDIM + (r >> 5) * DH + 2 * i;
    float inv = 1.f / powf(10000.f, (float)(2 * i) / 64.f);
    float ang = (float)n * inv;
    float s, c;
    sincosf(ang, &s, &c);
    float q0 = q[base], q1 = q[base + 1];
    rq[base]     = q0 * c - q1 * s;
    rq[base + 1] = q1 * c + q0 * s;
    float k0 = k[base], k1 = k[base + 1];
    rk[base]     = k0 * c - k1 * s;
    rk[base + 1] = k1 * c + k0 * s;
}

// ---------------- build compression MLP inputs ----------------
__global__ void build_kin_kernel(const float* __restrict__ k, const float* __restrict__ v,
                                 const float* __restrict__ k_pos, const float* __restrict__ v_pos,
                                 float* __restrict__ kin, float* __restrict__ vin)
{
    int idx = blockIdx.x * 256 + threadIdx.x;
    if (idx >= 2048 * 1024) return;
    int row = idx >> 10;
    int col = idx & 1023;
    int hh = row >> 8, cb = row & 255;
    int i = col >> 6, d = col & 63;
    int n = cb * CBLK + i;
    size_t ko = (size_t)n * DIDIM + hh * DH + d;
    size_t po = (size_t)(hh * CBLK + i) * DH + d;
    kin[idx] = k[ko] + k_pos[po];
    vin[idx] = v[ko] + v_pos[po];
}

// ---------------- concat mem slot + compressed k/v ----------------
__global__ void build_ckcv_kernel(const float* __restrict__ ckf, const float* __restrict__ cvf,
                                  const float* __restrict__ mem_k, const float* __restrict__ mem_v,
                                  float* __restrict__ ck, float* __restrict__ cv)
{
    int idx = blockIdx.x * 256 + threadIdx.x;
    if (idx >= NHEADS * NCOARSE * DH) return;
    int hh = idx / (NCOARSE * DH);
    int rem = idx - hh * (NCOARSE * DH);
    int j = rem / DH, d = rem % DH;
    if (j == 0) {
        ck[idx] = mem_k[hh * DH + d];
        cv[idx] = mem_v[hh * DH + d];
    } else {
        size_t src = (size_t)((hh << 8) + j - 1) * DH + d;
        ck[idx] = ckf[src];
        cv[idx] = cvf[src];
    }
}

// ---------------- compressed attention (chunked-smem AV) ----------------
__global__ __launch_bounds__(256) void csim_comp_kernel(
    const float* __restrict__ q, const float* __restrict__ ck, const float* __restrict__ cv,
    float* __restrict__ csim, float* __restrict__ comp)
{
    __shared__ float sq[8][64];
    __shared__ float sims[8][258];
    __shared__ float cvs[64][68];
    const int hh = blockIdx.y;
    const int n0 = blockIdx.x * 8;
    const int tid = threadIdx.x;
    const float SCALE = 0.125f;

    for (int t = tid; t < 8 * 64; t += 256) {
        int r = t >> 6, d = t & 63;
        sq[r][d] = q[(size_t)(n0 + r) * DIDIM + hh * DH + d];
    }
    __syncthreads();

    for (int j = tid; j < NCOARSE; j += 256) {
        const float* ckr = ck + ((size_t)(hh * NCOARSE + j) << 6);
        float acc[8] = {0.f, 0.f, 0.f, 0.f, 0.f, 0.f, 0.f, 0.f};
#pragma unroll 4
        for (int d = 0; d < 64; d++) {
            float kv = ckr[d];
#pragma unroll
            for (int r = 0; r < 8; r++) acc[r] += kv * sq[r][d];
        }
#pragma unroll
        for (int r = 0; r < 8; r++) {
            int n = n0 + r;
            float s = (j <= (n >> 4)) ? acc[r] * SCALE : -FLT_MAX;
            csim[((size_t)hh * NTOK + n) * NCOARSE + j] = s;
            sims[r][j] = s;
        }
    }
    __syncthreads();

    const int r = tid >> 5, lane = tid & 31;
    const int n = n0 + r;
    const int jmax = n >> 4;
    float m = -FLT_MAX;
    for (int j = lane; j <= jmax; j += 32) m = fmaxf(m, sims[r][j]);
    for (int o = 16; o; o >>= 1) m = fmaxf(m, __shfl_xor_sync(0xffffffffu, m, o));
    float z = 0.f;
    for (int j = lane; j <= jmax; j += 32) {
        float e = expf(sims[r][j] - m);
        sims[r][j] = e;
        z += e;
    }
    for (int o = 16; o; o >>= 1) z += __shfl_xor_sync(0xffffffffu, z, o);
    __syncwarp();
    const float invz = 1.f / z;

    // chunked AV: stage cv tiles in smem (coalesced, high-MLP), accumulate from LDS
    float acc0 = 0.f, acc1 = 0.f;
    const int jmax_blk = (n0 + 7) >> 4;        // uniform across block
    for (int j0 = 0; j0 <= jmax_blk; j0 += 64) {
        int jcnt = NCOARSE - j0; if (jcnt > 64) jcnt = 64;
        int need = jmax_blk + 1 - j0; if (jcnt > need) jcnt = need;
        __syncthreads();
        for (int e = tid; e < 64 * 16; e += 256) {
            int jl = e >> 4, seg = e & 15;
            if (jl < jcnt) {
                float4 vv = *reinterpret_cast<const float4*>(
                    cv + ((size_t)(hh * NCOARSE + j0 + jl) << 6) + seg * 4);
                *reinterpret_cast<float4*>(&cvs[jl][seg * 4]) = vv;
            }
        }
        __syncthreads();
        int jend = jmax - j0; if (jend > jcnt - 1) jend = jcnt - 1;
        for (int jl = 0; jl <= jend; jl++) {
            float w = sims[r][j0 + jl];
            acc0 += w * cvs[jl][lane];
            acc1 += w * cvs[jl][lane + 32];
        }
    }
    comp[((size_t)hh * NTOK + n) * DH + lane]      = acc0 * invz;
    comp[((size_t)hh * NTOK + n) * DH + lane + 32] = acc1 * invz;
}

// ---------------- top-2 helper ----------------
__device__ __forceinline__ void top2_insert(float v, int f,
                                            float& t1v, int& t1f, float& t2v, int& t2f)
{
    if (f == t1f || f == t2f) return;
    if (v > t1v || (v == t1v && f < t1f)) { t2v = t1v; t2f = t1f; t1v = v; t1f = f; }
    else if (v > t2v || (v == t2v && f < t2f)) { t2v = v; t2f = f; }
}

// ---------------- top-k + fine + slide + combine ----------------
__global__ __launch_bounds__(256) void fine_slide_kernel(
    const float* __restrict__ rq, const float* __restrict__ rk, const float* __restrict__ v,
    const float* __restrict__ csim, const float* __restrict__ comp,
    const float* __restrict__ gates, float* __restrict__ attn)
{
    const int hh = blockIdx.y;
    const int warp = threadIdx.x >> 5, lane = threadIdx.x & 31;
    const int n = blockIdx.x * 8 + warp;
    const float SCALE = 0.125f;
    const unsigned FULL = 0xffffffffu;

    const size_t qb = (size_t)n * DIDIM + hh * DH;
    const float q0 = rq[qb + lane];
    const float q1 = rq[qb + lane + 32];

    const int nfb = n >> 1;
    float t1v = -INFINITY, t2v = -INFINITY;
    int   t1f = INT_MAX,   t2f = INT_MAX;
    float vloc[8]; int cloc[8];
    const size_t cbase = ((size_t)hh * NTOK + n) * NCOARSE + 1;
#pragma unroll
    for (int i = 0; i < 8; i++) {
        int jp = i * 32 + lane;
        int cnt = nfb - jp * 8;
        cnt = cnt > 8 ? 8 : cnt;
        if (cnt > 0) {
            float val = csim[cbase + jp];
            vloc[i] = val; cloc[i] = cnt;
            top2_insert(val, jp * 8, t1v, t1f, t2v, t2f);
            if (cnt > 1) top2_insert(val, jp * 8 + 1, t1v, t1f, t2v, t2f);
        } else cloc[i] = 0;
    }
    for (int o = 16; o; o >>= 1) {
        float ov1 = __shfl_xor_sync(FULL, t1v, o); int of1 = __shfl_xor_sync(FULL, t1f, o);
        float ov2 = __shfl_xor_sync(FULL, t2v, o); int of2 = __shfl_xor_sync(FULL, t2f, o);
        top2_insert(ov1, of1, t1v, t1f, t2v, t2f);
        top2_insert(ov2, of2, t1v, t1f, t2v, t2f);
    }
    const float mx = fmaxf(t1v, -1000.f);
    float part = 0.f;
#pragma unroll
    for (int i = 0; i < 8; i++)
        if (cloc[i]) part += (float)cloc[i] * expf(vloc[i] - mx);
    for (int o = 16; o; o >>= 1) part += __shfl_xor_sync(FULL, part, o);
    const float Z = expf(-1000.f - mx) + part;

    int fb1, fb2; float sv1, sv2;
    if (t1f == INT_MAX) { fb1 = 0; fb2 = 1; sv1 = 0.f; sv2 = 0.f; }
    else {
        fb1 = t1f; sv1 = expf(t1v - mx) / Z;
        if (t2f == INT_MAX) { fb2 = (t1f == 0) ? 1 : 0; sv2 = 0.f; }
        else { fb2 = t2f; sv2 = expf(t2v - mx) / Z; }
    }

    int rows6[6]; float sims6[6];
    const int blks[3] = { fb1, fb2, n >> 1 };
    const float svs[2] = { sv1, sv2 };
#pragma unroll
    for (int e = 0; e < 6; e++) {
        int b = blks[e >> 1], s = e & 1;
        int row = b * 2 + s;
        rows6[e] = row;
        bool vld = (e < 4) ? (svs[e >> 1] > 1e-10f) : (s <= (n & 1));
        size_t kb = (size_t)row * DIDIM + hh * DH;
        float p = q0 * rk[kb + lane] + q1 * rk[kb + lane + 32];
        for (int o = 16; o; o >>= 1) p += __shfl_xor_sync(FULL, p, o);
        sims6[e] = vld ? p * SCALE : -FLT_MAX;
    }
    float fm = -FLT_MAX;
#pragma unroll
    for (int e = 0; e < 6; e++) fm = fmaxf(fm, sims6[e]);
    float fz = 0.f, fo0 = 0.f, fo1 = 0.f;
#pragma unroll
    for (int e = 0; e < 6; e++) {
        float pe = expf(sims6[e] - fm);
        fz += pe;
        size_t vb = (size_t)rows6[e] * DIDIM + hh * DH;
        fo0 += pe * v[vb + lane];
        fo1 += pe * v[vb + lane + 32];
    }
    fo0 /= fz; fo1 /= fz;

    float simsw[SWIN + 1];
#pragma unroll
    for (int w = 0; w <= SWIN; w++) {
        int row = n - SWIN + w;
        bool vld = (row >= 0);
        size_t kb = (size_t)(vld ? row : 0) * DIDIM + hh * DH;
        float k0 = vld ? rk[kb + lane] : 0.f;
        float k1 = vld ? rk[kb + lane + 32] : 0.f;
        float p = q0 * k0 + q1 * k1;
        for (int o = 16; o; o >>= 1) p += __shfl_xor_sync(FULL, p, o);
        simsw[w] = vld ? p * SCALE : -FLT_MAX;
    }
    float sm = -FLT_MAX;
#pragma unroll
    for (int w = 0; w <= SWIN; w++) sm = fmaxf(sm, simsw[w]);
    float sz = 0.f, so0 = 0.f, so1 = 0.f;
#pragma unroll
    for (int w = 0; w <= SWIN; w++) {
        float pe = expf(simsw[w] - sm);
        sz += pe;
        int row = n - SWIN + w;
        if (row >= 0) {
            size_t vb = (size_t)row * DIDIM + hh * DH;
            so0 += pe * v[vb + lane];
            so1 += pe * v[vb + lane + 32];
        }
    }
    so0 /= sz; so1 /= sz;

    const float g0 = gates[n * 24 + hh * 3 + 0];
    const float g1 = gates[n * 24 + hh * 3 + 1];
    const float g2 = gates[n * 24 + hh * 3 + 2];
    const size_t cb2 = ((size_t)hh * NTOK + n) * DH;
    const float c0 = comp[cb2 + lane], c1 = comp[cb2 + lane + 32];
    attn[qb + lane]      = g0 * c0 + g1 * fo0 + g2 * so0;
    attn[qb + lane + 32] = g0 * c1 + g1 * fo1 + g2 * so1;
}

// ---------------- host-side orchestration ----------------
static inline void launch_gemm_simt(const float* A, const float* B, float* C,
                                    int M, int Ncols, int K,
                                    const float* bias, int bias_mode,
                                    const float* resid, int act)
{
    dim3 grid((Ncols + 63) / 64, (M + 63) / 64);
    gemm_nt_kernel<<<grid, 256>>>(A, B, C, M, Ncols, K, bias, bias_mode, resid, act);
}

static inline void launch_gemm_tc(const float* A, const float* B, float* C,
                                  int M, int N, int K,
                                  const float* bias, int bias_mode,
                                  const float* resid, int act, int passes = 6)
{
    if (N % 128 == 0) {
        constexpr int STAGE = 3 * 128 * 80 + 3 * 128 * 80;    // 61440
        size_t smem = 2 * STAGE;                              // 122880
        dim3 grid(N / 128, M / 128);
        if (passes == 6) {
            cudaFuncSetAttribute(gemm_bf16s_kernel<128, 6>,
                                 cudaFuncAttributeMaxDynamicSharedMemorySize, (int)smem);
            gemm_bf16s_kernel<128, 6><<<grid, 256, smem>>>(A, B, C, M, N, K, bias, bias_mode, resid, act);
        } else {
            cudaFuncSetAttribute(gemm_bf16s_kernel<128, 4>,
                                 cudaFuncAttributeMaxDynamicSharedMemorySize, (int)smem);
            gemm_bf16s_kernel<128, 4><<<grid, 256, smem>>>(A, B, C, M, N, K, bias, bias_mode, resid, act);
        }
    } else {
        constexpr int STAGE = 3 * 128 * 80 + 3 * 64 * 80;     // 46080
        size_t smem = 2 * STAGE;                              // 92160
        cudaFuncSetAttribute(gemm_bf16s_kernel<64, 6>,
                             cudaFuncAttributeMaxDynamicSharedMemorySize, (int)smem);
        dim3 grid(N / 64, M / 128);
        gemm_bf16s_kernel<64, 6><<<grid, 256, smem>>>(A, B, C, M, N, K, bias, bias_mode, resid, act);
    }
}

extern "C" void kernel_launch(void* const* d_in, const int* in_sizes, int n_in,
                              void* d_out, int out_size)
{
    (void)in_sizes; (void)n_in; (void)out_size;
    float* base = nullptr;
    cudaGetSymbolAddress((void**)&base, g_buf);

    const float* x       = (const float*)d_in[0];
    const float* w_in    = (const float*)d_in[1];
    const float* b_in    = (const float*)d_in[2];
    const float* g_norm  = (const float*)d_in[3];
    const float* wq      = (const float*)d_in[4];
    const float* wk      = (const float*)d_in[5];
    const float* wv      = (const float*)d_in[6];
    const float* k_pos   = (const float*)d_in[7];
    const float* v_pos   = (const float*)d_in[8];
    const float* mem_k   = (const float*)d_in[9];
    const float* mem_v   = (const float*)d_in[10];
    const float* kc_w1   = (const float*)d_in[11];
    const float* kc_b1   = (const float*)d_in[12];
    const float* kc_w2   = (const float*)d_in[13];
    const float* kc_b2   = (const float*)d_in[14];
    const float* vc_w1   = (const float*)d_in[15];
    const float* vc_b1   = (const float*)d_in[16];
    const float* vc_w2   = (const float*)d_in[17];
    const float* vc_b2   = (const float*)d_in[18];
    const float* w_strat = (const float*)d_in[19];
    const float* b_strat = (const float*)d_in[20];
    const float* w_comb  = (const float*)d_in[21];
    const float* w_out   = (const float*)d_in[22];
    const float* b_out   = (const float*)d_in[23];
    float* out = (float*)d_out;

    // 1. x (C,N) -> xt (N,C)
    {
        dim3 th(32, 8), gr(NTOK / 32, CDIM / 32);
        transpose_kernel<<<gr, th>>>(x, base + O_XT, CDIM, NTOK);
    }
    // 2. xs_t = xt @ w_in^T + b_in
    launch_gemm_tc(base + O_XT, w_in, base + O_XST, NTOK, CDIM, CDIM, b_in, 1, nullptr, 0);
    // 3. RMSNorm
    rmsnorm_kernel<<<NTOK, 256>>>(base + O_XST, g_norm, base + O_H);
    // 4-6. q, k, v projections (wq lands in the ncu sampling slot)
    launch_gemm_tc(base + O_H, wq, base + O_Q, NTOK, DIDIM, CDIM, nullptr, 0, nullptr, 0);
    launch_gemm_tc(base + O_H, wk, base + O_K, NTOK, DIDIM, CDIM, nullptr, 0, nullptr, 0);
    launch_gemm_tc(base + O_H, wv, base + O_V, NTOK, DIDIM, CDIM, nullptr, 0, nullptr, 0);
    // 7. RoPE
    rope_kernel<<<(NTOK * (DIDIM / 2) + 255) / 256, 256>>>(base + O_Q, base + O_K,
                                                           base + O_RQ, base + O_RK);
    // 8. kin/vin
    build_kin_kernel<<<(2048 * 1024) / 256, 256>>>(base + O_K, base + O_V, k_pos, v_pos,
                                                   base + O_KIN, base + O_VIN);
    // 9-12. compression MLPs
    launch_gemm_tc(base + O_KIN, kc_w1, base + O_HID, 2048, 1024, 1024, kc_b1, 1, nullptr, 1);
    launch_gemm_tc(base + O_HID, kc_w2, base + O_CKF, 2048, 64, 1024, kc_b2, 1, nullptr, 0);
    launch_gemm_tc(base + O_VIN, vc_w1, base + O_HID, 2048, 1024, 1024, vc_b1, 1, nullptr, 1);
    launch_gemm_tc(base + O_HID, vc_w2, base + O_CVF, 2048, 64, 1024, vc_b2, 1, nullptr, 0);
    // 13. concat mem slots
    build_ckcv_kernel<<<(NHEADS * NCOARSE * DH + 255) / 256, 256>>>(
        base + O_CKF, base + O_CVF, mem_k, mem_v, base + O_CK, base + O_CV);
    // 14. compressed attention
    {
        dim3 gr(NTOK / 8, NHEADS);
        csim_comp_kernel<<<gr, 256>>>(base + O_Q, base + O_CK, base + O_CV,
                                      base + O_CSIM, base + O_COMP);
    }
    // 15. gates
    launch_gemm_simt(base + O_H, w_strat, base + O_GATE, NTOK, 24, CDIM, b_strat, 1, nullptr, 2);
    // 16. top-k + fine + slide + combine
    {
        dim3 gr(NTOK / 8, NHEADS);
        fine_slide_kernel<<<gr, 256>>>(base + O_RQ, base + O_RK, base + O_V,
                                       base + O_CSIM, base + O_COMP, base + O_GATE,
                                       base + O_ATTN);
    }
    // 17. xs_t (N,C) -> xs (C,N)  (residual for final GEMM; moved late)
    {
        dim3 th(32, 8), gr(CDIM / 32, NTOK / 32);
        transpose_kernel<<<gr, th>>>(base + O_XST, base + O_XS, NTOK, CDIM);
    }
    // 18. combine projection (output-side: 4-pass)
    launch_gemm_tc(base + O_ATTN, w_comb, base + O_OUTC, NTOK, CDIM, DIDIM, nullptr, 0, nullptr, 0, 4);
    // 19. output conv + bias + xs residual -> d_out (output-side: 4-pass)
    launch_gemm_tc(w_out, base + O_OUTC, out, CDIM, NTOK, CDIM, b_out, 2, base + O_XS, 0, 4);
}

// round 10
// speedup vs baseline: 1.8331x; 1.0752x over previous
#include <cuda_runtime.h>
#include <cuda_bf16.h>
#include <cfloat>
#include <climits>
#include <math.h>
#include <stdint.h>

// ---------------- problem constants ----------------
#define NTOK   4096
#define CDIM   512
#define DIDIM  512
#define NHEADS 8
#define DH     64
#define NCOARSE 257
#define CBLK   16
#define SWIN   8

static constexpr size_t SZ_NC = (size_t)NTOK * CDIM;

static constexpr size_t O_XT   = 0;
static constexpr size_t O_XST  = O_XT   + SZ_NC;
static constexpr size_t O_XS   = O_XST  + SZ_NC;
static constexpr size_t O_H    = O_XS   + SZ_NC;
static constexpr size_t O_Q    = O_H    + SZ_NC;
static constexpr size_t O_K    = O_Q    + SZ_NC;
static constexpr size_t O_V    = O_K    + SZ_NC;
static constexpr size_t O_RQ   = O_V    + SZ_NC;
static constexpr size_t O_RK   = O_RQ   + SZ_NC;
static constexpr size_t O_KIN  = O_RK   + SZ_NC;
static constexpr size_t O_VIN  = O_KIN  + SZ_NC;
static constexpr size_t O_HID  = O_VIN  + SZ_NC;      // (2048,1024) k-branch
static constexpr size_t O_HID2 = O_HID  + SZ_NC;      // (2048,1024) v-branch
static constexpr size_t O_CKF  = O_HID2 + SZ_NC;
static constexpr size_t O_CVF  = O_CKF  + (size_t)2048*64;
static constexpr size_t O_CK   = O_CVF  + (size_t)2048*64;
static constexpr size_t O_CV   = O_CK   + (size_t)NHEADS*NCOARSE*DH;
static constexpr size_t O_CSIM = O_CV   + (size_t)NHEADS*NCOARSE*DH;
static constexpr size_t O_COMP = O_CSIM + (size_t)NHEADS*NTOK*NCOARSE;
static constexpr size_t O_GATE = O_COMP + (size_t)NHEADS*NTOK*DH;
static constexpr size_t O_ATTN = O_GATE + (size_t)NTOK*24;
static constexpr size_t O_OUTC = O_ATTN + SZ_NC;
static constexpr size_t TOTAL  = O_OUTC + SZ_NC;

__device__ float g_buf[TOTAL];

// ============================================================================
// 3-limb bf16-split NT GEMM, 64xBN CTA tile, 128 threads, 2 CTAs/SM.
// PASSES=6: hh+hm+mh+hl+lh+mm (fp32-class).  PASSES=4: hh+hm+mh+mm.
// C[m,n] = dot(A[m,:], B[n,:]); A (M,K) rm, B (N,K) rm; fp32 in/out.
// M%64==0, N%BN==0, K%32==0.  blockIdx.z selects batch member.
// ============================================================================

struct GemmBatch {
    const float* A[3];
    const float* B[3];
    float*       C[3];
    const float* bias[3];
    const float* resid[3];
};

__device__ __forceinline__ uint32_t smem_u32(const void* p) {
    uint32_t a;
    asm("{ .reg .u64 t; cvta.to.shared.u64 t, %1; cvt.u32.u64 %0, t; }" : "=r"(a) : "l"(p));
    return a;
}

__device__ __forceinline__ void split3(float x, float y,
                                       uint32_t& hp, uint32_t& mp, uint32_t& lp)
{
    __nv_bfloat16 hx = __float2bfloat16(x), hy = __float2bfloat16(y);
    float rx = x - __bfloat162float(hx), ry = y - __bfloat162float(hy);
    __nv_bfloat16 mx = __float2bfloat16(rx), my = __float2bfloat16(ry);
    float sx = rx - __bfloat162float(mx), sy = ry - __bfloat162float(my);
    __nv_bfloat16 lx = __float2bfloat16(sx), ly = __float2bfloat16(sy);
    __nv_bfloat162 hv; hv.x = hx; hv.y = hy;
    __nv_bfloat162 mv; mv.x = mx; mv.y = my;
    __nv_bfloat162 lv; lv.x = lx; lv.y = ly;
    hp = *reinterpret_cast<uint32_t*>(&hv);
    mp = *reinterpret_cast<uint32_t*>(&mv);
    lp = *reinterpret_cast<uint32_t*>(&lv);
}

#define LDSM_X4(r0, r1, r2, r3, addr) \
    asm volatile("ldmatrix.sync.aligned.m8n8.x4.shared.b16 {%0,%1,%2,%3}, [%4];" \
                 : "=r"(r0), "=r"(r1), "=r"(r2), "=r"(r3) : "r"(addr))

__device__ __forceinline__ void mma_bf16(float4& d, const uint32_t* a, const uint32_t* b) {
    asm volatile(
        "mma.sync.aligned.m16n8k16.row.col.f32.bf16.bf16.f32 "
        "{%0,%1,%2,%3}, {%4,%5,%6,%7}, {%8,%9}, {%0,%1,%2,%3};"
        : "+f"(d.x), "+f"(d.y), "+f"(d.z), "+f"(d.w)
        : "r"(a[0]), "r"(a[1]), "r"(a[2]), "r"(a[3]), "r"(b[0]), "r"(b[1]));
}

template<int BN, int PASSES>
__global__ __launch_bounds__(128, 2) void gemm2_kernel(
    GemmBatch bt, int M, int N, int K, int bias_mode, int act)
{
    constexpr int LDSB = 80;            // row stride bytes (32 bf16 + 8 pad)
    constexpr int ASZ  = 64 * LDSB;     // 5120 B per limb
    constexpr int BSZ  = BN * LDSB;
    constexpr int NTW  = BN / 16;       // n8-tiles per warp (8 or 4)
    constexpr int BREG = BN / 16;       // float4 staged per thread for B (8 or 4)

    const float* __restrict__ A     = bt.A[blockIdx.z];
    const float* __restrict__ B     = bt.B[blockIdx.z];
    float*       __restrict__ C     = bt.C[blockIdx.z];
    const float* __restrict__ bias  = bt.bias[blockIdx.z];
    const float* __restrict__ resid = bt.resid[blockIdx.z];

    extern __shared__ char dsm[];
    const uint32_t sb = smem_u32(dsm);
    const int tid = threadIdx.x, warp = tid >> 5, lane = tid & 31;
    const int wm = warp >> 1, wn = warp & 1;
    const int bm0 = blockIdx.y * 64, bn0 = blockIdx.x * BN;

    float4 acc[2][NTW];
#pragma unroll
    for (int i = 0; i < 2; i++)
#pragma unroll
        for (int j = 0; j < NTW; j++) acc[i][j] = make_float4(0.f, 0.f, 0.f, 0.f);

    const int arow = tid >> 1, akh = (tid & 1) * 16;  // arow 0..63
    const float* aptr = A + (size_t)(bm0 + arow) * K + akh;
    const float* bptr = B + (size_t)(bn0 + arow) * K + akh;

    float4 areg[4], breg[BREG];

    auto ldg_tiles = [&](int k0) {
#pragma unroll
        for (int i = 0; i < 4; i++)
            areg[i] = *reinterpret_cast<const float4*>(aptr + k0 + i * 4);
#pragma unroll
        for (int i = 0; i < 4; i++)
            breg[i] = *reinterpret_cast<const float4*>(bptr + k0 + i * 4);
        if (BN == 128) {
#pragma unroll
            for (int i = 0; i < 4; i++)
                breg[4 + i] = *reinterpret_cast<const float4*>(bptr + (size_t)64 * K + k0 + i * 4);
        }
    };

    // write 16 floats (4 float4) of one row into 3 limb planes
    auto sts16 = [&](char* hb, char* mb, char* lb, int off, float4* rg) {
        uint32_t h[8], m[8], l[8];
#pragma unroll
        for (int i = 0; i < 4; i++) {
            const float* f = reinterpret_cast<const float*>(&rg[i]);
#pragma unroll
            for (int j = 0; j < 2; j++)
                split3(f[2 * j], f[2 * j + 1], h[2 * i + j], m[2 * i + j], l[2 * i + j]);
        }
        *reinterpret_cast<uint4*>(hb + off)      = make_uint4(h[0], h[1], h[2], h[3]);
        *reinterpret_cast<uint4*>(hb + off + 16) = make_uint4(h[4], h[5], h[6], h[7]);
        *reinterpret_cast<uint4*>(mb + off)      = make_uint4(m[0], m[1], m[2], m[3]);
        *reinterpret_cast<uint4*>(mb + off + 16) = make_uint4(m[4], m[5], m[6], m[7]);
        if (PASSES == 6) {
            *reinterpret_cast<uint4*>(lb + off)      = make_uint4(l[0], l[1], l[2], l[3]);
            *reinterpret_cast<uint4*>(lb + off + 16) = make_uint4(l[4], l[5], l[6], l[7]);
        }
    };

    auto sts_tiles = [&]() {
        int off = arow * LDSB + akh * 2;
        sts16(dsm, dsm + ASZ, dsm + 2 * ASZ, off, areg);
        char* bb = dsm + 3 * ASZ;
        sts16(bb, bb + BSZ, bb + 2 * BSZ, off, breg);
        if (BN == 128)
            sts16(bb, bb + BSZ, bb + 2 * BSZ, off + 64 * LDSB, breg + 4);
    };

    // ldmatrix address components
    const int a_r  = wm * 32 + (lane & 7) + ((lane >> 3) & 1) * 8;   // + mi*16
    const int a_kc = (lane >> 4) * 8;                                // + kk*16
    const int b_sel = lane >> 3;
    const int b_r   = wn * (BN / 2) + (b_sel >> 1) * 8 + (lane & 7); // + np*16
    const int b_kc  = (b_sel & 1) * 8;                               // + kk*16

    auto compute = [&]() {
        const uint32_t s0 = sb;
#pragma unroll
        for (int kk = 0; kk < 2; kk++) {
            uint32_t afh[2][4], afm[2][4], afl[2][4];
#pragma unroll
            for (int mi = 0; mi < 2; mi++) {
                int off = (a_r + mi * 16) * LDSB + (a_kc + kk * 16) * 2;
                LDSM_X4(afh[mi][0], afh[mi][1], afh[mi][2], afh[mi][3], s0 + off);
                LDSM_X4(afm[mi][0], afm[mi][1], afm[mi][2], afm[mi][3], s0 + ASZ + off);
                if (PASSES == 6)
                    LDSM_X4(afl[mi][0], afl[mi][1], afl[mi][2], afl[mi][3], s0 + 2 * ASZ + off);
            }
#pragma unroll
            for (int np = 0; np < NTW / 2; np++) {
                int off = (b_r + np * 16) * LDSB + (b_kc + kk * 16) * 2;
                uint32_t bh[2][2], bm[2][2], bl[2][2];
                LDSM_X4(bh[0][0], bh[0][1], bh[1][0], bh[1][1], s0 + 3 * ASZ + off);
                LDSM_X4(bm[0][0], bm[0][1], bm[1][0], bm[1][1], s0 + 3 * ASZ + BSZ + off);
                if (PASSES == 6)
                    LDSM_X4(bl[0][0], bl[0][1], bl[1][0], bl[1][1], s0 + 3 * ASZ + 2 * BSZ + off);
#pragma unroll
                for (int mi = 0; mi < 2; mi++)
#pragma unroll
                    for (int q = 0; q < 2; q++) {
                        int ni = 2 * np + q;
                        mma_bf16(acc[mi][ni], afh[mi], bh[q]);
                        mma_bf16(acc[mi][ni], afh[mi], bm[q]);
                        mma_bf16(acc[mi][ni], afm[mi], bh[q]);
                        if (PASSES == 6) {
                            mma_bf16(acc[mi][ni], afh[mi], bl[q]);
                            mma_bf16(acc[mi][ni], afl[mi], bh[q]);
                        }
                        mma_bf16(acc[mi][ni], afm[mi], bm[q]);
                    }
            }
        }
    };

    ldg_tiles(0);
    const int slabs = K / 32;
    for (int s = 0; s < slabs; s++) {
        if (s > 0) __syncthreads();       // previous compute done before overwrite
        sts_tiles();
        __syncthreads();
        if (s + 1 < slabs) ldg_tiles((s + 1) * 32);
        compute();
    }

    // epilogue
    const int g = lane >> 2, cc = lane & 3;
#pragma unroll
    for (int mi = 0; mi < 2; mi++) {
#pragma unroll
        for (int ni = 0; ni < NTW; ni++) {
            int mrow = bm0 + wm * 32 + mi * 16 + g;
            int ncol = bn0 + wn * (BN / 2) + ni * 8 + cc * 2;
            float2 r0 = make_float2(acc[mi][ni].x, acc[mi][ni].y);
            float2 r1 = make_float2(acc[mi][ni].z, acc[mi][ni].w);
            if (bias_mode == 1) {
                float b0 = bias[ncol], b1 = bias[ncol + 1];
                r0.x += b0; r0.y += b1; r1.x += b0; r1.y += b1;
            } else if (bias_mode == 2) {
                float bt_ = bias[mrow], bb_ = bias[mrow + 8];
                r0.x += bt_; r0.y += bt_; r1.x += bb_; r1.y += bb_;
            }
            if (act == 1) {
                r0.x = fmaxf(r0.x, 0.f); r0.y = fmaxf(r0.y, 0.f);
                r1.x = fmaxf(r1.x, 0.f); r1.y = fmaxf(r1.y, 0.f);
            }
            if (resid) {
                float2 q0 = *reinterpret_cast<const float2*>(resid + (size_t)mrow * N + ncol);
                float2 q1 = *reinterpret_cast<const float2*>(resid + (size_t)(mrow + 8) * N + ncol);
                r0.x += q0.x; r0.y += q0.y; r1.x += q1.x; r1.y += q1.y;
            }
            *reinterpret_cast<float2*>(C + (size_t)mrow * N + ncol) = r0;
            *reinterpret_cast<float2*>(C + (size_t)(mrow + 8) * N + ncol) = r1;
        }
    }
}

// ---------------- SIMT NT GEMM (gates only) ----------------
__global__ __launch_bounds__(256) void gemm_nt_kernel(
    const float* __restrict__ A, const float* __restrict__ B, float* __restrict__ C,
    int M, int Ncols, int K, const float* __restrict__ bias, int bias_mode,
    const float* __restrict__ resid, int act)
{
    __shared__ float As[16][64];
    __shared__ float Bs[16][64];
    const int tid = threadIdx.x;
    const int tx  = tid & 15;
    const int ty  = tid >> 4;
    const int bm0 = blockIdx.y * 64;
    const int bn0 = blockIdx.x * 64;
    const int lr  = tid >> 2;
    const int lk  = (tid & 3) << 2;

    float acc[4][4];
#pragma unroll
    for (int i = 0; i < 4; i++)
#pragma unroll
        for (int j = 0; j < 4; j++) acc[i][j] = 0.f;

    for (int k0 = 0; k0 < K; k0 += 16) {
        {
            int am = bm0 + lr;
            float4 av = make_float4(0.f, 0.f, 0.f, 0.f);
            if (am < M) av = *reinterpret_cast<const float4*>(A + (size_t)am * K + k0 + lk);
            As[lk + 0][lr] = av.x; As[lk + 1][lr] = av.y;
            As[lk + 2][lr] = av.z; As[lk + 3][lr] = av.w;
        }
        {
            int bn = bn0 + lr;
            float4 bv = make_float4(0.f, 0.f, 0.f, 0.f);
            if (bn < Ncols) bv = *reinterpret_cast<const float4*>(B + (size_t)bn * K + k0 + lk);
            Bs[lk + 0][lr] = bv.x; Bs[lk + 1][lr] = bv.y;
            Bs[lk + 2][lr] = bv.z; Bs[lk + 3][lr] = bv.w;
        }
        __syncthreads();
#pragma unroll
        for (int kk = 0; kk < 16; kk++) {
            float4 a = *reinterpret_cast<const float4*>(&As[kk][ty << 2]);
            float4 b = *reinterpret_cast<const float4*>(&Bs[kk][tx << 2]);
            acc[0][0] += a.x * b.x; acc[0][1] += a.x * b.y; acc[0][2] += a.x * b.z; acc[0][3] += a.x * b.w;
            acc[1][0] += a.y * b.x; acc[1][1] += a.y * b.y; acc[1][2] += a.y * b.z; acc[1][3] += a.y * b.w;
            acc[2][0] += a.z * b.x; acc[2][1] += a.z * b.y; acc[2][2] += a.z * b.z; acc[2][3] += a.z * b.w;
            acc[3][0] += a.w * b.x; acc[3][1] += a.w * b.y; acc[3][2] += a.w * b.z; acc[3][3] += a.w * b.w;
        }
        __syncthreads();
    }
#pragma unroll
    for (int i = 0; i < 4; i++) {
        int m = bm0 + (ty << 2) + i;
        if (m >= M) continue;
#pragma unroll
        for (int j = 0; j < 4; j++) {
            int nn = bn0 + (tx << 2) + j;
            if (nn >= Ncols) continue;
            float vv = acc[i][j];
            if (bias_mode == 1) vv += bias[nn];
            else if (bias_mode == 2) vv += bias[m];
            if (act == 1) vv = fmaxf(vv, 0.f);
            else if (act == 2) vv = 1.f / (1.f + expf(-vv));
            if (resid) vv += resid[(size_t)m * Ncols + nn];
            C[(size_t)m * Ncols + nn] = vv;
        }
    }
}

// ---------------- transpose ----------------
__global__ void transpose_kernel(const float* __restrict__ in, float* __restrict__ out,
                                 int R, int Ccols)
{
    __shared__ float tile[32][33];
    int r0 = blockIdx.y * 32, c0 = blockIdx.x * 32;
#pragma unroll
    for (int i = 0; i < 32; i += 8) {
        int r = r0 + threadIdx.y + i, c = c0 + threadIdx.x;
        if (r < R && c < Ccols) tile[threadIdx.y + i][threadIdx.x] = in[(size_t)r * Ccols + c];
    }
    __syncthreads();
#pragma unroll
    for (int i = 0; i < 32; i += 8) {
        int rr = c0 + threadIdx.y + i, cc = r0 + threadIdx.x;
        if (rr < Ccols && cc < R) out[(size_t)rr * R + cc] = tile[threadIdx.x][threadIdx.y + i];
    }
}

// ---------------- RMSNorm ----------------
__global__ void rmsnorm_kernel(const float* __restrict__ xs_t, const float* __restrict__ g,
                               float* __restrict__ h)
{
    int n = blockIdx.x, tid = threadIdx.x;
    const float* row = xs_t + (size_t)n * CDIM;
    float s = 0.f;
    for (int c = tid; c < CDIM; c += 256) { float v = row[c]; s += v * v; }
    __shared__ float red[256];
    red[tid] = s; __syncthreads();
    for (int o = 128; o; o >>= 1) { if (tid < o) red[tid] += red[tid + o]; __syncthreads(); }
    float inv = rsqrtf(red[0] / (float)CDIM + 1e-6f);
    for (int c = tid; c < CDIM; c += 256)
        h[(size_t)n * CDIM + c] = row[c] * inv * g[c];
}

// ---------------- RoPE ----------------
__global__ void rope_kernel(const float* __restrict__ q, const float* __restrict__ k,
                            float* __restrict__ rq, float* __restrict__ rk)
{
    int p = blockIdx.x * blockDim.x + threadIdx.x;
    if (p >= NTOK * (DIDIM / 2)) return;
    int n = p / (DIDIM / 2);
    int r = p % (DIDIM / 2);
    int i = r & 31;
    int base = n * DIDIM + (r >> 5) * DH + 2 * i;
    float inv = 1.f / powf(10000.f, (float)(2 * i) / 64.f);
    float ang = (float)n * inv;
    float s, c;
    sincosf(ang, &s, &c);
    float q0 = q[base], q1 = q[base + 1];
    rq[base]     = q0 * c - q1 * s;
    rq[base + 1] = q1 * c + q0 * s;
    float k0 = k[base], k1 = k[base + 1];
    rk[base]     = k0 * c - k1 * s;
    rk[base + 1] = k1 * c + k0 * s;
}

// ---------------- build compression MLP inputs ----------------
__global__ void build_kin_kernel(const float* __restrict__ k, const float* __restrict__ v,
                                 const float* __restrict__ k_pos, const float* __restrict__ v_pos,
                                 float* __restrict__ kin, float* __restrict__ vin)
{
    int idx = blockIdx.x * 256 + threadIdx.x;
    if (idx >= 2048 * 1024) return;
    int row = idx >> 10;
    int col = idx & 1023;
    int hh = row >> 8, cb = row & 255;
    int i = col >> 6, d = col & 63;
    int n = cb * CBLK + i;
    size_t ko = (size_t)n * DIDIM + hh * DH + d;
    size_t po = (size_t)(hh * CBLK + i) * DH + d;
    kin[idx] = k[ko] + k_pos[po];
    vin[idx] = v[ko] + v_pos[po];
}

// ---------------- concat mem slot + compressed k/v ----------------
__global__ void build_ckcv_kernel(const float* __restrict__ ckf, const float* __restrict__ cvf,
                                  const float* __restrict__ mem_k, const float* __restrict__ mem_v,
                                  float* __restrict__ ck, float* __restrict__ cv)
{
    int idx = blockIdx.x * 256 + threadIdx.x;
    if (idx >= NHEADS * NCOARSE * DH) return;
    int hh = idx / (NCOARSE * DH);
    int rem = idx - hh * (NCOARSE * DH);
    int j = rem / DH, d = rem % DH;
    if (j == 0) {
        ck[idx] = mem_k[hh * DH + d];
        cv[idx] = mem_v[hh * DH + d];
    } else {
        size_t src = (size_t)((hh << 8) + j - 1) * DH + d;
        ck[idx] = ckf[src];
        cv[idx] = cvf[src];
    }
}

// ---------------- compressed attention (chunked-smem AV) ----------------
__global__ __launch_bounds__(256) void csim_comp_kernel(
    const float* __restrict__ q, const float* __restrict__ ck, const float* __restrict__ cv,
    float* __restrict__ csim, float* __restrict__ comp)
{
    __shared__ float sq[8][64];
    __shared__ float sims[8][258];
    __shared__ float cvs[64][68];
    const int hh = blockIdx.y;
    const int n0 = blockIdx.x * 8;
    const int tid = threadIdx.x;
    const float SCALE = 0.125f;

    for (int t = tid; t < 8 * 64; t += 256) {
        int r = t >> 6, d = t & 63;
        sq[r][d] = q[(size_t)(n0 + r) * DIDIM + hh * DH + d];
    }
    __syncthreads();

    for (int j = tid; j < NCOARSE; j += 256) {
        const float* ckr = ck + ((size_t)(hh * NCOARSE + j) << 6);
        float acc[8] = {0.f, 0.f, 0.f, 0.f, 0.f, 0.f, 0.f, 0.f};
#pragma unroll 4
        for (int d = 0; d < 64; d++) {
            float kv = ckr[d];
#pragma unroll
            for (int r = 0; r < 8; r++) acc[r] += kv * sq[r][d];
        }
#pragma unroll
        for (int r = 0; r < 8; r++) {
            int n = n0 + r;
            float s = (j <= (n >> 4)) ? acc[r] * SCALE : -FLT_MAX;
            csim[((size_t)hh * NTOK + n) * NCOARSE + j] = s;
            sims[r][j] = s;
        }
    }
    __syncthreads();

    const int r = tid >> 5, lane = tid & 31;
    const int n = n0 + r;
    const int jmax = n >> 4;
    float m = -FLT_MAX;
    for (int j = lane; j <= jmax; j += 32) m = fmaxf(m, sims[r][j]);
    for (int o = 16; o; o >>= 1) m = fmaxf(m, __shfl_xor_sync(0xffffffffu, m, o));
    float z = 0.f;
    for (int j = lane; j <= jmax; j += 32) {
        float e = expf(sims[r][j] - m);
        sims[r][j] = e;
        z += e;
    }
    for (int o = 16; o; o >>= 1) z += __shfl_xor_sync(0xffffffffu, z, o);
    __syncwarp();
    const float invz = 1.f / z;

    float acc0 = 0.f, acc1 = 0.f;
    const int jmax_blk = (n0 + 7) >> 4;
    for (int j0 = 0; j0 <= jmax_blk; j0 += 64) {
        int jcnt = NCOARSE - j0; if (jcnt > 64) jcnt = 64;
        int need = jmax_blk + 1 - j0; if (jcnt > need) jcnt = need;
        __syncthreads();
        for (int e = tid; e < 64 * 16; e += 256) {
            int jl = e >> 4, seg = e & 15;
            if (jl < jcnt) {
                float4 vv = *reinterpret_cast<const float4*>(
                    cv + ((size_t)(hh * NCOARSE + j0 + jl) << 6) + seg * 4);
                *reinterpret_cast<float4*>(&cvs[jl][seg * 4]) = vv;
            }
        }
        __syncthreads();
        int jend = jmax - j0; if (jend > jcnt - 1) jend = jcnt - 1;
        for (int jl = 0; jl <= jend; jl++) {
            float w = sims[r][j0 + jl];
            acc0 += w * cvs[jl][lane];
            acc1 += w * cvs[jl][lane + 32];
        }
    }
    comp[((size_t)hh * NTOK + n) * DH + lane]      = acc0 * invz;
    comp[((size_t)hh * NTOK + n) * DH + lane + 32] = acc1 * invz;
}

// ---------------- top-2 helper ----------------
__device__ __forceinline__ void top2_insert(float v, int f,
                                            float& t1v, int& t1f, float& t2v, int& t2f)
{
    if (f == t1f || f == t2f) return;
    if (v > t1v || (v == t1v && f < t1f)) { t2v = t1v; t2f = t1f; t1v = v; t1f = f; }
    else if (v > t2v || (v == t2v && f < t2f)) { t2v = v; t2f = f; }
}

// ---------------- top-k + fine + slide + combine ----------------
__global__ __launch_bounds__(256) void fine_slide_kernel(
    const float* __restrict__ rq, const float* __restrict__ rk, const float* __restrict__ v,
    const float* __restrict__ csim, const float* __restrict__ comp,
    const float* __restrict__ gates, float* __restrict__ attn)
{
    const int hh = blockIdx.y;
    const int warp = threadIdx.x >> 5, lane = threadIdx.x & 31;
    const int n = blockIdx.x * 8 + warp;
    const float SCALE = 0.125f;
    const unsigned FULL = 0xffffffffu;

    const size_t qb = (size_t)n * DIDIM + hh * DH;
    const float q0 = rq[qb + lane];
    const float q1 = rq[qb + lane + 32];

    const int nfb = n >> 1;
    float t1v = -INFINITY, t2v = -INFINITY;
    int   t1f = INT_MAX,   t2f = INT_MAX;
    float vloc[8]; int cloc[8];
    const size_t cbase = ((size_t)hh * NTOK + n) * NCOARSE + 1;
#pragma unroll
    for (int i = 0; i < 8; i++) {
        int jp = i * 32 + lane;
        int cnt = nfb - jp * 8;
        cnt = cnt > 8 ? 8 : cnt;
        if (cnt > 0) {
            float val = csim[cbase + jp];
            vloc[i] = val; cloc[i] = cnt;
            top2_insert(val, jp * 8, t1v, t1f, t2v, t2f);
            if (cnt > 1) top2_insert(val, jp * 8 + 1, t1v, t1f, t2v, t2f);
        } else cloc[i] = 0;
    }
    for (int o = 16; o; o >>= 1) {
        float ov1 = __shfl_xor_sync(FULL, t1v, o); int of1 = __shfl_xor_sync(FULL, t1f, o);
        float ov2 = __shfl_xor_sync(FULL, t2v, o); int of2 = __shfl_xor_sync(FULL, t2f, o);
        top2_insert(ov1, of1, t1v, t1f, t2v, t2f);
        top2_insert(ov2, of2, t1v, t1f, t2v, t2f);
    }
    const float mx = fmaxf(t1v, -1000.f);
    float part = 0.f;
#pragma unroll
    for (int i = 0; i < 8; i++)
        if (cloc[i]) part += (float)cloc[i] * expf(vloc[i] - mx);
    for (int o = 16; o; o >>= 1) part += __shfl_xor_sync(FULL, part, o);
    const float Z = expf(-1000.f - mx) + part;

    int fb1, fb2; float sv1, sv2;
    if (t1f == INT_MAX) { fb1 = 0; fb2 = 1; sv1 = 0.f; sv2 = 0.f; }
    else {
        fb1 = t1f; sv1 = expf(t1v - mx) / Z;
        if (t2f == INT_MAX) { fb2 = (t1f == 0) ? 1 : 0; sv2 = 0.f; }
        else { fb2 = t2f; sv2 = expf(t2v - mx) / Z; }
    }

    int rows6[6]; float sims6[6];
    const int blks[3] = { fb1, fb2, n >> 1 };
    const float svs[2] = { sv1, sv2 };
#pragma unroll
    for (int e = 0; e < 6; e++) {
        int b = blks[e >> 1], s = e & 1;
        int row = b * 2 + s;
        rows6[e] = row;
        bool vld = (e < 4) ? (svs[e >> 1] > 1e-10f) : (s <= (n & 1));
        size_t kb = (size_t)row * DIDIM + hh * DH;
        float p = q0 * rk[kb + lane] + q1 * rk[kb + lane + 32];
        for (int o = 16; o; o >>= 1) p += __shfl_xor_sync(FULL, p, o);
        sims6[e] = vld ? p * SCALE : -FLT_MAX;
    }
    float fm = -FLT_MAX;
#pragma unroll
    for (int e = 0; e < 6; e++) fm = fmaxf(fm, sims6[e]);
    float fz = 0.f, fo0 = 0.f, fo1 = 0.f;
#pragma unroll
    for (int e = 0; e < 6; e++) {
        float pe = expf(sims6[e] - fm);
        fz += pe;
        size_t vb = (size_t)rows6[e] * DIDIM + hh * DH;
        fo0 += pe * v[vb + lane];
        fo1 += pe * v[vb + lane + 32];
    }
    fo0 /= fz; fo1 /= fz;

    float simsw[SWIN + 1];
#pragma unroll
    for (int w = 0; w <= SWIN; w++) {
        int row = n - SWIN + w;
        bool vld = (row >= 0);
        size_t kb = (size_t)(vld ? row : 0) * DIDIM + hh * DH;
        float k0 = vld ? rk[kb + lane] : 0.f;
        float k1 = vld ? rk[kb + lane + 32] : 0.f;
        float p = q0 * k0 + q1 * k1;
        for (int o = 16; o; o >>= 1) p += __shfl_xor_sync(FULL, p, o);
        simsw[w] = vld ? p * SCALE : -FLT_MAX;
    }
    float sm = -FLT_MAX;
#pragma unroll
    for (int w = 0; w <= SWIN; w++) sm = fmaxf(sm, simsw[w]);
    float sz = 0.f, so0 = 0.f, so1 = 0.f;
#pragma unroll
    for (int w = 0; w <= SWIN; w++) {
        float pe = expf(simsw[w] - sm);
        sz += pe;
        int row = n - SWIN + w;
        if (row >= 0) {
            size_t vb = (size_t)row * DIDIM + hh * DH;
            so0 += pe * v[vb + lane];
            so1 += pe * v[vb + lane + 32];
        }
    }
    so0 /= sz; so1 /= sz;

    const float g0 = gates[n * 24 + hh * 3 + 0];
    const float g1 = gates[n * 24 + hh * 3 + 1];
    const float g2 = gates[n * 24 + hh * 3 + 2];
    const size_t cb2 = ((size_t)hh * NTOK + n) * DH;
    const float c0 = comp[cb2 + lane], c1 = comp[cb2 + lane + 32];
    attn[qb + lane]      = g0 * c0 + g1 * fo0 + g2 * so0;
    attn[qb + lane + 32] = g0 * c1 + g1 * fo1 + g2 * so1;
}

// ---------------- host-side orchestration ----------------
template<int BN, int P>
static inline void launch_g2(const GemmBatch& bt, int M, int N, int K,
                             int bias_mode, int act, int nz)
{
    constexpr int SMEM = 3 * 64 * 80 + 3 * BN * 80;
    dim3 grid(N / BN, M / 64, nz);
    gemm2_kernel<BN, P><<<grid, 128, SMEM>>>(bt, M, N, K, bias_mode, act);
}

extern "C" void kernel_launch(void* const* d_in, const int* in_sizes, int n_in,
                              void* d_out, int out_size)
{
    (void)in_sizes; (void)n_in; (void)out_size;
    float* base = nullptr;
    cudaGetSymbolAddress((void**)&base, g_buf);

    const float* x       = (const float*)d_in[0];
    const float* w_in    = (const float*)d_in[1];
    const float* b_in    = (const float*)d_in[2];
    const float* g_norm  = (const float*)d_in[3];
    const float* wq      = (const float*)d_in[4];
    const float* wk      = (const float*)d_in[5];
    const float* wv      = (const float*)d_in[6];
    const float* k_pos   = (const float*)d_in[7];
    const float* v_pos   = (const float*)d_in[8];
    const float* mem_k   = (const float*)d_in[9];
    const float* mem_v   = (const float*)d_in[10];
    const float* kc_w1   = (const float*)d_in[11];
    const float* kc_b1   = (const float*)d_in[12];
    const float* kc_w2   = (const float*)d_in[13];
    const float* kc_b2   = (const float*)d_in[14];
    const float* vc_w1   = (const float*)d_in[15];
    const float* vc_b1   = (const float*)d_in[16];
    const float* vc_w2   = (const float*)d_in[17];
    const float* vc_b2   = (const float*)d_in[18];
    const float* w_strat = (const float*)d_in[19];
    const float* b_strat = (const float*)d_in[20];
    const float* w_comb  = (const float*)d_in[21];
    const float* w_out   = (const float*)d_in[22];
    const float* b_out   = (const float*)d_in[23];
    float* out = (float*)d_out;

    // 1. x (C,N) -> xt (N,C)
    {
        dim3 th(32, 8), gr(NTOK / 32, CDIM / 32);
        transpose_kernel<<<gr, th>>>(x, base + O_XT, CDIM, NTOK);
    }
    // 2. xs_t = xt @ w_in^T + b_in
    {
        GemmBatch bt{};
        bt.A[0] = base + O_XT; bt.B[0] = w_in; bt.C[0] = base + O_XST;
        bt.bias[0] = b_in; bt.resid[0] = nullptr;
        launch_g2<128, 6>(bt, NTOK, CDIM, CDIM, 1, 0, 1);
    }
    // 3. RMSNorm
    rmsnorm_kernel<<<NTOK, 256>>>(base + O_XST, g_norm, base + O_H);
    // 4. q/k/v batched projection
    {
        GemmBatch bt{};
        bt.A[0] = bt.A[1] = bt.A[2] = base + O_H;
        bt.B[0] = wq; bt.B[1] = wk; bt.B[2] = wv;
        bt.C[0] = base + O_Q; bt.C[1] = base + O_K; bt.C[2] = base + O_V;
        launch_g2<128, 6>(bt, NTOK, DIDIM, CDIM, 0, 0, 3);
    }
    // 5. kin/vin (uses pre-rope k, v)
    build_kin_kernel<<<(2048 * 1024) / 256, 256>>>(base + O_K, base + O_V, k_pos, v_pos,
                                                   base + O_KIN, base + O_VIN);
    // 6. compression MLP layer-1 (batched pair)  [ncu capture slot]
    {
        GemmBatch bt{};
        bt.A[0] = base + O_KIN; bt.A[1] = base + O_VIN;
        bt.B[0] = kc_w1; bt.B[1] = vc_w1;
        bt.C[0] = base + O_HID; bt.C[1] = base + O_HID2;
        bt.bias[0] = kc_b1; bt.bias[1] = vc_b1;
        launch_g2<128, 6>(bt, 2048, 1024, 1024, 1, 1, 2);
    }
    // 7. RoPE
    rope_kernel<<<(NTOK * (DIDIM / 2) + 255) / 256, 256>>>(base + O_Q, base + O_K,
                                                           base + O_RQ, base + O_RK);
    // 8. compression MLP layer-2 (batched pair, N=64)
    {
        GemmBatch bt{};
        bt.A[0] = base + O_HID; bt.A[1] = base + O_HID2;
        bt.B[0] = kc_w2; bt.B[1] = vc_w2;
        bt.C[0] = base + O_CKF; bt.C[1] = base + O_CVF;
        bt.bias[0] = kc_b2; bt.bias[1] = vc_b2;
        launch_g2<64, 6>(bt, 2048, 64, 1024, 1, 0, 2);
    }
    // 9. concat mem slots
    build_ckcv_kernel<<<(NHEADS * NCOARSE * DH + 255) / 256, 256>>>(
        base + O_CKF, base + O_CVF, mem_k, mem_v, base + O_CK, base + O_CV);
    // 10. compressed attention
    {
        dim3 gr(NTOK / 8, NHEADS);
        csim_comp_kernel<<<gr, 256>>>(base + O_Q, base + O_CK, base + O_CV,
                                      base + O_CSIM, base + O_COMP);
    }
    // 11. gates
    {
        dim3 grid(1, NTOK / 64);
        gemm_nt_kernel<<<grid, 256>>>(base + O_H, w_strat, base + O_GATE,
                                      NTOK, 24, CDIM, b_strat, 1, nullptr, 2);
    }
    // 12. top-k + fine + slide + combine
    {
        dim3 gr(NTOK / 8, NHEADS);
        fine_slide_kernel<<<gr, 256>>>(base + O_RQ, base + O_RK, base + O_V,
                                       base + O_CSIM, base + O_COMP, base + O_GATE,
                                       base + O_ATTN);
    }
    // 13. xs_t (N,C) -> xs (C,N)  (residual for final GEMM)
    {
        dim3 th(32, 8), gr(CDIM / 32, NTOK / 32);
        transpose_kernel<<<gr, th>>>(base + O_XST, base + O_XS, NTOK, CDIM);
    }
    // 14. combine projection (output-side: 4-pass)
    {
        GemmBatch bt{};
        bt.A[0] = base + O_ATTN; bt.B[0] = w_comb; bt.C[0] = base + O_OUTC;
        launch_g2<128, 4>(bt, NTOK, CDIM, DIDIM, 0, 0, 1);
    }
    // 15. output conv + bias + xs residual -> d_out (output-side: 4-pass)
    {
        GemmBatch bt{};
        bt.A[0] = w_out; bt.B[0] = base + O_OUTC; bt.C[0] = out;
        bt.bias[0] = b_out; bt.resid[0] = base + O_XS;
        launch_g2<128, 4>(bt, CDIM, NTOK, CDIM, 2, 0, 1);
    }
}

// round 11
// speedup vs baseline: 2.2669x; 1.2367x over previous
#include <cuda_runtime.h>
#include <cuda_bf16.h>
#include <cfloat>
#include <climits>
#include <math.h>
#include <stdint.h>

// ---------------- problem constants ----------------
#define NTOK   4096
#define CDIM   512
#define DIDIM  512
#define NHEADS 8
#define DH     64
#define NCOARSE 257
#define CBLK   16
#define SWIN   8

static constexpr size_t SZ_NC = (size_t)NTOK * CDIM;

static constexpr size_t O_XT   = 0;
static constexpr size_t O_XST  = O_XT   + SZ_NC;
static constexpr size_t O_XS   = O_XST  + SZ_NC;
static constexpr size_t O_H    = O_XS   + SZ_NC;
static constexpr size_t O_Q    = O_H    + SZ_NC;
static constexpr size_t O_K    = O_Q    + SZ_NC;
static constexpr size_t O_V    = O_K    + SZ_NC;
static constexpr size_t O_RQ   = O_V    + SZ_NC;
static constexpr size_t O_RK   = O_RQ   + SZ_NC;
static constexpr size_t O_KIN  = O_RK   + SZ_NC;
static constexpr size_t O_VIN  = O_KIN  + SZ_NC;
static constexpr size_t O_HID  = O_VIN  + SZ_NC;      // (2048,1024) k-branch
static constexpr size_t O_HID2 = O_HID  + SZ_NC;      // (2048,1024) v-branch
static constexpr size_t O_CKF  = O_HID2 + SZ_NC;
static constexpr size_t O_CVF  = O_CKF  + (size_t)2048*64;
static constexpr size_t O_CK   = O_CVF  + (size_t)2048*64;
static constexpr size_t O_CV   = O_CK   + (size_t)NHEADS*NCOARSE*DH;
static constexpr size_t O_CSIM = O_CV   + (size_t)NHEADS*NCOARSE*DH;
static constexpr size_t O_COMP = O_CSIM + (size_t)NHEADS*NTOK*NCOARSE;
static constexpr size_t O_GATE = O_COMP + (size_t)NHEADS*NTOK*DH;
static constexpr size_t O_ATTN = O_GATE + (size_t)NTOK*24;
static constexpr size_t O_OUTC = O_ATTN + SZ_NC;
static constexpr size_t TOTAL  = O_OUTC + SZ_NC;

__device__ float g_buf[TOTAL];

// ============================================================================
// 3-limb bf16-split NT GEMM, 64xBN CTA tile, 128 threads, 2 CTAs/SM.
// PASSES=6: hh+hm+mh+hl+lh+mm (fp32-class).  PASSES=4: hh+hm+mh+mm.
// ============================================================================

struct GemmBatch {
    const float* A[3];
    const float* B[3];
    float*       C[3];
    const float* bias[3];
    const float* resid[3];
};

__device__ __forceinline__ uint32_t smem_u32(const void* p) {
    uint32_t a;
    asm("{ .reg .u64 t; cvta.to.shared.u64 t, %1; cvt.u32.u64 %0, t; }" : "=r"(a) : "l"(p));
    return a;
}

__device__ __forceinline__ void split3(float x, float y,
                                       uint32_t& hp, uint32_t& mp, uint32_t& lp)
{
    __nv_bfloat16 hx = __float2bfloat16(x), hy = __float2bfloat16(y);
    float rx = x - __bfloat162float(hx), ry = y - __bfloat162float(hy);
    __nv_bfloat16 mx = __float2bfloat16(rx), my = __float2bfloat16(ry);
    float sx = rx - __bfloat162float(mx), sy = ry - __bfloat162float(my);
    __nv_bfloat16 lx = __float2bfloat16(sx), ly = __float2bfloat16(sy);
    __nv_bfloat162 hv; hv.x = hx; hv.y = hy;
    __nv_bfloat162 mv; mv.x = mx; mv.y = my;
    __nv_bfloat162 lv; lv.x = lx; lv.y = ly;
    hp = *reinterpret_cast<uint32_t*>(&hv);
    mp = *reinterpret_cast<uint32_t*>(&mv);
    lp = *reinterpret_cast<uint32_t*>(&lv);
}

#define LDSM_X4(r0, r1, r2, r3, addr) \
    asm volatile("ldmatrix.sync.aligned.m8n8.x4.shared.b16 {%0,%1,%2,%3}, [%4];" \
                 : "=r"(r0), "=r"(r1), "=r"(r2), "=r"(r3) : "r"(addr))

__device__ __forceinline__ void mma_bf16(float4& d, const uint32_t* a, const uint32_t* b) {
    asm volatile(
        "mma.sync.aligned.m16n8k16.row.col.f32.bf16.bf16.f32 "
        "{%0,%1,%2,%3}, {%4,%5,%6,%7}, {%8,%9}, {%0,%1,%2,%3};"
        : "+f"(d.x), "+f"(d.y), "+f"(d.z), "+f"(d.w)
        : "r"(a[0]), "r"(a[1]), "r"(a[2]), "r"(a[3]), "r"(b[0]), "r"(b[1]));
}

template<int BN, int PASSES>
__global__ __launch_bounds__(128, 2) void gemm2_kernel(
    GemmBatch bt, int M, int N, int K, int bias_mode, int act)
{
    constexpr int LDSB = 80;
    constexpr int ASZ  = 64 * LDSB;
    constexpr int BSZ  = BN * LDSB;
    constexpr int NTW  = BN / 16;
    constexpr int BREG = BN / 16;

    const float* __restrict__ A     = bt.A[blockIdx.z];
    const float* __restrict__ B     = bt.B[blockIdx.z];
    float*       __restrict__ C     = bt.C[blockIdx.z];
    const float* __restrict__ bias  = bt.bias[blockIdx.z];
    const float* __restrict__ resid = bt.resid[blockIdx.z];

    extern __shared__ char dsm[];
    const uint32_t sb = smem_u32(dsm);
    const int tid = threadIdx.x, warp = tid >> 5, lane = tid & 31;
    const int wm = warp >> 1, wn = warp & 1;
    const int bm0 = blockIdx.y * 64, bn0 = blockIdx.x * BN;

    float4 acc[2][NTW];
#pragma unroll
    for (int i = 0; i < 2; i++)
#pragma unroll
        for (int j = 0; j < NTW; j++) acc[i][j] = make_float4(0.f, 0.f, 0.f, 0.f);

    const int arow = tid >> 1, akh = (tid & 1) * 16;
    const float* aptr = A + (size_t)(bm0 + arow) * K + akh;
    const float* bptr = B + (size_t)(bn0 + arow) * K + akh;

    float4 areg[4], breg[BREG];

    auto ldg_tiles = [&](int k0) {
#pragma unroll
        for (int i = 0; i < 4; i++)
            areg[i] = *reinterpret_cast<const float4*>(aptr + k0 + i * 4);
#pragma unroll
        for (int i = 0; i < 4; i++)
            breg[i] = *reinterpret_cast<const float4*>(bptr + k0 + i * 4);
        if (BN == 128) {
#pragma unroll
            for (int i = 0; i < 4; i++)
                breg[4 + i] = *reinterpret_cast<const float4*>(bptr + (size_t)64 * K + k0 + i * 4);
        }
    };

    auto sts16 = [&](char* hb, char* mb, char* lb, int off, float4* rg) {
        uint32_t h[8], m[8], l[8];
#pragma unroll
        for (int i = 0; i < 4; i++) {
            const float* f = reinterpret_cast<const float*>(&rg[i]);
#pragma unroll
            for (int j = 0; j < 2; j++)
                split3(f[2 * j], f[2 * j + 1], h[2 * i + j], m[2 * i + j], l[2 * i + j]);
        }
        *reinterpret_cast<uint4*>(hb + off)      = make_uint4(h[0], h[1], h[2], h[3]);
        *reinterpret_cast<uint4*>(hb + off + 16) = make_uint4(h[4], h[5], h[6], h[7]);
        *reinterpret_cast<uint4*>(mb + off)      = make_uint4(m[0], m[1], m[2], m[3]);
        *reinterpret_cast<uint4*>(mb + off + 16) = make_uint4(m[4], m[5], m[6], m[7]);
        if (PASSES == 6) {
            *reinterpret_cast<uint4*>(lb + off)      = make_uint4(l[0], l[1], l[2], l[3]);
            *reinterpret_cast<uint4*>(lb + off + 16) = make_uint4(l[4], l[5], l[6], l[7]);
        }
    };

    auto sts_tiles = [&]() {
        int off = arow * LDSB + akh * 2;
        sts16(dsm, dsm + ASZ, dsm + 2 * ASZ, off, areg);
        char* bb = dsm + 3 * ASZ;
        sts16(bb, bb + BSZ, bb + 2 * BSZ, off, breg);
        if (BN == 128)
            sts16(bb, bb + BSZ, bb + 2 * BSZ, off + 64 * LDSB, breg + 4);
    };

    const int a_r  = wm * 32 + (lane & 7) + ((lane >> 3) & 1) * 8;
    const int a_kc = (lane >> 4) * 8;
    const int b_sel = lane >> 3;
    const int b_r   = wn * (BN / 2) + (b_sel >> 1) * 8 + (lane & 7);
    const int b_kc  = (b_sel & 1) * 8;

    auto compute = [&]() {
        const uint32_t s0 = sb;
#pragma unroll
        for (int kk = 0; kk < 2; kk++) {
            uint32_t afh[2][4], afm[2][4], afl[2][4];
#pragma unroll
            for (int mi = 0; mi < 2; mi++) {
                int off = (a_r + mi * 16) * LDSB + (a_kc + kk * 16) * 2;
                LDSM_X4(afh[mi][0], afh[mi][1], afh[mi][2], afh[mi][3], s0 + off);
                LDSM_X4(afm[mi][0], afm[mi][1], afm[mi][2], afm[mi][3], s0 + ASZ + off);
                if (PASSES == 6)
                    LDSM_X4(afl[mi][0], afl[mi][1], afl[mi][2], afl[mi][3], s0 + 2 * ASZ + off);
            }
#pragma unroll
            for (int np = 0; np < NTW / 2; np++) {
                int off = (b_r + np * 16) * LDSB + (b_kc + kk * 16) * 2;
                uint32_t bh[2][2], bm[2][2], bl[2][2];
                LDSM_X4(bh[0][0], bh[0][1], bh[1][0], bh[1][1], s0 + 3 * ASZ + off);
                LDSM_X4(bm[0][0], bm[0][1], bm[1][0], bm[1][1], s0 + 3 * ASZ + BSZ + off);
                if (PASSES == 6)
                    LDSM_X4(bl[0][0], bl[0][1], bl[1][0], bl[1][1], s0 + 3 * ASZ + 2 * BSZ + off);
#pragma unroll
                for (int mi = 0; mi < 2; mi++)
#pragma unroll
                    for (int q = 0; q < 2; q++) {
                        int ni = 2 * np + q;
                        mma_bf16(acc[mi][ni], afh[mi], bh[q]);
                        mma_bf16(acc[mi][ni], afh[mi], bm[q]);
                        mma_bf16(acc[mi][ni], afm[mi], bh[q]);
                        if (PASSES == 6) {
                            mma_bf16(acc[mi][ni], afh[mi], bl[q]);
                            mma_bf16(acc[mi][ni], afl[mi], bh[q]);
                        }
                        mma_bf16(acc[mi][ni], afm[mi], bm[q]);
                    }
            }
        }
    };

    ldg_tiles(0);
    const int slabs = K / 32;
    for (int s = 0; s < slabs; s++) {
        if (s > 0) __syncthreads();
        sts_tiles();
        __syncthreads();
        if (s + 1 < slabs) ldg_tiles((s + 1) * 32);
        compute();
    }

    const int g = lane >> 2, cc = lane & 3;
#pragma unroll
    for (int mi = 0; mi < 2; mi++) {
#pragma unroll
        for (int ni = 0; ni < NTW; ni++) {
            int mrow = bm0 + wm * 32 + mi * 16 + g;
            int ncol = bn0 + wn * (BN / 2) + ni * 8 + cc * 2;
            float2 r0 = make_float2(acc[mi][ni].x, acc[mi][ni].y);
            float2 r1 = make_float2(acc[mi][ni].z, acc[mi][ni].w);
            if (bias_mode == 1) {
                float b0 = bias[ncol], b1 = bias[ncol + 1];
                r0.x += b0; r0.y += b1; r1.x += b0; r1.y += b1;
            } else if (bias_mode == 2) {
                float bt_ = bias[mrow], bb_ = bias[mrow + 8];
                r0.x += bt_; r0.y += bt_; r1.x += bb_; r1.y += bb_;
            }
            if (act == 1) {
                r0.x = fmaxf(r0.x, 0.f); r0.y = fmaxf(r0.y, 0.f);
                r1.x = fmaxf(r1.x, 0.f); r1.y = fmaxf(r1.y, 0.f);
            }
            if (resid) {
                float2 q0 = *reinterpret_cast<const float2*>(resid + (size_t)mrow * N + ncol);
                float2 q1 = *reinterpret_cast<const float2*>(resid + (size_t)(mrow + 8) * N + ncol);
                r0.x += q0.x; r0.y += q0.y; r1.x += q1.x; r1.y += q1.y;
            }
            *reinterpret_cast<float2*>(C + (size_t)mrow * N + ncol) = r0;
            *reinterpret_cast<float2*>(C + (size_t)(mrow + 8) * N + ncol) = r1;
        }
    }
}

// ---------------- SIMT NT GEMM (gates only) ----------------
__global__ __launch_bounds__(256) void gemm_nt_kernel(
    const float* __restrict__ A, const float* __restrict__ B, float* __restrict__ C,
    int M, int Ncols, int K, const float* __restrict__ bias, int bias_mode,
    const float* __restrict__ resid, int act)
{
    __shared__ float As[16][64];
    __shared__ float Bs[16][64];
    const int tid = threadIdx.x;
    const int tx  = tid & 15;
    const int ty  = tid >> 4;
    const int bm0 = blockIdx.y * 64;
    const int bn0 = blockIdx.x * 64;
    const int lr  = tid >> 2;
    const int lk  = (tid & 3) << 2;

    float acc[4][4];
#pragma unroll
    for (int i = 0; i < 4; i++)
#pragma unroll
        for (int j = 0; j < 4; j++) acc[i][j] = 0.f;

    for (int k0 = 0; k0 < K; k0 += 16) {
        {
            int am = bm0 + lr;
            float4 av = make_float4(0.f, 0.f, 0.f, 0.f);
            if (am < M) av = *reinterpret_cast<const float4*>(A + (size_t)am * K + k0 + lk);
            As[lk + 0][lr] = av.x; As[lk + 1][lr] = av.y;
            As[lk + 2][lr] = av.z; As[lk + 3][lr] = av.w;
        }
        {
            int bn = bn0 + lr;
            float4 bv = make_float4(0.f, 0.f, 0.f, 0.f);
            if (bn < Ncols) bv = *reinterpret_cast<const float4*>(B + (size_t)bn * K + k0 + lk);
            Bs[lk + 0][lr] = bv.x; Bs[lk + 1][lr] = bv.y;
            Bs[lk + 2][lr] = bv.z; Bs[lk + 3][lr] = bv.w;
        }
        __syncthreads();
#pragma unroll
        for (int kk = 0; kk < 16; kk++) {
            float4 a = *reinterpret_cast<const float4*>(&As[kk][ty << 2]);
            float4 b = *reinterpret_cast<const float4*>(&Bs[kk][tx << 2]);
            acc[0][0] += a.x * b.x; acc[0][1] += a.x * b.y; acc[0][2] += a.x * b.z; acc[0][3] += a.x * b.w;
            acc[1][0] += a.y * b.x; acc[1][1] += a.y * b.y; acc[1][2] += a.y * b.z; acc[1][3] += a.y * b.w;
            acc[2][0] += a.z * b.x; acc[2][1] += a.z * b.y; acc[2][2] += a.z * b.z; acc[2][3] += a.z * b.w;
            acc[3][0] += a.w * b.x; acc[3][1] += a.w * b.y; acc[3][2] += a.w * b.z; acc[3][3] += a.w * b.w;
        }
        __syncthreads();
    }
#pragma unroll
    for (int i = 0; i < 4; i++) {
        int m = bm0 + (ty << 2) + i;
        if (m >= M) continue;
#pragma unroll
        for (int j = 0; j < 4; j++) {
            int nn = bn0 + (tx << 2) + j;
            if (nn >= Ncols) continue;
            float vv = acc[i][j];
            if (bias_mode == 1) vv += bias[nn];
            else if (bias_mode == 2) vv += bias[m];
            if (act == 1) vv = fmaxf(vv, 0.f);
            else if (act == 2) vv = 1.f / (1.f + expf(-vv));
            if (resid) vv += resid[(size_t)m * Ncols + nn];
            C[(size_t)m * Ncols + nn] = vv;
        }
    }
}

// ---------------- transpose ----------------
__global__ void transpose_kernel(const float* __restrict__ in, float* __restrict__ out,
                                 int R, int Ccols)
{
    __shared__ float tile[32][33];
    int r0 = blockIdx.y * 32, c0 = blockIdx.x * 32;
#pragma unroll
    for (int i = 0; i < 32; i += 8) {
        int r = r0 + threadIdx.y + i, c = c0 + threadIdx.x;
        if (r < R && c < Ccols) tile[threadIdx.y + i][threadIdx.x] = in[(size_t)r * Ccols + c];
    }
    __syncthreads();
#pragma unroll
    for (int i = 0; i < 32; i += 8) {
        int rr = c0 + threadIdx.y + i, cc = r0 + threadIdx.x;
        if (rr < Ccols && cc < R) out[(size_t)rr * R + cc] = tile[threadIdx.x][threadIdx.y + i];
    }
}

// ---------------- RMSNorm ----------------
__global__ void rmsnorm_kernel(const float* __restrict__ xs_t, const float* __restrict__ g,
                               float* __restrict__ h)
{
    int n = blockIdx.x, tid = threadIdx.x;
    const float* row = xs_t + (size_t)n * CDIM;
    float s = 0.f;
    for (int c = tid; c < CDIM; c += 256) { float v = row[c]; s += v * v; }
    __shared__ float red[256];
    red[tid] = s; __syncthreads();
    for (int o = 128; o; o >>= 1) { if (tid < o) red[tid] += red[tid + o]; __syncthreads(); }
    float inv = rsqrtf(red[0] / (float)CDIM + 1e-6f);
    for (int c = tid; c < CDIM; c += 256)
        h[(size_t)n * CDIM + c] = row[c] * inv * g[c];
}

// ---------------- RoPE ----------------
__global__ void rope_kernel(const float* __restrict__ q, const float* __restrict__ k,
                            float* __restrict__ rq, float* __restrict__ rk)
{
    int p = blockIdx.x * blockDim.x + threadIdx.x;
    if (p >= NTOK * (DIDIM / 2)) return;
    int n = p / (DIDIM / 2);
    int r = p % (DIDIM / 2);
    int i = r & 31;
    int base = n * DIDIM + (r >> 5) * DH + 2 * i;
    float inv = 1.f / powf(10000.f, (float)(2 * i) / 64.f);
    float ang = (float)n * inv;
    float s, c;
    sincosf(ang, &s, &c);
    float q0 = q[base], q1 = q[base + 1];
    rq[base]     = q0 * c - q1 * s;
    rq[base + 1] = q1 * c + q0 * s;
    float k0 = k[base], k1 = k[base + 1];
    rk[base]     = k0 * c - k1 * s;
    rk[base + 1] = k1 * c + k0 * s;
}

// ---------------- build compression MLP inputs ----------------
__global__ void build_kin_kernel(const float* __restrict__ k, const float* __restrict__ v,
                                 const float* __restrict__ k_pos, const float* __restrict__ v_pos,
                                 float* __restrict__ kin, float* __restrict__ vin)
{
    int idx = blockIdx.x * 256 + threadIdx.x;
    if (idx >= 2048 * 1024) return;
    int row = idx >> 10;
    int col = idx & 1023;
    int hh = row >> 8, cb = row & 255;
    int i = col >> 6, d = col & 63;
    int n = cb * CBLK + i;
    size_t ko = (size_t)n * DIDIM + hh * DH + d;
    size_t po = (size_t)(hh * CBLK + i) * DH + d;
    kin[idx] = k[ko] + k_pos[po];
    vin[idx] = v[ko] + v_pos[po];
}

// ---------------- concat mem slot + compressed k/v ----------------
__global__ void build_ckcv_kernel(const float* __restrict__ ckf, const float* __restrict__ cvf,
                                  const float* __restrict__ mem_k, const float* __restrict__ mem_v,
                                  float* __restrict__ ck, float* __restrict__ cv)
{
    int idx = blockIdx.x * 256 + threadIdx.x;
    if (idx >= NHEADS * NCOARSE * DH) return;
    int hh = idx / (NCOARSE * DH);
    int rem = idx - hh * (NCOARSE * DH);
    int j = rem / DH, d = rem % DH;
    if (j == 0) {
        ck[idx] = mem_k[hh * DH + d];
        cv[idx] = mem_v[hh * DH + d];
    } else {
        size_t src = (size_t)((hh << 8) + j - 1) * DH + d;
        ck[idx] = ckf[src];
        cv[idx] = cvf[src];
    }
}

// ---------------- compressed attention (smem-staged QK^T + chunked AV) ----------------
__global__ __launch_bounds__(256) void csim_comp_kernel(
    const float* __restrict__ q, const float* __restrict__ ck, const float* __restrict__ cv,
    float* __restrict__ csim, float* __restrict__ comp)
{
    __shared__ float sq[8][64];
    __shared__ float sims[8][260];
    __shared__ float cks[64][68];    // reused for cv in the AV phase
    const int hh = blockIdx.y;
    const int n0 = blockIdx.x * 8;
    const int tid = threadIdx.x;
    const int warp = tid >> 5, lane = tid & 31;
    const float SCALE = 0.125f;

    for (int t = tid; t < 8 * 64; t += 256) {
        int r = t >> 6, d = t & 63;
        sq[r][d] = q[(size_t)(n0 + r) * DIDIM + hh * DH + d];
    }
    __syncthreads();

    const int jmax_blk = (n0 + 7) >> 4;
    const int r = warp;                 // one warp per query row
    const int nrow = n0 + r;
    const int jmaxr = nrow >> 4;
    const size_t crow = ((size_t)hh * NTOK + nrow) * NCOARSE;

    for (int j0 = 0; j0 < NCOARSE; j0 += 64) {
        int jcnt = NCOARSE - j0; if (jcnt > 64) jcnt = 64;
        if (j0 <= jmax_blk) {
            // coalesced cooperative load of ck chunk
            for (int e = tid; e < 64 * 16; e += 256) {
                int jl = e >> 4, seg = e & 15;
                if (jl < jcnt) {
                    float4 vv = *reinterpret_cast<const float4*>(
                        ck + ((size_t)(hh * NCOARSE + j0 + jl) << 6) + seg * 4);
                    *reinterpret_cast<float4*>(&cks[jl][seg * 4]) = vv;
                }
            }
            __syncthreads();
            // each warp computes its row against the chunk (lane-rotated, bank-clean)
#pragma unroll
            for (int half = 0; half < 2; half++) {
                int jl = lane + 32 * half;
                if (jl < jcnt) {
                    float acc = 0.f;
#pragma unroll 8
                    for (int dd = 0; dd < 64; dd++) {
                        int d = (dd + lane) & 63;
                        acc += sq[r][d] * cks[jl][d];
                    }
                    int j = j0 + jl;
                    float s = (j <= jmaxr) ? acc * SCALE : -FLT_MAX;
                    csim[crow + j] = s;
                    sims[r][j] = s;
                }
            }
            __syncthreads();
        } else {
            // beyond block causal bound: fill sentinel, no loads/compute
#pragma unroll
            for (int half = 0; half < 2; half++) {
                int jl = lane + 32 * half;
                if (jl < jcnt) {
                    int j = j0 + jl;
                    csim[crow + j] = -FLT_MAX;
                    sims[r][j] = -FLT_MAX;
                }
            }
        }
    }
    __syncthreads();

    // softmax over valid range
    float m = -FLT_MAX;
    for (int j = lane; j <= jmaxr; j += 32) m = fmaxf(m, sims[r][j]);
    for (int o = 16; o; o >>= 1) m = fmaxf(m, __shfl_xor_sync(0xffffffffu, m, o));
    float z = 0.f;
    for (int j = lane; j <= jmaxr; j += 32) {
        float e = expf(sims[r][j] - m);
        sims[r][j] = e;
        z += e;
    }
    for (int o = 16; o; o >>= 1) z += __shfl_xor_sync(0xffffffffu, z, o);
    __syncwarp();
    const float invz = 1.f / z;

    // chunked AV (cv staged in smem, reuse cks)
    float acc0 = 0.f, acc1 = 0.f;
    for (int j0 = 0; j0 <= jmax_blk; j0 += 64) {
        int jcnt = NCOARSE - j0; if (jcnt > 64) jcnt = 64;
        int need = jmax_blk + 1 - j0; if (jcnt > need) jcnt = need;
        __syncthreads();
        for (int e = tid; e < 64 * 16; e += 256) {
            int jl = e >> 4, seg = e & 15;
            if (jl < jcnt) {
                float4 vv = *reinterpret_cast<const float4*>(
                    cv + ((size_t)(hh * NCOARSE + j0 + jl) << 6) + seg * 4);
                *reinterpret_cast<float4*>(&cks[jl][seg * 4]) = vv;
            }
        }
        __syncthreads();
        int jend = jmaxr - j0; if (jend > jcnt - 1) jend = jcnt - 1;
        for (int jl = 0; jl <= jend; jl++) {
            float w = sims[r][j0 + jl];
            acc0 += w * cks[jl][lane];
            acc1 += w * cks[jl][lane + 32];
        }
    }
    comp[((size_t)hh * NTOK + nrow) * DH + lane]      = acc0 * invz;
    comp[((size_t)hh * NTOK + nrow) * DH + lane + 32] = acc1 * invz;
}

// ---------------- top-2 helper ----------------
__device__ __forceinline__ void top2_insert(float v, int f,
                                            float& t1v, int& t1f, float& t2v, int& t2f)
{
    if (f == t1f || f == t2f) return;
    if (v > t1v || (v == t1v && f < t1f)) { t2v = t1v; t2f = t1f; t1v = v; t1f = f; }
    else if (v > t2v || (v == t2v && f < t2f)) { t2v = v; t2f = f; }
}

// ---------------- top-k + fine + slide + combine ----------------
__global__ __launch_bounds__(256) void fine_slide_kernel(
    const float* __restrict__ rq, const float* __restrict__ rk, const float* __restrict__ v,
    const float* __restrict__ csim, const float* __restrict__ comp,
    const float* __restrict__ gates, float* __restrict__ attn)
{
    const int hh = blockIdx.y;
    const int warp = threadIdx.x >> 5, lane = threadIdx.x & 31;
    const int n = blockIdx.x * 8 + warp;
    const float SCALE = 0.125f;
    const unsigned FULL = 0xffffffffu;

    const size_t qb = (size_t)n * DIDIM + hh * DH;
    const float q0 = rq[qb + lane];
    const float q1 = rq[qb + lane + 32];

    const int nfb = n >> 1;
    float t1v = -INFINITY, t2v = -INFINITY;
    int   t1f = INT_MAX,   t2f = INT_MAX;
    float vloc[8]; int cloc[8];
    const size_t cbase = ((size_t)hh * NTOK + n) * NCOARSE + 1;
#pragma unroll
    for (int i = 0; i < 8; i++) {
        int jp = i * 32 + lane;
        int cnt = nfb - jp * 8;
        cnt = cnt > 8 ? 8 : cnt;
        if (cnt > 0) {
            float val = csim[cbase + jp];
            vloc[i] = val; cloc[i] = cnt;
            top2_insert(val, jp * 8, t1v, t1f, t2v, t2f);
            if (cnt > 1) top2_insert(val, jp * 8 + 1, t1v, t1f, t2v, t2f);
        } else cloc[i] = 0;
    }
    for (int o = 16; o; o >>= 1) {
        float ov1 = __shfl_xor_sync(FULL, t1v, o); int of1 = __shfl_xor_sync(FULL, t1f, o);
        float ov2 = __shfl_xor_sync(FULL, t2v, o); int of2 = __shfl_xor_sync(FULL, t2f, o);
        top2_insert(ov1, of1, t1v, t1f, t2v, t2f);
        top2_insert(ov2, of2, t1v, t1f, t2v, t2f);
    }
    const float mx = fmaxf(t1v, -1000.f);
    float part = 0.f;
#pragma unroll
    for (int i = 0; i < 8; i++)
        if (cloc[i]) part += (float)cloc[i] * expf(vloc[i] - mx);
    for (int o = 16; o; o >>= 1) part += __shfl_xor_sync(FULL, part, o);
    const float Z = expf(-1000.f - mx) + part;

    int fb1, fb2; float sv1, sv2;
    if (t1f == INT_MAX) { fb1 = 0; fb2 = 1; sv1 = 0.f; sv2 = 0.f; }
    else {
        fb1 = t1f; sv1 = expf(t1v - mx) / Z;
        if (t2f == INT_MAX) { fb2 = (t1f == 0) ? 1 : 0; sv2 = 0.f; }
        else { fb2 = t2f; sv2 = expf(t2v - mx) / Z; }
    }

    int rows6[6]; float sims6[6];
    const int blks[3] = { fb1, fb2, n >> 1 };
    const float svs[2] = { sv1, sv2 };
#pragma unroll
    for (int e = 0; e < 6; e++) {
        int b = blks[e >> 1], s = e & 1;
        int row = b * 2 + s;
        rows6[e] = row;
        bool vld = (e < 4) ? (svs[e >> 1] > 1e-10f) : (s <= (n & 1));
        size_t kb = (size_t)row * DIDIM + hh * DH;
        float p = q0 * rk[kb + lane] + q1 * rk[kb + lane + 32];
        for (int o = 16; o; o >>= 1) p += __shfl_xor_sync(FULL, p, o);
        sims6[e] = vld ? p * SCALE : -FLT_MAX;
    }
    float fm = -FLT_MAX;
#pragma unroll
    for (int e = 0; e < 6; e++) fm = fmaxf(fm, sims6[e]);
    float fz = 0.f, fo0 = 0.f, fo1 = 0.f;
#pragma unroll
    for (int e = 0; e < 6; e++) {
        float pe = expf(sims6[e] - fm);
        fz += pe;
        size_t vb = (size_t)rows6[e] * DIDIM + hh * DH;
        fo0 += pe * v[vb + lane];
        fo1 += pe * v[vb + lane + 32];
    }
    fo0 /= fz; fo1 /= fz;

    float simsw[SWIN + 1];
#pragma unroll
    for (int w = 0; w <= SWIN; w++) {
        int row = n - SWIN + w;
        bool vld = (row >= 0);
        size_t kb = (size_t)(vld ? row : 0) * DIDIM + hh * DH;
        float k0 = vld ? rk[kb + lane] : 0.f;
        float k1 = vld ? rk[kb + lane + 32] : 0.f;
        float p = q0 * k0 + q1 * k1;
        for (int o = 16; o; o >>= 1) p += __shfl_xor_sync(FULL, p, o);
        simsw[w] = vld ? p * SCALE : -FLT_MAX;
    }
    float sm = -FLT_MAX;
#pragma unroll
    for (int w = 0; w <= SWIN; w++) sm = fmaxf(sm, simsw[w]);
    float sz = 0.f, so0 = 0.f, so1 = 0.f;
#pragma unroll
    for (int w = 0; w <= SWIN; w++) {
        float pe = expf(simsw[w] - sm);
        sz += pe;
        int row = n - SWIN + w;
        if (row >= 0) {
            size_t vb = (size_t)row * DIDIM + hh * DH;
            so0 += pe * v[vb + lane];
            so1 += pe * v[vb + lane + 32];
        }
    }
    so0 /= sz; so1 /= sz;

    const float g0 = gates[n * 24 + hh * 3 + 0];
    const float g1 = gates[n * 24 + hh * 3 + 1];
    const float g2 = gates[n * 24 + hh * 3 + 2];
    const size_t cb2 = ((size_t)hh * NTOK + n) * DH;
    const float c0 = comp[cb2 + lane], c1 = comp[cb2 + lane + 32];
    attn[qb + lane]      = g0 * c0 + g1 * fo0 + g2 * so0;
    attn[qb + lane + 32] = g0 * c1 + g1 * fo1 + g2 * so1;
}

// ---------------- host-side orchestration ----------------
template<int BN, int P>
static inline void launch_g2(const GemmBatch& bt, int M, int N, int K,
                             int bias_mode, int act, int nz)
{
    constexpr int SMEM = 3 * 64 * 80 + 3 * BN * 80;
    dim3 grid(N / BN, M / 64, nz);
    gemm2_kernel<BN, P><<<grid, 128, SMEM>>>(bt, M, N, K, bias_mode, act);
}

extern "C" void kernel_launch(void* const* d_in, const int* in_sizes, int n_in,
                              void* d_out, int out_size)
{
    (void)in_sizes; (void)n_in; (void)out_size;
    float* base = nullptr;
    cudaGetSymbolAddress((void**)&base, g_buf);

    const float* x       = (const float*)d_in[0];
    const float* w_in    = (const float*)d_in[1];
    const float* b_in    = (const float*)d_in[2];
    const float* g_norm  = (const float*)d_in[3];
    const float* wq      = (const float*)d_in[4];
    const float* wk      = (const float*)d_in[5];
    const float* wv      = (const float*)d_in[6];
    const float* k_pos   = (const float*)d_in[7];
    const float* v_pos   = (const float*)d_in[8];
    const float* mem_k   = (const float*)d_in[9];
    const float* mem_v   = (const float*)d_in[10];
    const float* kc_w1   = (const float*)d_in[11];
    const float* kc_b1   = (const float*)d_in[12];
    const float* kc_w2   = (const float*)d_in[13];
    const float* kc_b2   = (const float*)d_in[14];
    const float* vc_w1   = (const float*)d_in[15];
    const float* vc_b1   = (const float*)d_in[16];
    const float* vc_w2   = (const float*)d_in[17];
    const float* vc_b2   = (const float*)d_in[18];
    const float* w_strat = (const float*)d_in[19];
    const float* b_strat = (const float*)d_in[20];
    const float* w_comb  = (const float*)d_in[21];
    const float* w_out   = (const float*)d_in[22];
    const float* b_out   = (const float*)d_in[23];
    float* out = (float*)d_out;

    // 1. x (C,N) -> xt (N,C)
    {
        dim3 th(32, 8), gr(NTOK / 32, CDIM / 32);
        transpose_kernel<<<gr, th>>>(x, base + O_XT, CDIM, NTOK);
    }
    // 2. xs_t = xt @ w_in^T + b_in
    {
        GemmBatch bt{};
        bt.A[0] = base + O_XT; bt.B[0] = w_in; bt.C[0] = base + O_XST;
        bt.bias[0] = b_in; bt.resid[0] = nullptr;
        launch_g2<128, 6>(bt, NTOK, CDIM, CDIM, 1, 0, 1);
    }
    // 3. RMSNorm
    rmsnorm_kernel<<<NTOK, 256>>>(base + O_XST, g_norm, base + O_H);
    // 4. q/k/v batched projection  [ncu capture region]
    {
        GemmBatch bt{};
        bt.A[0] = bt.A[1] = bt.A[2] = base + O_H;
        bt.B[0] = wq; bt.B[1] = wk; bt.B[2] = wv;
        bt.C[0] = base + O_Q; bt.C[1] = base + O_K; bt.C[2] = base + O_V;
        launch_g2<128, 6>(bt, NTOK, DIDIM, CDIM, 0, 0, 3);
    }
    // 5. kin/vin (uses pre-rope k, v)
    build_kin_kernel<<<(2048 * 1024) / 256, 256>>>(base + O_K, base + O_V, k_pos, v_pos,
                                                   base + O_KIN, base + O_VIN);
    // 6. compression MLP layer-1 (batched pair)
    {
        GemmBatch bt{};
        bt.A[0] = base + O_KIN; bt.A[1] = base + O_VIN;
        bt.B[0] = kc_w1; bt.B[1] = vc_w1;
        bt.C[0] = base + O_HID; bt.C[1] = base + O_HID2;
        bt.bias[0] = kc_b1; bt.bias[1] = vc_b1;
        launch_g2<128, 6>(bt, 2048, 1024, 1024, 1, 1, 2);
    }
    // 7. RoPE
    rope_kernel<<<(NTOK * (DIDIM / 2) + 255) / 256, 256>>>(base + O_Q, base + O_K,
                                                           base + O_RQ, base + O_RK);
    // 8. compression MLP layer-2 (batched pair, N=64)
    {
        GemmBatch bt{};
        bt.A[0] = base + O_HID; bt.A[1] = base + O_HID2;
        bt.B[0] = kc_w2; bt.B[1] = vc_w2;
        bt.C[0] = base + O_CKF; bt.C[1] = base + O_CVF;
        bt.bias[0] = kc_b2; bt.bias[1] = vc_b2;
        launch_g2<64, 6>(bt, 2048, 64, 1024, 1, 0, 2);
    }
    // 9. concat mem slots
    build_ckcv_kernel<<<(NHEADS * NCOARSE * DH + 255) / 256, 256>>>(
        base + O_CKF, base + O_CVF, mem_k, mem_v, base + O_CK, base + O_CV);
    // 10. compressed attention
    {
        dim3 gr(NTOK / 8, NHEADS);
        csim_comp_kernel<<<gr, 256>>>(base + O_Q, base + O_CK, base + O_CV,
                                      base + O_CSIM, base + O_COMP);
    }
    // 11. gates
    {
        dim3 grid(1, NTOK / 64);
        gemm_nt_kernel<<<grid, 256>>>(base + O_H, w_strat, base + O_GATE,
                                      NTOK, 24, CDIM, b_strat, 1, nullptr, 2);
    }
    // 12. top-k + fine + slide + combine
    {
        dim3 gr(NTOK / 8, NHEADS);
        fine_slide_kernel<<<gr, 256>>>(base + O_RQ, base + O_RK, base + O_V,
                                       base + O_CSIM, base + O_COMP, base + O_GATE,
                                       base + O_ATTN);
    }
    // 13. xs_t (N,C) -> xs (C,N)  (residual for final GEMM)
    {
        dim3 th(32, 8), gr(CDIM / 32, NTOK / 32);
        transpose_kernel<<<gr, th>>>(base + O_XST, base + O_XS, NTOK, CDIM);
    }
    // 14. combine projection (output-side: 4-pass)
    {
        GemmBatch bt{};
        bt.A[0] = base + O_ATTN; bt.B[0] = w_comb; bt.C[0] = base + O_OUTC;
        launch_g2<128, 4>(bt, NTOK, CDIM, DIDIM, 0, 0, 1);
    }
    // 15. output conv + bias + xs residual -> d_out (output-side: 4-pass)
    {
        GemmBatch bt{};
        bt.A[0] = w_out; bt.B[0] = base + O_OUTC; bt.C[0] = out;
        bt.bias[0] = b_out; bt.resid[0] = base + O_XS;
        launch_g2<128, 4>(bt, CDIM, NTOK, CDIM, 2, 0, 1);
    }
}